// round 1
// baseline (speedup 1.0000x reference)
#include <cuda_runtime.h>
#include <math.h>
#include <stdint.h>

// Problem constants (fixed by the dataset)
#define BB  2
#define LL  8192
#define DD  1024
#define HH  16
#define PP  64
#define CLc 256
#define NCC 32
#define MM  (BB*LL)   // 16384 rows

// ---------------------------------------------------------------------------
// Scratch (device globals: allocation-free rule)
// ---------------------------------------------------------------------------
__device__ float g_c[BB*LL*DD];
__device__ float g_b[BB*LL*DD];
__device__ float g_x[BB*LL*DD];     // becomes x*dt in place
__device__ float g_y[BB*LL*DD];     // Y_diag then += Y_off
__device__ float g_dt[BB*LL*HH];
__device__ float g_ac[BB*LL*HH];    // per-chunk inclusive cumsum of dt*A
__device__ float g_cdec[BB*NCC*HH]; // exp(Acum_last)
__device__ float g_states[BB*NCC*HH*PP*PP];
__device__ float g_prev[BB*NCC*HH*PP*PP];

// ---------------------------------------------------------------------------
// Generic SGEMM: C[M,N] = A[M,K] @ B[K,N], row-major. BM=BN=128, BK=8,
// 256 threads, 8x8 accum per thread.
// ---------------------------------------------------------------------------
__global__ __launch_bounds__(256) void sgemm(const float* __restrict__ A,
                                             const float* __restrict__ Bm,
                                             float* __restrict__ C,
                                             int M, int N, int K) {
    __shared__ float sA[8][128];
    __shared__ float sB[8][128];
    int tid = threadIdx.x;
    int tx = tid & 15, ty = tid >> 4;
    int bm = blockIdx.y * 128, bn = blockIdx.x * 128;

    int arow = tid >> 1, acol = (tid & 1) * 4;
    int brow = tid >> 5, bcol = (tid & 31) * 4;
    const float* Aptr = A + (size_t)(bm + arow) * K + acol;
    const float* Bptr = Bm + (size_t)brow * N + bn + bcol;

    float acc[8][8];
#pragma unroll
    for (int i = 0; i < 8; i++)
#pragma unroll
        for (int j = 0; j < 8; j++) acc[i][j] = 0.f;

    for (int k0 = 0; k0 < K; k0 += 8) {
        float4 av = *(const float4*)(Aptr + k0);
        sA[acol + 0][arow] = av.x;
        sA[acol + 1][arow] = av.y;
        sA[acol + 2][arow] = av.z;
        sA[acol + 3][arow] = av.w;
        *(float4*)&sB[brow][bcol] = *(const float4*)(Bptr + (size_t)k0 * N);
        __syncthreads();
#pragma unroll
        for (int k = 0; k < 8; k++) {
            float a[8], b[8];
            *(float4*)&a[0] = *(float4*)&sA[k][ty * 4];
            *(float4*)&a[4] = *(float4*)&sA[k][64 + ty * 4];
            *(float4*)&b[0] = *(float4*)&sB[k][tx * 4];
            *(float4*)&b[4] = *(float4*)&sB[k][64 + tx * 4];
#pragma unroll
            for (int i = 0; i < 8; i++)
#pragma unroll
                for (int j = 0; j < 8; j++) acc[i][j] += a[i] * b[j];
        }
        __syncthreads();
    }

#pragma unroll
    for (int i = 0; i < 8; i++) {
        int row = bm + ((i < 4) ? (ty * 4 + i) : (64 + ty * 4 + i - 4));
        float4 v0 = make_float4(acc[i][0], acc[i][1], acc[i][2], acc[i][3]);
        float4 v1 = make_float4(acc[i][4], acc[i][5], acc[i][6], acc[i][7]);
        *(float4*)&C[(size_t)row * N + bn + tx * 4] = v0;
        *(float4*)&C[(size_t)row * N + bn + 64 + tx * 4] = v1;
    }
}

// ---------------------------------------------------------------------------
// dt = softplus(hs @ Wdt)   (N=16 skinny GEMM). Block = 16 rows x 16 cols.
// ---------------------------------------------------------------------------
__global__ __launch_bounds__(256) void dt_kernel(const float* __restrict__ hs,
                                                 const float* __restrict__ Wdt) {
    int row = blockIdx.x * 16 + (threadIdx.x >> 4);
    int n = threadIdx.x & 15;
    const float* hr = hs + (size_t)row * DD;
    float s = 0.f;
#pragma unroll 8
    for (int k = 0; k < DD; k++) s += hr[k] * Wdt[k * HH + n];
    // numerically-stable softplus (matches jax.nn.softplus)
    float sp = fmaxf(s, 0.f) + log1pf(expf(-fabsf(s)));
    g_dt[row * HH + n] = sp;
}

// ---------------------------------------------------------------------------
// RoPE on c and b (in place), x *= dt (in place). One thread per (row,h,p<32).
// ---------------------------------------------------------------------------
__global__ __launch_bounds__(256) void rope_kernel(const float* __restrict__ cosp,
                                                   const float* __restrict__ sinp) {
    int t = blockIdx.x * 256 + threadIdx.x;
    int p = t & 31;
    int h = (t >> 5) & 15;
    int row = t >> 9;                       // b*L + l
    int base = row * DD + h * 64;
    float c1 = cosp[row * 64 + p],      s1 = sinp[row * 64 + p];
    float c2 = cosp[row * 64 + p + 32], s2 = sinp[row * 64 + p + 32];

    float a = g_c[base + p], q = g_c[base + p + 32];
    g_c[base + p]      = a * c1 - q * s1;
    g_c[base + p + 32] = q * c2 + a * s2;

    a = g_b[base + p]; q = g_b[base + p + 32];
    g_b[base + p]      = a * c1 - q * s1;
    g_b[base + p + 32] = q * c2 + a * s2;

    float dtv = g_dt[row * HH + h];
    g_x[base + p]      *= dtv;
    g_x[base + p + 32] *= dtv;
}

// ---------------------------------------------------------------------------
// Per-chunk inclusive cumsum of dA = dt*A[h].  One block per (b,c,h).
// ---------------------------------------------------------------------------
__global__ __launch_bounds__(256) void acum_kernel(const float* __restrict__ A) {
    __shared__ float s[256];
    int bid = blockIdx.x;
    int h = bid & 15, c = (bid >> 4) & 31, b = bid >> 9;
    int l = threadIdx.x;
    int row = b * LL + c * CLc + l;
    s[l] = g_dt[row * HH + h] * A[h];
    __syncthreads();
    for (int off = 1; off < 256; off <<= 1) {
        float u = (l >= off) ? s[l - off] : 0.f;
        __syncthreads();
        s[l] += u;
        __syncthreads();
    }
    g_ac[row * HH + h] = s[l];
    if (l == 255) g_cdec[bid] = expf(s[255]);
}

// ---------------------------------------------------------------------------
// Intra-chunk masked attention: Y_diag.  One block per (b,c,h,ltile).
// dynamic smem: sC[64*64] | sS[64*65] (B tile then S) | sX[64*64]
// ---------------------------------------------------------------------------
__global__ __launch_bounds__(256) void ka_kernel() {
    extern __shared__ float sm[];
    float* sC = sm;                // 4096
    float* sS = sm + 4096;         // 64*65 = 4160
    float* sX = sm + 4096 + 4160;  // 4096
    int bid = blockIdx.x;
    int lt = bid & 3;
    int h = (bid >> 2) & 15;
    int c = (bid >> 6) & 31;
    int b = bid >> 11;
    int tid = threadIdx.x, tx = tid & 15, ty = tid >> 4;
    int chunk_row = b * LL + c * CLc;
    int lrow0 = chunk_row + lt * 64;

#pragma unroll
    for (int r = 0; r < 16; r++) {
        int idx = tid + r * 256;
        int rr = idx >> 6, cc = idx & 63;
        sC[rr * 64 + cc] = g_c[(size_t)(lrow0 + rr) * DD + h * 64 + cc];
    }
    float acl[4];
#pragma unroll
    for (int i = 0; i < 4; i++) acl[i] = g_ac[(lrow0 + ty * 4 + i) * HH + h];

    float Y[4][4];
#pragma unroll
    for (int i = 0; i < 4; i++)
#pragma unroll
        for (int j = 0; j < 4; j++) Y[i][j] = 0.f;

    for (int st = 0; st <= lt; st++) {
        int srow0 = chunk_row + st * 64;
#pragma unroll
        for (int r = 0; r < 16; r++) {
            int idx = tid + r * 256;
            int rr = idx >> 6, cc = idx & 63;
            sS[rr * 65 + cc] = g_b[(size_t)(srow0 + rr) * DD + h * 64 + cc];
            sX[rr * 64 + cc] = g_x[(size_t)(srow0 + rr) * DD + h * 64 + cc];
        }
        __syncthreads();

        float Sacc[4][4];
#pragma unroll
        for (int i = 0; i < 4; i++)
#pragma unroll
            for (int j = 0; j < 4; j++) Sacc[i][j] = 0.f;
#pragma unroll 4
        for (int n = 0; n < 64; n++) {
            float av[4], bv[4];
#pragma unroll
            for (int i = 0; i < 4; i++) av[i] = sC[(ty * 4 + i) * 64 + n];
#pragma unroll
            for (int j = 0; j < 4; j++) bv[j] = sS[(tx * 4 + j) * 65 + n];
#pragma unroll
            for (int i = 0; i < 4; i++)
#pragma unroll
                for (int j = 0; j < 4; j++) Sacc[i][j] += av[i] * bv[j];
        }
        float acs[4];
#pragma unroll
        for (int j = 0; j < 4; j++) acs[j] = g_ac[(srow0 + tx * 4 + j) * HH + h];
#pragma unroll
        for (int i = 0; i < 4; i++)
#pragma unroll
            for (int j = 0; j < 4; j++) {
                int lg = lt * 64 + ty * 4 + i;
                int sg = st * 64 + tx * 4 + j;
                Sacc[i][j] = (sg <= lg) ? Sacc[i][j] * expf(acl[i] - acs[j]) : 0.f;
            }
        __syncthreads();   // done reading B tile from sS
#pragma unroll
        for (int i = 0; i < 4; i++)
#pragma unroll
            for (int j = 0; j < 4; j++)
                sS[(ty * 4 + i) * 65 + tx * 4 + j] = Sacc[i][j];
        __syncthreads();

#pragma unroll 4
        for (int s = 0; s < 64; s++) {
            float av[4], xv[4];
#pragma unroll
            for (int i = 0; i < 4; i++) av[i] = sS[(ty * 4 + i) * 65 + s];
#pragma unroll
            for (int j = 0; j < 4; j++) xv[j] = sX[s * 64 + tx * 4 + j];
#pragma unroll
            for (int i = 0; i < 4; i++)
#pragma unroll
                for (int j = 0; j < 4; j++) Y[i][j] += av[i] * xv[j];
        }
        __syncthreads();
    }
#pragma unroll
    for (int i = 0; i < 4; i++) {
        float4 v = make_float4(Y[i][0], Y[i][1], Y[i][2], Y[i][3]);
        *(float4*)&g_y[(size_t)(lrow0 + ty * 4 + i) * DD + h * 64 + tx * 4] = v;
    }
}

// ---------------------------------------------------------------------------
// Chunk states: states[p,n] = sum_l xdt[l,p] * b[l,n] * exp(Alast - Ac[l]).
// One block per (b,c,h).
// ---------------------------------------------------------------------------
__global__ __launch_bounds__(256) void kb_kernel() {
    __shared__ float sX[4096];
    __shared__ float sB[4096];
    int bid = blockIdx.x;
    int h = bid & 15, c = (bid >> 4) & 31, b = bid >> 9;
    int tid = threadIdx.x, tx = tid & 15, ty = tid >> 4;
    int chunk_row = b * LL + c * CLc;
    float aclast = g_ac[(chunk_row + 255) * HH + h];

    float acc[4][4];
#pragma unroll
    for (int i = 0; i < 4; i++)
#pragma unroll
        for (int j = 0; j < 4; j++) acc[i][j] = 0.f;

    for (int ltile = 0; ltile < 4; ltile++) {
        int r0 = chunk_row + ltile * 64;
#pragma unroll
        for (int r = 0; r < 16; r++) {
            int idx = tid + r * 256;
            int rr = idx >> 6, cc = idx & 63;
            float w = expf(aclast - g_ac[(r0 + rr) * HH + h]);
            sB[rr * 64 + cc] = g_b[(size_t)(r0 + rr) * DD + h * 64 + cc] * w;
            sX[rr * 64 + cc] = g_x[(size_t)(r0 + rr) * DD + h * 64 + cc];
        }
        __syncthreads();
#pragma unroll 4
        for (int l = 0; l < 64; l++) {
            float xv[4], bv[4];
#pragma unroll
            for (int i = 0; i < 4; i++) xv[i] = sX[l * 64 + ty * 4 + i];
#pragma unroll
            for (int j = 0; j < 4; j++) bv[j] = sB[l * 64 + tx * 4 + j];
#pragma unroll
            for (int i = 0; i < 4; i++)
#pragma unroll
                for (int j = 0; j < 4; j++) acc[i][j] += xv[i] * bv[j];
        }
        __syncthreads();
    }
    int sb = ((b * NCC + c) * HH + h) * 4096;
#pragma unroll
    for (int i = 0; i < 4; i++) {
        float4 v = make_float4(acc[i][0], acc[i][1], acc[i][2], acc[i][3]);
        *(float4*)&g_states[sb + (ty * 4 + i) * 64 + tx * 4] = v;
    }
}

// ---------------------------------------------------------------------------
// Sequential chunk scan.  One block per (b,h), 256 threads x 16 elems.
// Writes prev_states and final_state (into d_out tail).
// ---------------------------------------------------------------------------
__global__ __launch_bounds__(256) void kc_kernel(float* __restrict__ fs) {
    int bid = blockIdx.x;
    int h = bid & 15, b = bid >> 4;
    int tid = threadIdx.x;
    float st[16];
#pragma unroll
    for (int k = 0; k < 16; k++) st[k] = 0.f;
    for (int c = 0; c < NCC; c++) {
        float dec = g_cdec[(b * NCC + c) * HH + h];
        int base = ((b * NCC + c) * HH + h) * 4096;
#pragma unroll
        for (int k = 0; k < 16; k++) {
            int e = k * 256 + tid;
            g_prev[base + e] = st[k];
            st[k] = st[k] * dec + g_states[base + e];
        }
    }
    int fb = (b * HH + h) * 4096;
#pragma unroll
    for (int k = 0; k < 16; k++) fs[fb + k * 256 + tid] = st[k];
}

// ---------------------------------------------------------------------------
// Y_off: y[l,p] += exp(Ac[l]) * sum_n c[l,n]*prev[p,n].  Block per (b,c,h,lt).
// ---------------------------------------------------------------------------
__global__ __launch_bounds__(256) void kd_kernel() {
    __shared__ float sC[4096];
    __shared__ float sP[64 * 65];
    int bid = blockIdx.x;
    int lt = bid & 3;
    int h = (bid >> 2) & 15;
    int c = (bid >> 6) & 31;
    int b = bid >> 11;
    int tid = threadIdx.x, tx = tid & 15, ty = tid >> 4;
    int chunk_row = b * LL + c * CLc;
    int lrow0 = chunk_row + lt * 64;
    int pb = ((b * NCC + c) * HH + h) * 4096;

#pragma unroll
    for (int r = 0; r < 16; r++) {
        int idx = tid + r * 256;
        int rr = idx >> 6, cc = idx & 63;
        sC[rr * 64 + cc] = g_c[(size_t)(lrow0 + rr) * DD + h * 64 + cc];
        sP[rr * 65 + cc] = g_prev[pb + idx];
    }
    __syncthreads();

    float acc[4][4];
#pragma unroll
    for (int i = 0; i < 4; i++)
#pragma unroll
        for (int j = 0; j < 4; j++) acc[i][j] = 0.f;
#pragma unroll 4
    for (int n = 0; n < 64; n++) {
        float cv[4], pv[4];
#pragma unroll
        for (int i = 0; i < 4; i++) cv[i] = sC[(ty * 4 + i) * 64 + n];
#pragma unroll
        for (int j = 0; j < 4; j++) pv[j] = sP[(tx * 4 + j) * 65 + n];
#pragma unroll
        for (int i = 0; i < 4; i++)
#pragma unroll
            for (int j = 0; j < 4; j++) acc[i][j] += cv[i] * pv[j];
    }
#pragma unroll
    for (int i = 0; i < 4; i++) {
        float e = expf(g_ac[(lrow0 + ty * 4 + i) * HH + h]);
        float* yp = &g_y[(size_t)(lrow0 + ty * 4 + i) * DD + h * 64 + tx * 4];
        float4 v = *(float4*)yp;
        v.x += acc[i][0] * e; v.y += acc[i][1] * e;
        v.z += acc[i][2] * e; v.w += acc[i][3] * e;
        *(float4*)yp = v;
    }
}

// ---------------------------------------------------------------------------
// kernel_launch
// ---------------------------------------------------------------------------
extern "C" void kernel_launch(void* const* d_in, const int* in_sizes, int n_in,
                              void* d_out, int out_size) {
    (void)in_sizes; (void)n_in; (void)out_size;
    const float* hs   = (const float*)d_in[0];
    const float* cosp = (const float*)d_in[1];
    const float* sinp = (const float*)d_in[2];
    const float* Wc   = (const float*)d_in[3];
    const float* Wb   = (const float*)d_in[4];
    const float* Wdt  = (const float*)d_in[5];
    const float* Wx   = (const float*)d_in[6];
    const float* Wout = (const float*)d_in[7];
    const float* A    = (const float*)d_in[8];
    float* out = (float*)d_out;
    float* fs  = out + (size_t)MM * DD;   // final_state after flattened y@Wout

    float *pc, *pb, *px, *py;
    cudaGetSymbolAddress((void**)&pc, g_c);
    cudaGetSymbolAddress((void**)&pb, g_b);
    cudaGetSymbolAddress((void**)&px, g_x);
    cudaGetSymbolAddress((void**)&py, g_y);

    dim3 gg(DD / 128, MM / 128);
    sgemm<<<gg, 256>>>(hs, Wc, pc, MM, DD, DD);
    sgemm<<<gg, 256>>>(hs, Wb, pb, MM, DD, DD);
    sgemm<<<gg, 256>>>(hs, Wx, px, MM, DD, DD);
    dt_kernel<<<MM / 16, 256>>>(hs, Wdt);
    rope_kernel<<<(MM * HH * 32) / 256, 256>>>(cosp, sinp);
    acum_kernel<<<BB * NCC * HH, 256>>>(A);

    int ka_smem = (4096 + 64 * 65 + 4096) * 4;  // 49408 B
    cudaFuncSetAttribute(ka_kernel, cudaFuncAttributeMaxDynamicSharedMemorySize, ka_smem);
    ka_kernel<<<BB * NCC * HH * 4, 256, ka_smem>>>();

    kb_kernel<<<BB * NCC * HH, 256>>>();
    kc_kernel<<<BB * HH, 256>>>(fs);
    kd_kernel<<<BB * NCC * HH * 4, 256>>>();
    sgemm<<<gg, 256>>>(py, Wout, out, MM, DD, DD);
}

// round 3
// speedup vs baseline: 2.8067x; 2.8067x over previous
#include <cuda_runtime.h>
#include <cuda_bf16.h>
#include <math.h>
#include <stdint.h>

// Problem constants (fixed by the dataset)
#define BB  2
#define LL  8192
#define DD  1024
#define HH  16
#define PP  64
#define CLc 256
#define NCC 32
#define MM  (BB*LL)   // 16384 rows

// tcgen05 only exists in the arch-specific (sm_103a/sm_100a) compilation pass.
#if defined(__CUDA_ARCH_FEAT_SM103_ALL) || defined(__CUDA_ARCH_FEAT_SM100_ALL) || \
    defined(__CUDA_ARCH_FEAT_SM101_ALL) || defined(__CUDA_ARCH_SPECIFIC__)
#define HAS_TCGEN05 1
#else
#define HAS_TCGEN05 0
#endif

// ---------------------------------------------------------------------------
// Scratch (device globals: allocation-free rule)
// ---------------------------------------------------------------------------
__device__ float g_c[BB*LL*DD];
__device__ float g_b[BB*LL*DD];
__device__ float g_x[BB*LL*DD];     // becomes x*dt in place
__device__ float g_y[BB*LL*DD];     // Y_diag then += Y_off
__device__ float g_dt[BB*LL*HH];
__device__ float g_ac[BB*LL*HH];
__device__ float g_cdec[BB*NCC*HH];
__device__ float g_states[BB*NCC*HH*PP*PP];
__device__ float g_prev[BB*NCC*HH*PP*PP];

// bf16 split buffers
__device__ __nv_bfloat16 g_ahi[MM*DD];   // hs (then y) high part
__device__ __nv_bfloat16 g_alo[MM*DD];   // hs (then y) low part
__device__ __nv_bfloat16 g_wt_hi[4][DD*DD]; // transposed weights: 0=Wc 1=Wb 2=Wx 3=Wout
__device__ __nv_bfloat16 g_wt_lo[4][DD*DD];

// ---------------------------------------------------------------------------
// PTX helpers
// ---------------------------------------------------------------------------
__device__ __forceinline__ uint32_t smem_u32(const void* p) {
    uint32_t a;
    asm("{ .reg .u64 t; cvta.to.shared.u64 t, %1; cvt.u32.u64 %0, t; }"
        : "=r"(a) : "l"(p));
    return a;
}
__device__ __forceinline__ uint32_t swz(uint32_t off) { return off ^ ((off >> 3) & 0x70); }

#if HAS_TCGEN05
__device__ __forceinline__ uint32_t elect_one() {
    uint32_t pred;
    asm volatile("{\n\t.reg .pred p;\n\telect.sync _|p, 0xFFFFFFFF;\n\t"
                 "selp.b32 %0, 1, 0, p;\n\t}" : "=r"(pred));
    return pred;
}
#define MBAR_INIT(a, c) \
    asm volatile("mbarrier.init.shared.b64 [%0], %1;" :: "r"(a), "r"(c) : "memory")
#define MBAR_WAIT(a, ph) do { \
    asm volatile("{\n\t.reg .pred P1;\n\t" \
        "WL_%=:\n\t" \
        "mbarrier.try_wait.parity.acquire.cta.shared::cta.b64 P1, [%0], %1, 0x989680;\n\t" \
        "@P1 bra.uni WD_%=;\n\tbra.uni WL_%=;\n\tWD_%=:\n\t}" \
        :: "r"(a), "r"(ph) : "memory"); \
} while (0)
#define TC_ALLOC(sa, n) \
    asm volatile("tcgen05.alloc.cta_group::1.sync.aligned.shared::cta.b32 [%0], %1;" \
                 :: "r"(sa), "r"(n) : "memory")
#define TC_DEALLOC(t, n) \
    asm volatile("tcgen05.dealloc.cta_group::1.sync.aligned.b32 %0, %1;" :: "r"(t), "r"(n))
#define TC_COMMIT(a) \
    asm volatile("tcgen05.commit.cta_group::1.mbarrier::arrive::one.shared::cluster.b64 [%0];" \
                 :: "r"(a) : "memory")
#define TC_FENCE_AFTER() asm volatile("tcgen05.fence::after_thread_sync;" ::: "memory")
#define TC_FENCE_BEFORE() asm volatile("tcgen05.fence::before_thread_sync;" ::: "memory")
#define TC_WAIT_LD() asm volatile("tcgen05.wait::ld.sync.aligned;" ::: "memory")
#define FENCE_ASYNC() asm volatile("fence.proxy.async.shared::cta;" ::: "memory")

__device__ __forceinline__ void mma_f16_ss(uint32_t d, uint64_t ad, uint64_t bd,
                                           uint32_t idesc, uint32_t en) {
    asm volatile("{\n\t.reg .pred p;\n\tsetp.ne.u32 p, %4, 0;\n\t"
                 "tcgen05.mma.cta_group::1.kind::f16 [%0], %1, %2, %3, {%5,%5,%5,%5}, p;\n\t}"
                 :: "r"(d), "l"(ad), "l"(bd), "r"(idesc), "r"(en), "r"(0u) : "memory");
}
__device__ __forceinline__ void ldtm32(uint32_t* r, uint32_t ta) {
    asm volatile("tcgen05.ld.sync.aligned.32x32b.x32.b32 "
        "{%0,%1,%2,%3,%4,%5,%6,%7,%8,%9,%10,%11,%12,%13,%14,%15,"
        "%16,%17,%18,%19,%20,%21,%22,%23,%24,%25,%26,%27,%28,%29,%30,%31}, [%32];"
        : "=r"(r[0]),"=r"(r[1]),"=r"(r[2]),"=r"(r[3]),"=r"(r[4]),"=r"(r[5]),"=r"(r[6]),"=r"(r[7]),
          "=r"(r[8]),"=r"(r[9]),"=r"(r[10]),"=r"(r[11]),"=r"(r[12]),"=r"(r[13]),"=r"(r[14]),"=r"(r[15]),
          "=r"(r[16]),"=r"(r[17]),"=r"(r[18]),"=r"(r[19]),"=r"(r[20]),"=r"(r[21]),"=r"(r[22]),"=r"(r[23]),
          "=r"(r[24]),"=r"(r[25]),"=r"(r[26]),"=r"(r[27]),"=r"(r[28]),"=r"(r[29]),"=r"(r[30]),"=r"(r[31])
        : "r"(ta));
}
static constexpr uint64_t DESC_BASE =
    (uint64_t(2) << 61) | (uint64_t(1) << 46) | (uint64_t(64) << 32) | (uint64_t(1) << 16);
__device__ __forceinline__ uint64_t mk_desc(uint32_t addr) {
    return DESC_BASE | ((uint64_t)(addr >> 4) & 0x3FFF);
}
#endif  // HAS_TCGEN05

// ---------------------------------------------------------------------------
// Split fp32 -> bf16 hi/lo (vectorized x4)
// ---------------------------------------------------------------------------
__global__ __launch_bounds__(256) void fsplit(const float* __restrict__ in,
                                              __nv_bfloat16* __restrict__ hi,
                                              __nv_bfloat16* __restrict__ lo) {
    int idx = blockIdx.x * 256 + threadIdx.x;
    float4 v = ((const float4*)in)[idx];
    __nv_bfloat16 h0 = __float2bfloat16(v.x), h1 = __float2bfloat16(v.y);
    __nv_bfloat16 h2 = __float2bfloat16(v.z), h3 = __float2bfloat16(v.w);
    __nv_bfloat16 l0 = __float2bfloat16(v.x - __bfloat162float(h0));
    __nv_bfloat16 l1 = __float2bfloat16(v.y - __bfloat162float(h1));
    __nv_bfloat16 l2 = __float2bfloat16(v.z - __bfloat162float(h2));
    __nv_bfloat16 l3 = __float2bfloat16(v.w - __bfloat162float(h3));
    ((__nv_bfloat162*)hi)[idx*2]     = __halves2bfloat162(h0, h1);
    ((__nv_bfloat162*)hi)[idx*2 + 1] = __halves2bfloat162(h2, h3);
    ((__nv_bfloat162*)lo)[idx*2]     = __halves2bfloat162(l0, l1);
    ((__nv_bfloat162*)lo)[idx*2 + 1] = __halves2bfloat162(l2, l3);
}

// ---------------------------------------------------------------------------
// Transpose + split weights: W[K][N] fp32 -> T[N][K] bf16 hi/lo (1024x1024)
// ---------------------------------------------------------------------------
__global__ __launch_bounds__(256) void wsplit(const float* __restrict__ W,
                                              __nv_bfloat16* __restrict__ Thi,
                                              __nv_bfloat16* __restrict__ Tlo) {
    __shared__ float t[32][33];
    int bx = blockIdx.x * 32, by = blockIdx.y * 32;
    int x = threadIdx.x & 31, y = threadIdx.x >> 5;   // 32 x 8
#pragma unroll
    for (int j = 0; j < 4; j++)
        t[y + j*8][x] = W[(size_t)(by + y + j*8) * DD + bx + x];
    __syncthreads();
#pragma unroll
    for (int j = 0; j < 4; j++) {
        float v = t[x][y + j*8];
        __nv_bfloat16 h = __float2bfloat16(v);
        __nv_bfloat16 l = __float2bfloat16(v - __bfloat162float(h));
        size_t o = (size_t)(bx + y + j*8) * DD + by + x;
        Thi[o] = h; Tlo[o] = l;
    }
}

// ---------------------------------------------------------------------------
// GEMM: C[16384,1024] = (Ahi+Alo)[16384,1024] @ (Bhi+Blo)^T, B stored [N][K].
// tcgen05 path: BM=128 BN=256 BK=64, double-buffered, bf16x3 split.
// Fallback path (non-'a' pass only): CUDA-core tiled fp32.
// grid = (N/256=4, M/128=128), 256 threads.
// ---------------------------------------------------------------------------
#define GK 1024
#define GN 1024
#define NCHUNK 16
#define BUF_STRIDE 98304
// idesc: dtype F32, atype/btype BF16, N=256, M=128
#define GIDESC ((1u<<4)|(1u<<7)|(1u<<10)|((256u/8)<<17)|((128u/16)<<24))

__global__ __launch_bounds__(256, 1) void gemm_t(
        const __nv_bfloat16* __restrict__ Ahi, const __nv_bfloat16* __restrict__ Alo,
        const __nv_bfloat16* __restrict__ Bhi, const __nv_bfloat16* __restrict__ Blo,
        float* __restrict__ C) {
    extern __shared__ char sm[];
#if HAS_TCGEN05
    uint32_t sbase = smem_u32(sm);
    int tid = threadIdx.x;
    int wid = tid >> 5, lid = tid & 31;
    int bn = blockIdx.x * 256, bm = blockIdx.y * 128;

    if (tid == 0) { MBAR_INIT(sbase + 8, 1); MBAR_INIT(sbase + 16, 1); }
    if (wid == 0) TC_ALLOC(sbase, 256);
    __syncthreads();
    uint32_t tmem;
    asm volatile("ld.shared.b32 %0, [%1];" : "=r"(tmem) : "r"(sbase));

    auto load_chunk = [&](int chunk, int buf) {
        uint32_t boff = 1024u + (uint32_t)buf * BUF_STRIDE;
        int k0 = chunk * 64;
#pragma unroll
        for (int t = 0; t < 4; t++) {            // A hi/lo: 128x64 bf16
            int i = tid + t * 256;
            int r = i >> 3, c8 = i & 7;
            uint32_t so = swz((uint32_t)(r * 128 + c8 * 16));
            *(uint4*)(sm + boff + so) =
                *(const uint4*)(Ahi + (size_t)(bm + r) * GK + k0 + c8 * 8);
            *(uint4*)(sm + boff + 16384 + so) =
                *(const uint4*)(Alo + (size_t)(bm + r) * GK + k0 + c8 * 8);
        }
#pragma unroll
        for (int t = 0; t < 8; t++) {            // B hi/lo: 256x64 bf16
            int i = tid + t * 256;
            int r = i >> 3, c8 = i & 7;
            uint32_t so = swz((uint32_t)(r * 128 + c8 * 16));
            *(uint4*)(sm + boff + 32768 + so) =
                *(const uint4*)(Bhi + (size_t)(bn + r) * GK + k0 + c8 * 8);
            *(uint4*)(sm + boff + 65536 + so) =
                *(const uint4*)(Blo + (size_t)(bn + r) * GK + k0 + c8 * 8);
        }
    };

    load_chunk(0, 0);
    FENCE_ASYNC();
    __syncthreads();

    int ph0 = 0, ph1 = 0;
    for (int k = 0; k < NCHUNK; k++) {
        int b = k & 1;
        if (wid == 0) {
            if (elect_one()) {
                uint32_t boff = sbase + 1024u + (uint32_t)b * BUF_STRIDE;
                uint64_t dah = mk_desc(boff);
                uint64_t dal = mk_desc(boff + 16384);
                uint64_t dbh = mk_desc(boff + 32768);
                uint64_t dbl = mk_desc(boff + 65536);
#pragma unroll
                for (int ks = 0; ks < 4; ks++) {
                    mma_f16_ss(tmem, dah + ks*2, dbh + ks*2, GIDESC,
                               (k == 0 && ks == 0) ? 0u : 1u);
                    mma_f16_ss(tmem, dah + ks*2, dbl + ks*2, GIDESC, 1u);
                    mma_f16_ss(tmem, dal + ks*2, dbh + ks*2, GIDESC, 1u);
                }
                TC_COMMIT(sbase + 8 + (uint32_t)b * 8);
            }
        }
        if (k + 1 < NCHUNK) {
            int nb = (k + 1) & 1;
            if (k >= 1) {
                uint32_t mb = sbase + 8 + (uint32_t)nb * 8;
                if (nb == 0) { MBAR_WAIT(mb, ph0); ph0 ^= 1; }
                else         { MBAR_WAIT(mb, ph1); ph1 ^= 1; }
            }
            load_chunk(k + 1, nb);
            FENCE_ASYNC();
            __syncthreads();
        }
    }
    MBAR_WAIT(sbase + 16, ph1);
    TC_FENCE_AFTER();

    if (wid < 4) {
        int row = bm + wid * 32 + lid;
        float* crow = C + (size_t)row * GN + bn;
#pragma unroll
        for (int cb = 0; cb < 8; cb++) {
            uint32_t r[32];
            ldtm32(r, tmem + cb * 32);
            TC_WAIT_LD();
#pragma unroll
            for (int j = 0; j < 8; j++) {
                float4 v = make_float4(__uint_as_float(r[j*4]), __uint_as_float(r[j*4+1]),
                                       __uint_as_float(r[j*4+2]), __uint_as_float(r[j*4+3]));
                *(float4*)(crow + cb * 32 + j * 4) = v;
            }
        }
        TC_FENCE_BEFORE();
    }
    __syncthreads();
    if (wid == 0) TC_DEALLOC(tmem, 256);
#else
    // CUDA-core fallback (used only if the arch-specific SASS is unavailable).
    int tid = threadIdx.x;
    int tx = tid & 15, ty = tid >> 4;
    int bn = blockIdx.x * 256, bm = blockIdx.y * 128;
    float* sA = (float*)sm;            // [16][128]
    float* sB = (float*)(sm + 8192);   // [16][128]
    for (int half = 0; half < 2; half++) {
        int bn2 = bn + half * 128;
        float acc[8][8];
#pragma unroll
        for (int i = 0; i < 8; i++)
#pragma unroll
            for (int j = 0; j < 8; j++) acc[i][j] = 0.f;
        for (int k0 = 0; k0 < GK; k0 += 16) {
            for (int i = tid; i < 2048; i += 256) {
                int r = i >> 4, kk = i & 15;
                sA[kk*128 + r] = __bfloat162float(Ahi[(size_t)(bm + r)*GK + k0 + kk]) +
                                 __bfloat162float(Alo[(size_t)(bm + r)*GK + k0 + kk]);
                sB[kk*128 + r] = __bfloat162float(Bhi[(size_t)(bn2 + r)*GK + k0 + kk]) +
                                 __bfloat162float(Blo[(size_t)(bn2 + r)*GK + k0 + kk]);
            }
            __syncthreads();
#pragma unroll
            for (int kk = 0; kk < 16; kk++) {
                float a[8], b[8];
#pragma unroll
                for (int i = 0; i < 4; i++) {
                    a[i] = sA[kk*128 + ty*4 + i];
                    a[i+4] = sA[kk*128 + 64 + ty*4 + i];
                    b[i] = sB[kk*128 + tx*4 + i];
                    b[i+4] = sB[kk*128 + 64 + tx*4 + i];
                }
#pragma unroll
                for (int i = 0; i < 8; i++)
#pragma unroll
                    for (int j = 0; j < 8; j++) acc[i][j] += a[i] * b[j];
            }
            __syncthreads();
        }
#pragma unroll
        for (int i = 0; i < 8; i++) {
            int row = bm + ((i < 4) ? (ty*4 + i) : (64 + ty*4 + i - 4));
#pragma unroll
            for (int j = 0; j < 8; j++) {
                int col = bn2 + ((j < 4) ? (tx*4 + j) : (64 + tx*4 + j - 4));
                C[(size_t)row * GN + col] = acc[i][j];
            }
        }
        __syncthreads();
    }
#endif
}

// ---------------------------------------------------------------------------
// dt = softplus(hs @ Wdt): warp computes 4 rows; Wdt cached in smem [16][1028]
// ---------------------------------------------------------------------------
__global__ __launch_bounds__(256) void dt2(const float* __restrict__ hs,
                                           const float* __restrict__ Wdt) {
    extern __shared__ float sw[];   // 16 * 1028 floats
    int tid = threadIdx.x;
    for (int i = tid; i < 16384; i += 256)
        sw[(i & 15) * 1028 + (i >> 4)] = Wdt[i];
    __syncthreads();
    int w = tid >> 5, l = tid & 31;
    int row0 = blockIdx.x * 32 + w * 4;
    float acc[4][16];
#pragma unroll
    for (int r = 0; r < 4; r++)
#pragma unroll
        for (int n = 0; n < 16; n++) acc[r][n] = 0.f;
#pragma unroll
    for (int it = 0; it < 8; it++) {
        int k0 = it * 128 + l * 4;
        float4 h[4];
#pragma unroll
        for (int r = 0; r < 4; r++)
            h[r] = *(const float4*)&hs[(size_t)(row0 + r) * DD + k0];
#pragma unroll
        for (int n = 0; n < 16; n++) {
            float4 wv = *(const float4*)&sw[n * 1028 + k0];
#pragma unroll
            for (int r = 0; r < 4; r++)
                acc[r][n] += h[r].x*wv.x + h[r].y*wv.y + h[r].z*wv.z + h[r].w*wv.w;
        }
    }
#pragma unroll
    for (int off = 16; off; off >>= 1)
#pragma unroll
        for (int r = 0; r < 4; r++)
#pragma unroll
            for (int n = 0; n < 16; n++)
                acc[r][n] += __shfl_xor_sync(0xFFFFFFFFu, acc[r][n], off);
    if (l == 0) {
#pragma unroll
        for (int r = 0; r < 4; r++)
#pragma unroll
            for (int n = 0; n < 16; n++) {
                float s = acc[r][n];
                g_dt[(row0 + r) * HH + n] = fmaxf(s, 0.f) + log1pf(expf(-fabsf(s)));
            }
    }
}

// ---------------------------------------------------------------------------
// RoPE on c and b (in place), x *= dt (in place).
// ---------------------------------------------------------------------------
__global__ __launch_bounds__(256) void rope_kernel(const float* __restrict__ cosp,
                                                   const float* __restrict__ sinp) {
    int t = blockIdx.x * 256 + threadIdx.x;
    int p = t & 31;
    int h = (t >> 5) & 15;
    int row = t >> 9;
    int base = row * DD + h * 64;
    float c1 = cosp[row * 64 + p],      s1 = sinp[row * 64 + p];
    float c2 = cosp[row * 64 + p + 32], s2 = sinp[row * 64 + p + 32];

    float a = g_c[base + p], q = g_c[base + p + 32];
    g_c[base + p]      = a * c1 - q * s1;
    g_c[base + p + 32] = q * c2 + a * s2;

    a = g_b[base + p]; q = g_b[base + p + 32];
    g_b[base + p]      = a * c1 - q * s1;
    g_b[base + p + 32] = q * c2 + a * s2;

    float dtv = g_dt[row * HH + h];
    g_x[base + p]      *= dtv;
    g_x[base + p + 32] *= dtv;
}

// ---------------------------------------------------------------------------
// Per-chunk inclusive cumsum of dA = dt*A[h].
// ---------------------------------------------------------------------------
__global__ __launch_bounds__(256) void acum_kernel(const float* __restrict__ A) {
    __shared__ float s[256];
    int bid = blockIdx.x;
    int h = bid & 15, c = (bid >> 4) & 31, b = bid >> 9;
    int l = threadIdx.x;
    int row = b * LL + c * CLc + l;
    s[l] = g_dt[row * HH + h] * A[h];
    __syncthreads();
    for (int off = 1; off < 256; off <<= 1) {
        float u = (l >= off) ? s[l - off] : 0.f;
        __syncthreads();
        s[l] += u;
        __syncthreads();
    }
    g_ac[row * HH + h] = s[l];
    if (l == 255) g_cdec[bid] = expf(s[255]);
}

// ---------------------------------------------------------------------------
// Intra-chunk masked attention: Y_diag.
// ---------------------------------------------------------------------------
__global__ __launch_bounds__(256) void ka_kernel() {
    extern __shared__ float smf[];
    float* sC = smf;
    float* sS = smf + 4096;
    float* sX = smf + 4096 + 4160;
    int bid = blockIdx.x;
    int lt = bid & 3;
    int h = (bid >> 2) & 15;
    int c = (bid >> 6) & 31;
    int b = bid >> 11;
    int tid = threadIdx.x, tx = tid & 15, ty = tid >> 4;
    int chunk_row = b * LL + c * CLc;
    int lrow0 = chunk_row + lt * 64;

#pragma unroll
    for (int r = 0; r < 16; r++) {
        int idx = tid + r * 256;
        int rr = idx >> 6, cc = idx & 63;
        sC[rr * 64 + cc] = g_c[(size_t)(lrow0 + rr) * DD + h * 64 + cc];
    }
    float acl[4];
#pragma unroll
    for (int i = 0; i < 4; i++) acl[i] = g_ac[(lrow0 + ty * 4 + i) * HH + h];

    float Y[4][4];
#pragma unroll
    for (int i = 0; i < 4; i++)
#pragma unroll
        for (int j = 0; j < 4; j++) Y[i][j] = 0.f;

    for (int st = 0; st <= lt; st++) {
        int srow0 = chunk_row + st * 64;
#pragma unroll
        for (int r = 0; r < 16; r++) {
            int idx = tid + r * 256;
            int rr = idx >> 6, cc = idx & 63;
            sS[rr * 65 + cc] = g_b[(size_t)(srow0 + rr) * DD + h * 64 + cc];
            sX[rr * 64 + cc] = g_x[(size_t)(srow0 + rr) * DD + h * 64 + cc];
        }
        __syncthreads();

        float Sacc[4][4];
#pragma unroll
        for (int i = 0; i < 4; i++)
#pragma unroll
            for (int j = 0; j < 4; j++) Sacc[i][j] = 0.f;
#pragma unroll 4
        for (int n = 0; n < 64; n++) {
            float av[4], bv[4];
#pragma unroll
            for (int i = 0; i < 4; i++) av[i] = sC[(ty * 4 + i) * 64 + n];
#pragma unroll
            for (int j = 0; j < 4; j++) bv[j] = sS[(tx * 4 + j) * 65 + n];
#pragma unroll
            for (int i = 0; i < 4; i++)
#pragma unroll
                for (int j = 0; j < 4; j++) Sacc[i][j] += av[i] * bv[j];
        }
        float acs[4];
#pragma unroll
        for (int j = 0; j < 4; j++) acs[j] = g_ac[(srow0 + tx * 4 + j) * HH + h];
#pragma unroll
        for (int i = 0; i < 4; i++)
#pragma unroll
            for (int j = 0; j < 4; j++) {
                int lg = lt * 64 + ty * 4 + i;
                int sg = st * 64 + tx * 4 + j;
                Sacc[i][j] = (sg <= lg) ? Sacc[i][j] * expf(acl[i] - acs[j]) : 0.f;
            }
        __syncthreads();
#pragma unroll
        for (int i = 0; i < 4; i++)
#pragma unroll
            for (int j = 0; j < 4; j++)
                sS[(ty * 4 + i) * 65 + tx * 4 + j] = Sacc[i][j];
        __syncthreads();

#pragma unroll 4
        for (int s = 0; s < 64; s++) {
            float av[4], xv[4];
#pragma unroll
            for (int i = 0; i < 4; i++) av[i] = sS[(ty * 4 + i) * 65 + s];
#pragma unroll
            for (int j = 0; j < 4; j++) xv[j] = sX[s * 64 + tx * 4 + j];
#pragma unroll
            for (int i = 0; i < 4; i++)
#pragma unroll
                for (int j = 0; j < 4; j++) Y[i][j] += av[i] * xv[j];
        }
        __syncthreads();
    }
#pragma unroll
    for (int i = 0; i < 4; i++) {
        float4 v = make_float4(Y[i][0], Y[i][1], Y[i][2], Y[i][3]);
        *(float4*)&g_y[(size_t)(lrow0 + ty * 4 + i) * DD + h * 64 + tx * 4] = v;
    }
}

// ---------------------------------------------------------------------------
// Chunk states.
// ---------------------------------------------------------------------------
__global__ __launch_bounds__(256) void kb_kernel() {
    __shared__ float sX[4096];
    __shared__ float sB[4096];
    int bid = blockIdx.x;
    int h = bid & 15, c = (bid >> 4) & 31, b = bid >> 9;
    int tid = threadIdx.x, tx = tid & 15, ty = tid >> 4;
    int chunk_row = b * LL + c * CLc;
    float aclast = g_ac[(chunk_row + 255) * HH + h];

    float acc[4][4];
#pragma unroll
    for (int i = 0; i < 4; i++)
#pragma unroll
        for (int j = 0; j < 4; j++) acc[i][j] = 0.f;

    for (int ltile = 0; ltile < 4; ltile++) {
        int r0 = chunk_row + ltile * 64;
#pragma unroll
        for (int r = 0; r < 16; r++) {
            int idx = tid + r * 256;
            int rr = idx >> 6, cc = idx & 63;
            float w = expf(aclast - g_ac[(r0 + rr) * HH + h]);
            sB[rr * 64 + cc] = g_b[(size_t)(r0 + rr) * DD + h * 64 + cc] * w;
            sX[rr * 64 + cc] = g_x[(size_t)(r0 + rr) * DD + h * 64 + cc];
        }
        __syncthreads();
#pragma unroll 4
        for (int l = 0; l < 64; l++) {
            float xv[4], bv[4];
#pragma unroll
            for (int i = 0; i < 4; i++) xv[i] = sX[l * 64 + ty * 4 + i];
#pragma unroll
            for (int j = 0; j < 4; j++) bv[j] = sB[l * 64 + tx * 4 + j];
#pragma unroll
            for (int i = 0; i < 4; i++)
#pragma unroll
                for (int j = 0; j < 4; j++) acc[i][j] += xv[i] * bv[j];
        }
        __syncthreads();
    }
    int sb = ((b * NCC + c) * HH + h) * 4096;
#pragma unroll
    for (int i = 0; i < 4; i++) {
        float4 v = make_float4(acc[i][0], acc[i][1], acc[i][2], acc[i][3]);
        *(float4*)&g_states[sb + (ty * 4 + i) * 64 + tx * 4] = v;
    }
}

// ---------------------------------------------------------------------------
// Sequential chunk scan.
// ---------------------------------------------------------------------------
__global__ __launch_bounds__(256) void kc_kernel(float* __restrict__ fs) {
    int bid = blockIdx.x;
    int h = bid & 15, b = bid >> 4;
    int tid = threadIdx.x;
    float st[16];
#pragma unroll
    for (int k = 0; k < 16; k++) st[k] = 0.f;
    for (int c = 0; c < NCC; c++) {
        float dec = g_cdec[(b * NCC + c) * HH + h];
        int base = ((b * NCC + c) * HH + h) * 4096;
#pragma unroll
        for (int k = 0; k < 16; k++) {
            int e = k * 256 + tid;
            g_prev[base + e] = st[k];
            st[k] = st[k] * dec + g_states[base + e];
        }
    }
    int fb = (b * HH + h) * 4096;
#pragma unroll
    for (int k = 0; k < 16; k++) fs[fb + k * 256 + tid] = st[k];
}

// ---------------------------------------------------------------------------
// Y_off accumulate.
// ---------------------------------------------------------------------------
__global__ __launch_bounds__(256) void kd_kernel() {
    __shared__ float sC[4096];
    __shared__ float sP[64 * 65];
    int bid = blockIdx.x;
    int lt = bid & 3;
    int h = (bid >> 2) & 15;
    int c = (bid >> 6) & 31;
    int b = bid >> 11;
    int tid = threadIdx.x, tx = tid & 15, ty = tid >> 4;
    int chunk_row = b * LL + c * CLc;
    int lrow0 = chunk_row + lt * 64;
    int pb = ((b * NCC + c) * HH + h) * 4096;

#pragma unroll
    for (int r = 0; r < 16; r++) {
        int idx = tid + r * 256;
        int rr = idx >> 6, cc = idx & 63;
        sC[rr * 64 + cc] = g_c[(size_t)(lrow0 + rr) * DD + h * 64 + cc];
        sP[rr * 65 + cc] = g_prev[pb + idx];
    }
    __syncthreads();

    float acc[4][4];
#pragma unroll
    for (int i = 0; i < 4; i++)
#pragma unroll
        for (int j = 0; j < 4; j++) acc[i][j] = 0.f;
#pragma unroll 4
    for (int n = 0; n < 64; n++) {
        float cv[4], pv[4];
#pragma unroll
        for (int i = 0; i < 4; i++) cv[i] = sC[(ty * 4 + i) * 64 + n];
#pragma unroll
        for (int j = 0; j < 4; j++) pv[j] = sP[(tx * 4 + j) * 65 + n];
#pragma unroll
        for (int i = 0; i < 4; i++)
#pragma unroll
            for (int j = 0; j < 4; j++) acc[i][j] += cv[i] * pv[j];
    }
#pragma unroll
    for (int i = 0; i < 4; i++) {
        float e = expf(g_ac[(lrow0 + ty * 4 + i) * HH + h]);
        float* yp = &g_y[(size_t)(lrow0 + ty * 4 + i) * DD + h * 64 + tx * 4];
        float4 v = *(float4*)yp;
        v.x += acc[i][0] * e; v.y += acc[i][1] * e;
        v.z += acc[i][2] * e; v.w += acc[i][3] * e;
        *(float4*)yp = v;
    }
}

// ---------------------------------------------------------------------------
// kernel_launch
// ---------------------------------------------------------------------------
extern "C" void kernel_launch(void* const* d_in, const int* in_sizes, int n_in,
                              void* d_out, int out_size) {
    (void)in_sizes; (void)n_in; (void)out_size;
    const float* hs   = (const float*)d_in[0];
    const float* cosp = (const float*)d_in[1];
    const float* sinp = (const float*)d_in[2];
    const float* Wc   = (const float*)d_in[3];
    const float* Wb   = (const float*)d_in[4];
    const float* Wdt  = (const float*)d_in[5];
    const float* Wx   = (const float*)d_in[6];
    const float* Wout = (const float*)d_in[7];
    const float* A    = (const float*)d_in[8];
    float* out = (float*)d_out;
    float* fs  = out + (size_t)MM * DD;

    float *pc, *pb, *px, *py;
    __nv_bfloat16 *ahi, *alo, *whi, *wlo;
    cudaGetSymbolAddress((void**)&pc, g_c);
    cudaGetSymbolAddress((void**)&pb, g_b);
    cudaGetSymbolAddress((void**)&px, g_x);
    cudaGetSymbolAddress((void**)&py, g_y);
    cudaGetSymbolAddress((void**)&ahi, g_ahi);
    cudaGetSymbolAddress((void**)&alo, g_alo);
    cudaGetSymbolAddress((void**)&whi, g_wt_hi);
    cudaGetSymbolAddress((void**)&wlo, g_wt_lo);

    int gemm_smem = 1024 + 2 * BUF_STRIDE;           // 197632 B
    int ka_smem = (4096 + 64 * 65 + 4096) * 4;       // 49408 B
    int dt_smem = 16 * 1028 * 4;                     // 65792 B
    cudaFuncSetAttribute(gemm_t, cudaFuncAttributeMaxDynamicSharedMemorySize, gemm_smem);
    cudaFuncSetAttribute(ka_kernel, cudaFuncAttributeMaxDynamicSharedMemorySize, ka_smem);
    cudaFuncSetAttribute(dt2, cudaFuncAttributeMaxDynamicSharedMemorySize, dt_smem);

    // 1. split hs -> bf16 hi/lo
    fsplit<<<(MM * DD / 4) / 256, 256>>>(hs, ahi, alo);
    // 2. transpose+split weights
    dim3 wg(32, 32);
    wsplit<<<wg, 256>>>(Wc,   whi + 0 * (size_t)DD * DD, wlo + 0 * (size_t)DD * DD);
    wsplit<<<wg, 256>>>(Wb,   whi + 1 * (size_t)DD * DD, wlo + 1 * (size_t)DD * DD);
    wsplit<<<wg, 256>>>(Wx,   whi + 2 * (size_t)DD * DD, wlo + 2 * (size_t)DD * DD);
    wsplit<<<wg, 256>>>(Wout, whi + 3 * (size_t)DD * DD, wlo + 3 * (size_t)DD * DD);

    // 3. tensor-core projections
    dim3 gg(GN / 256, MM / 128);
    gemm_t<<<gg, 256, gemm_smem>>>(ahi, alo, whi + 0 * (size_t)DD * DD, wlo + 0 * (size_t)DD * DD, pc);
    gemm_t<<<gg, 256, gemm_smem>>>(ahi, alo, whi + 1 * (size_t)DD * DD, wlo + 1 * (size_t)DD * DD, pb);
    gemm_t<<<gg, 256, gemm_smem>>>(ahi, alo, whi + 2 * (size_t)DD * DD, wlo + 2 * (size_t)DD * DD, px);

    // 4. dt + elementwise + SSM core
    dt2<<<MM / 32, 256, dt_smem>>>(hs, Wdt);
    rope_kernel<<<(MM * HH * 32) / 256, 256>>>(cosp, sinp);
    acum_kernel<<<BB * NCC * HH, 256>>>(A);
    ka_kernel<<<BB * NCC * HH * 4, 256, ka_smem>>>();
    kb_kernel<<<BB * NCC * HH, 256>>>();
    kc_kernel<<<BB * HH, 256>>>(fs);
    kd_kernel<<<BB * NCC * HH * 4, 256>>>();

    // 5. output projection: split y then GEMM (reuses hi/lo buffers)
    fsplit<<<(MM * DD / 4) / 256, 256>>>(py, ahi, alo);
    gemm_t<<<gg, 256, gemm_smem>>>(ahi, alo, whi + 3 * (size_t)DD * DD, wlo + 3 * (size_t)DD * DD, out);
}

// round 4
// speedup vs baseline: 3.1215x; 1.1121x over previous
#include <cuda_runtime.h>
#include <cuda_bf16.h>
#include <math.h>
#include <stdint.h>

// Problem constants (fixed by the dataset)
#define BB  2
#define LL  8192
#define DD  1024
#define HH  16
#define PP  64
#define CLc 256
#define NCC 32
#define MM  (BB*LL)   // 16384 rows

#if defined(__CUDA_ARCH_FEAT_SM103_ALL) || defined(__CUDA_ARCH_FEAT_SM100_ALL) || \
    defined(__CUDA_ARCH_FEAT_SM101_ALL) || defined(__CUDA_ARCH_SPECIFIC__)
#define HAS_TCGEN05 1
#else
#define HAS_TCGEN05 0
#endif

// ---------------------------------------------------------------------------
// Scratch
// ---------------------------------------------------------------------------
__device__ float g_c[BB*LL*DD];     // post-GEMM c (rope applied at consumption)
__device__ float g_b[BB*LL*DD];
__device__ float g_x[BB*LL*DD];     // raw x (dt applied at consumption)
__device__ float g_dt[BB*LL*HH];
__device__ float g_ac[BB*LL*HH];
__device__ float g_cdec[BB*NCC*HH];
__device__ float g_states[BB*NCC*HH*PP*PP];
__device__ float g_prev[BB*NCC*HH*PP*PP];

__device__ __nv_bfloat16 g_ahi[MM*DD];
__device__ __nv_bfloat16 g_alo[MM*DD];
__device__ __nv_bfloat16 g_wt_hi[4][DD*DD];
__device__ __nv_bfloat16 g_wt_lo[4][DD*DD];

// ---------------------------------------------------------------------------
// Helpers
// ---------------------------------------------------------------------------
__device__ __forceinline__ uint32_t smem_u32(const void* p) {
    uint32_t a;
    asm("{ .reg .u64 t; cvta.to.shared.u64 t, %1; cvt.u32.u64 %0, t; }"
        : "=r"(a) : "l"(p));
    return a;
}
__device__ __forceinline__ uint32_t swz(uint32_t off) { return off ^ ((off >> 3) & 0x70); }

__device__ __forceinline__ void split2(float v, float& hi, float& lo) {
    __nv_bfloat16 h = __float2bfloat16(v);
    hi = __bfloat162float(h);
    lo = v - hi;
}
__device__ __forceinline__ uint32_t pack_bf2(float a, float b) {
    __nv_bfloat162 t = __halves2bfloat162(__float2bfloat16(a), __float2bfloat16(b));
    return *(uint32_t*)&t;
}
__device__ __forceinline__ void st_split_bf16(char* hi, char* lo, uint32_t off, float v) {
    __nv_bfloat16 h = __float2bfloat16(v);
    __nv_bfloat16 l = __float2bfloat16(v - __bfloat162float(h));
    *(__nv_bfloat16*)(hi + off) = h;
    *(__nv_bfloat16*)(lo + off) = l;
}

#if HAS_TCGEN05
__device__ __forceinline__ uint32_t elect_one() {
    uint32_t pred;
    asm volatile("{\n\t.reg .pred p;\n\telect.sync _|p, 0xFFFFFFFF;\n\t"
                 "selp.b32 %0, 1, 0, p;\n\t}" : "=r"(pred));
    return pred;
}
#define MBAR_INIT(a, c) \
    asm volatile("mbarrier.init.shared.b64 [%0], %1;" :: "r"(a), "r"(c) : "memory")
#define MBAR_WAIT(a, ph) do { \
    asm volatile("{\n\t.reg .pred P1;\n\t" \
        "WL_%=:\n\t" \
        "mbarrier.try_wait.parity.acquire.cta.shared::cta.b64 P1, [%0], %1, 0x989680;\n\t" \
        "@P1 bra.uni WD_%=;\n\tbra.uni WL_%=;\n\tWD_%=:\n\t}" \
        :: "r"(a), "r"(ph) : "memory"); \
} while (0)
#define TC_ALLOC(sa, n) \
    asm volatile("tcgen05.alloc.cta_group::1.sync.aligned.shared::cta.b32 [%0], %1;" \
                 :: "r"(sa), "r"(n) : "memory")
#define TC_DEALLOC(t, n) \
    asm volatile("tcgen05.dealloc.cta_group::1.sync.aligned.b32 %0, %1;" :: "r"(t), "r"(n))
#define TC_COMMIT(a) \
    asm volatile("tcgen05.commit.cta_group::1.mbarrier::arrive::one.shared::cluster.b64 [%0];" \
                 :: "r"(a) : "memory")
#define TC_FENCE_AFTER() asm volatile("tcgen05.fence::after_thread_sync;" ::: "memory")
#define TC_FENCE_BEFORE() asm volatile("tcgen05.fence::before_thread_sync;" ::: "memory")
#define TC_WAIT_LD() asm volatile("tcgen05.wait::ld.sync.aligned;" ::: "memory")
#define FENCE_ASYNC() asm volatile("fence.proxy.async.shared::cta;" ::: "memory")

__device__ __forceinline__ void mma_f16_ss(uint32_t d, uint64_t ad, uint64_t bd,
                                           uint32_t idesc, uint32_t en) {
    asm volatile("{\n\t.reg .pred p;\n\tsetp.ne.u32 p, %4, 0;\n\t"
                 "tcgen05.mma.cta_group::1.kind::f16 [%0], %1, %2, %3, {%5,%5,%5,%5}, p;\n\t}"
                 :: "r"(d), "l"(ad), "l"(bd), "r"(idesc), "r"(en), "r"(0u) : "memory");
}
__device__ __forceinline__ void ldtm32(uint32_t* r, uint32_t ta) {
    asm volatile("tcgen05.ld.sync.aligned.32x32b.x32.b32 "
        "{%0,%1,%2,%3,%4,%5,%6,%7,%8,%9,%10,%11,%12,%13,%14,%15,"
        "%16,%17,%18,%19,%20,%21,%22,%23,%24,%25,%26,%27,%28,%29,%30,%31}, [%32];"
        : "=r"(r[0]),"=r"(r[1]),"=r"(r[2]),"=r"(r[3]),"=r"(r[4]),"=r"(r[5]),"=r"(r[6]),"=r"(r[7]),
          "=r"(r[8]),"=r"(r[9]),"=r"(r[10]),"=r"(r[11]),"=r"(r[12]),"=r"(r[13]),"=r"(r[14]),"=r"(r[15]),
          "=r"(r[16]),"=r"(r[17]),"=r"(r[18]),"=r"(r[19]),"=r"(r[20]),"=r"(r[21]),"=r"(r[22]),"=r"(r[23]),
          "=r"(r[24]),"=r"(r[25]),"=r"(r[26]),"=r"(r[27]),"=r"(r[28]),"=r"(r[29]),"=r"(r[30]),"=r"(r[31])
        : "r"(ta));
}
static constexpr uint64_t DESC_BASE =
    (uint64_t(2) << 61) | (uint64_t(1) << 46) | (uint64_t(64) << 32) | (uint64_t(1) << 16);
__device__ __forceinline__ uint64_t mk_desc(uint32_t addr) {
    return DESC_BASE | ((uint64_t)(addr >> 4) & 0x3FFF);
}
#define IDESC_N(N) ((1u<<4)|(1u<<7)|(1u<<10)|(((N)/8u)<<17)|(8u<<24))
#endif  // HAS_TCGEN05

// ---------------------------------------------------------------------------
// fsplit / wsplit (unchanged)
// ---------------------------------------------------------------------------
__global__ __launch_bounds__(256) void fsplit(const float* __restrict__ in,
                                              __nv_bfloat16* __restrict__ hi,
                                              __nv_bfloat16* __restrict__ lo) {
    int idx = blockIdx.x * 256 + threadIdx.x;
    float4 v = ((const float4*)in)[idx];
    __nv_bfloat16 h0 = __float2bfloat16(v.x), h1 = __float2bfloat16(v.y);
    __nv_bfloat16 h2 = __float2bfloat16(v.z), h3 = __float2bfloat16(v.w);
    __nv_bfloat16 l0 = __float2bfloat16(v.x - __bfloat162float(h0));
    __nv_bfloat16 l1 = __float2bfloat16(v.y - __bfloat162float(h1));
    __nv_bfloat16 l2 = __float2bfloat16(v.z - __bfloat162float(h2));
    __nv_bfloat16 l3 = __float2bfloat16(v.w - __bfloat162float(h3));
    ((__nv_bfloat162*)hi)[idx*2]     = __halves2bfloat162(h0, h1);
    ((__nv_bfloat162*)hi)[idx*2 + 1] = __halves2bfloat162(h2, h3);
    ((__nv_bfloat162*)lo)[idx*2]     = __halves2bfloat162(l0, l1);
    ((__nv_bfloat162*)lo)[idx*2 + 1] = __halves2bfloat162(l2, l3);
}

__global__ __launch_bounds__(256) void wsplit(const float* __restrict__ W,
                                              __nv_bfloat16* __restrict__ Thi,
                                              __nv_bfloat16* __restrict__ Tlo) {
    __shared__ float t[32][33];
    int bx = blockIdx.x * 32, by = blockIdx.y * 32;
    int x = threadIdx.x & 31, y = threadIdx.x >> 5;
#pragma unroll
    for (int j = 0; j < 4; j++)
        t[y + j*8][x] = W[(size_t)(by + y + j*8) * DD + bx + x];
    __syncthreads();
#pragma unroll
    for (int j = 0; j < 4; j++) {
        float v = t[x][y + j*8];
        __nv_bfloat16 h = __float2bfloat16(v);
        __nv_bfloat16 l = __float2bfloat16(v - __bfloat162float(h));
        size_t o = (size_t)(bx + y + j*8) * DD + by + x;
        Thi[o] = h; Tlo[o] = l;
    }
}

// ---------------------------------------------------------------------------
// tcgen05 GEMM (unchanged from R3, with CUDA-core fallback)
// ---------------------------------------------------------------------------
#define GK 1024
#define GN 1024
#define NCHUNK 16
#define BUF_STRIDE 98304
#define GIDESC ((1u<<4)|(1u<<7)|(1u<<10)|((256u/8)<<17)|((128u/16)<<24))

__global__ __launch_bounds__(256, 1) void gemm_t(
        const __nv_bfloat16* __restrict__ Ahi, const __nv_bfloat16* __restrict__ Alo,
        const __nv_bfloat16* __restrict__ Bhi, const __nv_bfloat16* __restrict__ Blo,
        float* __restrict__ C) {
    extern __shared__ char sm[];
#if HAS_TCGEN05
    uint32_t sbase = smem_u32(sm);
    int tid = threadIdx.x;
    int wid = tid >> 5, lid = tid & 31;
    int bn = blockIdx.x * 256, bm = blockIdx.y * 128;

    if (tid == 0) { MBAR_INIT(sbase + 8, 1); MBAR_INIT(sbase + 16, 1); }
    if (wid == 0) TC_ALLOC(sbase, 256);
    __syncthreads();
    uint32_t tmem;
    asm volatile("ld.shared.b32 %0, [%1];" : "=r"(tmem) : "r"(sbase));

    auto load_chunk = [&](int chunk, int buf) {
        uint32_t boff = 1024u + (uint32_t)buf * BUF_STRIDE;
        int k0 = chunk * 64;
#pragma unroll
        for (int t = 0; t < 4; t++) {
            int i = tid + t * 256;
            int r = i >> 3, c8 = i & 7;
            uint32_t so = swz((uint32_t)(r * 128 + c8 * 16));
            *(uint4*)(sm + boff + so) =
                *(const uint4*)(Ahi + (size_t)(bm + r) * GK + k0 + c8 * 8);
            *(uint4*)(sm + boff + 16384 + so) =
                *(const uint4*)(Alo + (size_t)(bm + r) * GK + k0 + c8 * 8);
        }
#pragma unroll
        for (int t = 0; t < 8; t++) {
            int i = tid + t * 256;
            int r = i >> 3, c8 = i & 7;
            uint32_t so = swz((uint32_t)(r * 128 + c8 * 16));
            *(uint4*)(sm + boff + 32768 + so) =
                *(const uint4*)(Bhi + (size_t)(bn + r) * GK + k0 + c8 * 8);
            *(uint4*)(sm + boff + 65536 + so) =
                *(const uint4*)(Blo + (size_t)(bn + r) * GK + k0 + c8 * 8);
        }
    };

    load_chunk(0, 0);
    FENCE_ASYNC();
    __syncthreads();

    int ph0 = 0, ph1 = 0;
    for (int k = 0; k < NCHUNK; k++) {
        int b = k & 1;
        if (wid == 0) {
            if (elect_one()) {
                uint32_t boff = sbase + 1024u + (uint32_t)b * BUF_STRIDE;
                uint64_t dah = mk_desc(boff);
                uint64_t dal = mk_desc(boff + 16384);
                uint64_t dbh = mk_desc(boff + 32768);
                uint64_t dbl = mk_desc(boff + 65536);
#pragma unroll
                for (int ks = 0; ks < 4; ks++) {
                    mma_f16_ss(tmem, dah + ks*2, dbh + ks*2, GIDESC,
                               (k == 0 && ks == 0) ? 0u : 1u);
                    mma_f16_ss(tmem, dah + ks*2, dbl + ks*2, GIDESC, 1u);
                    mma_f16_ss(tmem, dal + ks*2, dbh + ks*2, GIDESC, 1u);
                }
                TC_COMMIT(sbase + 8 + (uint32_t)b * 8);
            }
        }
        if (k + 1 < NCHUNK) {
            int nb = (k + 1) & 1;
            if (k >= 1) {
                uint32_t mb = sbase + 8 + (uint32_t)nb * 8;
                if (nb == 0) { MBAR_WAIT(mb, ph0); ph0 ^= 1; }
                else         { MBAR_WAIT(mb, ph1); ph1 ^= 1; }
            }
            load_chunk(k + 1, nb);
            FENCE_ASYNC();
            __syncthreads();
        }
    }
    MBAR_WAIT(sbase + 16, ph1);
    TC_FENCE_AFTER();

    if (wid < 4) {
        int row = bm + wid * 32 + lid;
        float* crow = C + (size_t)row * GN + bn;
#pragma unroll
        for (int cb = 0; cb < 8; cb++) {
            uint32_t r[32];
            ldtm32(r, tmem + cb * 32);
            TC_WAIT_LD();
#pragma unroll
            for (int j = 0; j < 8; j++) {
                float4 v = make_float4(__uint_as_float(r[j*4]), __uint_as_float(r[j*4+1]),
                                       __uint_as_float(r[j*4+2]), __uint_as_float(r[j*4+3]));
                *(float4*)(crow + cb * 32 + j * 4) = v;
            }
        }
        TC_FENCE_BEFORE();
    }
    __syncthreads();
    if (wid == 0) TC_DEALLOC(tmem, 256);
#else
    int tid = threadIdx.x;
    int tx = tid & 15, ty = tid >> 4;
    int bn = blockIdx.x * 256, bm = blockIdx.y * 128;
    float* sA = (float*)sm;
    float* sB = (float*)(sm + 8192);
    for (int half = 0; half < 2; half++) {
        int bn2 = bn + half * 128;
        float acc[8][8];
#pragma unroll
        for (int i = 0; i < 8; i++)
#pragma unroll
            for (int j = 0; j < 8; j++) acc[i][j] = 0.f;
        for (int k0 = 0; k0 < GK; k0 += 16) {
            for (int i = tid; i < 2048; i += 256) {
                int r = i >> 4, kk = i & 15;
                sA[kk*128 + r] = __bfloat162float(Ahi[(size_t)(bm + r)*GK + k0 + kk]) +
                                 __bfloat162float(Alo[(size_t)(bm + r)*GK + k0 + kk]);
                sB[kk*128 + r] = __bfloat162float(Bhi[(size_t)(bn2 + r)*GK + k0 + kk]) +
                                 __bfloat162float(Blo[(size_t)(bn2 + r)*GK + k0 + kk]);
            }
            __syncthreads();
#pragma unroll
            for (int kk = 0; kk < 16; kk++) {
                float a[8], b[8];
#pragma unroll
                for (int i = 0; i < 4; i++) {
                    a[i] = sA[kk*128 + ty*4 + i];
                    a[i+4] = sA[kk*128 + 64 + ty*4 + i];
                    b[i] = sB[kk*128 + tx*4 + i];
                    b[i+4] = sB[kk*128 + 64 + tx*4 + i];
                }
#pragma unroll
                for (int i = 0; i < 8; i++)
#pragma unroll
                    for (int j = 0; j < 8; j++) acc[i][j] += a[i] * b[j];
            }
            __syncthreads();
        }
#pragma unroll
        for (int i = 0; i < 8; i++) {
            int row = bm + ((i < 4) ? (ty*4 + i) : (64 + ty*4 + i - 4));
#pragma unroll
            for (int j = 0; j < 8; j++) {
                int col = bn2 + ((j < 4) ? (tx*4 + j) : (64 + tx*4 + j - 4));
                C[(size_t)row * GN + col] = acc[i][j];
            }
        }
        __syncthreads();
    }
#endif
}

// ---------------------------------------------------------------------------
// dt = softplus(hs @ Wdt)
// ---------------------------------------------------------------------------
__global__ __launch_bounds__(256) void dt2(const float* __restrict__ hs,
                                           const float* __restrict__ Wdt) {
    extern __shared__ float sw[];
    int tid = threadIdx.x;
    for (int i = tid; i < 16384; i += 256)
        sw[(i & 15) * 1028 + (i >> 4)] = Wdt[i];
    __syncthreads();
    int w = tid >> 5, l = tid & 31;
    int row0 = blockIdx.x * 32 + w * 4;
    float acc[4][16];
#pragma unroll
    for (int r = 0; r < 4; r++)
#pragma unroll
        for (int n = 0; n < 16; n++) acc[r][n] = 0.f;
#pragma unroll
    for (int it = 0; it < 8; it++) {
        int k0 = it * 128 + l * 4;
        float4 h[4];
#pragma unroll
        for (int r = 0; r < 4; r++)
            h[r] = *(const float4*)&hs[(size_t)(row0 + r) * DD + k0];
#pragma unroll
        for (int n = 0; n < 16; n++) {
            float4 wv = *(const float4*)&sw[n * 1028 + k0];
#pragma unroll
            for (int r = 0; r < 4; r++)
                acc[r][n] += h[r].x*wv.x + h[r].y*wv.y + h[r].z*wv.z + h[r].w*wv.w;
        }
    }
#pragma unroll
    for (int off = 16; off; off >>= 1)
#pragma unroll
        for (int r = 0; r < 4; r++)
#pragma unroll
            for (int n = 0; n < 16; n++)
                acc[r][n] += __shfl_xor_sync(0xFFFFFFFFu, acc[r][n], off);
    if (l == 0) {
#pragma unroll
        for (int r = 0; r < 4; r++)
#pragma unroll
            for (int n = 0; n < 16; n++) {
                float s = acc[r][n];
                g_dt[(row0 + r) * HH + n] = fmaxf(s, 0.f) + log1pf(expf(-fabsf(s)));
            }
    }
}

// ---------------------------------------------------------------------------
// Per-chunk inclusive cumsum of dA
// ---------------------------------------------------------------------------
__global__ __launch_bounds__(256) void acum_kernel(const float* __restrict__ A) {
    __shared__ float s[256];
    int bid = blockIdx.x;
    int h = bid & 15, c = (bid >> 4) & 31, b = bid >> 9;
    int l = threadIdx.x;
    int row = b * LL + c * CLc + l;
    s[l] = g_dt[row * HH + h] * A[h];
    __syncthreads();
    for (int off = 1; off < 256; off <<= 1) {
        float u = (l >= off) ? s[l - off] : 0.f;
        __syncthreads();
        s[l] += u;
        __syncthreads();
    }
    g_ac[row * HH + h] = s[l];
    if (l == 255) g_cdec[bid] = expf(s[255]);
}

// ---------------------------------------------------------------------------
// Chunk states (rope + x*dt fused into the fill)
// ---------------------------------------------------------------------------
__global__ __launch_bounds__(256) void kb_kernel(const float* __restrict__ cosp,
                                                 const float* __restrict__ sinp) {
    __shared__ float sX[4096];
    __shared__ float sB[4096];
    int bid = blockIdx.x;
    int h = bid & 15, c = (bid >> 4) & 31, b = bid >> 9;
    int tid = threadIdx.x, tx = tid & 15, ty = tid >> 4;
    int chunk_row = b * LL + c * CLc;
    float aclast = g_ac[(chunk_row + 255) * HH + h];

    float acc[4][4];
#pragma unroll
    for (int i = 0; i < 4; i++)
#pragma unroll
        for (int j = 0; j < 4; j++) acc[i][j] = 0.f;

    for (int ltile = 0; ltile < 4; ltile++) {
        int r0 = chunk_row + ltile * 64;
#pragma unroll
        for (int t = 0; t < 8; t++) {                 // 2048 pairs / 256 thr
            int pr = tid + t * 256;
            int rr = pr >> 5, pp = pr & 31;
            int row = r0 + rr;
            const float* bb = g_b + (size_t)row * DD + h * 64;
            const float* xx = g_x + (size_t)row * DD + h * 64;
            float a = bb[pp], q = bb[pp + 32];
            float c1 = cosp[row*64 + pp],      s1 = sinp[row*64 + pp];
            float c2 = cosp[row*64 + pp + 32], s2 = sinp[row*64 + pp + 32];
            float w = expf(aclast - g_ac[row * HH + h]);
            float dtv = g_dt[row * HH + h];
            sB[rr*64 + pp]      = (a * c1 - q * s1) * w;
            sB[rr*64 + pp + 32] = (q * c2 + a * s2) * w;
            sX[rr*64 + pp]      = xx[pp] * dtv;
            sX[rr*64 + pp + 32] = xx[pp + 32] * dtv;
        }
        __syncthreads();
#pragma unroll 4
        for (int l = 0; l < 64; l++) {
            float xv[4], bv[4];
#pragma unroll
            for (int i = 0; i < 4; i++) xv[i] = sX[l * 64 + ty * 4 + i];
#pragma unroll
            for (int j = 0; j < 4; j++) bv[j] = sB[l * 64 + tx * 4 + j];
#pragma unroll
            for (int i = 0; i < 4; i++)
#pragma unroll
                for (int j = 0; j < 4; j++) acc[i][j] += xv[i] * bv[j];
        }
        __syncthreads();
    }
    int sb = ((b * NCC + c) * HH + h) * 4096;
#pragma unroll
    for (int i = 0; i < 4; i++) {
        float4 v = make_float4(acc[i][0], acc[i][1], acc[i][2], acc[i][3]);
        *(float4*)&g_states[sb + (ty * 4 + i) * 64 + tx * 4] = v;
    }
}

// ---------------------------------------------------------------------------
// Sequential chunk scan
// ---------------------------------------------------------------------------
__global__ __launch_bounds__(256) void kc_kernel(float* __restrict__ fs) {
    int bid = blockIdx.x;
    int h = bid & 15, b = bid >> 4;
    int tid = threadIdx.x;
    float st[16];
#pragma unroll
    for (int k = 0; k < 16; k++) st[k] = 0.f;
    for (int c = 0; c < NCC; c++) {
        float dec = g_cdec[(b * NCC + c) * HH + h];
        int base = ((b * NCC + c) * HH + h) * 4096;
#pragma unroll
        for (int k = 0; k < 16; k++) {
            int e = k * 256 + tid;
            g_prev[base + e] = st[k];
            st[k] = st[k] * dec + g_states[base + e];
        }
    }
    int fb = (b * HH + h) * 4096;
#pragma unroll
    for (int k = 0; k < 16; k++) fs[fb + k * 256 + tid] = st[k];
}

// ---------------------------------------------------------------------------
// Flash kernel: Y_diag + Y_off on tensor cores, writes y hi/lo split directly.
// One block per (b,c,h,half=128 rows). 256 threads.
// ---------------------------------------------------------------------------
#define FL_SMEM 182272
#define FO_AC   64
#define FO_CHI  2048
#define FO_CLO  18432
#define FO_BHI  34816
#define FO_BLO  67584
#define FO_XHI  100352
#define FO_XLO  133120
#define FO_PHI  165888
#define FO_PLO  174080

__global__ __launch_bounds__(256, 1) void flash_k(const float* __restrict__ cosp,
                                                  const float* __restrict__ sinp,
                                                  __nv_bfloat16* __restrict__ yhi,
                                                  __nv_bfloat16* __restrict__ ylo) {
    extern __shared__ char sm[];
    int tid = threadIdx.x, wid = tid >> 5, lid = tid & 31;
    int bid = blockIdx.x;
    int half = bid & 1, h = (bid >> 1) & 15, c = (bid >> 5) & 31, b = bid >> 10;
    int chunk_row = b * LL + c * CLc;
    int l0g = half * 128;
    int SL = half ? 256 : 128;
    float* acs = (float*)(sm + FO_AC);

#if HAS_TCGEN05
    uint32_t sbase = smem_u32(sm);
    int nsl = SL / 128;
    if (tid == 0) {
        MBAR_INIT(sbase + 8, 1);  MBAR_INIT(sbase + 16, 1);
        MBAR_INIT(sbase + 24, 1); MBAR_INIT(sbase + 32, 1);
    }
    if (wid == 0) TC_ALLOC(sbase, 512);
    __syncthreads();
    uint32_t tmem;
    asm volatile("ld.shared.b32 %0, [%1];" : "=r"(tmem) : "r"(sbase));

    acs[tid] = g_ac[(chunk_row + tid) * HH + h];

    // C tile (rope) 128x64 hi/lo
    for (int t = 0; t < 16; t++) {
        int pr = tid + t * 256;
        int rr = pr >> 5, pp = pr & 31;
        int row = chunk_row + l0g + rr;
        const float* cb = g_c + (size_t)row * DD + h * 64;
        float a = cb[pp], q = cb[pp + 32];
        float c1 = cosp[row*64 + pp],      s1 = sinp[row*64 + pp];
        float c2 = cosp[row*64 + pp + 32], s2 = sinp[row*64 + pp + 32];
        float v1 = a * c1 - q * s1;
        float v2 = q * c2 + a * s2;
        st_split_bf16(sm + FO_CHI, sm + FO_CLO, swz(rr*128 + pp*2), v1);
        st_split_bf16(sm + FO_CHI, sm + FO_CLO, swz(rr*128 + (pp+32)*2), v2);
    }
    // B tile (rope) SLx64 hi/lo
    for (int t = 0; t < SL/8; t++) {
        int pr = tid + t * 256;
        int rr = pr >> 5, pp = pr & 31;
        int row = chunk_row + rr;
        const float* bb = g_b + (size_t)row * DD + h * 64;
        float a = bb[pp], q = bb[pp + 32];
        float c1 = cosp[row*64 + pp],      s1 = sinp[row*64 + pp];
        float c2 = cosp[row*64 + pp + 32], s2 = sinp[row*64 + pp + 32];
        float v1 = a * c1 - q * s1;
        float v2 = q * c2 + a * s2;
        st_split_bf16(sm + FO_BHI, sm + FO_BLO, swz(rr*128 + pp*2), v1);
        st_split_bf16(sm + FO_BHI, sm + FO_BLO, swz(rr*128 + (pp+32)*2), v2);
    }
    // X^T tile: [64 p][SL s] bf16 blocked atoms (8 p-rows per atom), x*dt fused
    for (int t = 0; t < SL/8; t++) {
        int idx = tid + t * 256;
        int p = idx & 63, sp = idx >> 6;
        int s = sp * 2;
        int row1 = chunk_row + s, row2 = row1 + 1;
        float x1 = g_x[(size_t)row1 * DD + h*64 + p] * g_dt[row1*HH + h];
        float x2 = g_x[(size_t)row2 * DD + h*64 + p] * g_dt[row2*HH + h];
        float h1, lo1, h2, lo2;
        split2(x1, h1, lo1); split2(x2, h2, lo2);
        uint32_t off = swz((uint32_t)(((p>>3) + (s>>6)*8)*1024 + (p&7)*128 + (s&63)*2));
        *(uint32_t*)(sm + FO_XHI + off) = pack_bf2(h1, h2);
        *(uint32_t*)(sm + FO_XLO + off) = pack_bf2(lo1, lo2);
    }
    // prev tile [64 p][64 n]
    {
        int pbase = ((b * NCC + c) * HH + h) * 4096;
        for (int t = 0; t < 16; t++) {
            int idx = tid + t * 256;
            int p = idx >> 6, n = idx & 63;
            float v = g_prev[pbase + idx];
            st_split_bf16(sm + FO_PHI, sm + FO_PLO, swz(p*128 + n*2), v);
        }
    }
    FENCE_ASYNC();
    __syncthreads();

    // MMA1: S = C * B^T (N = SL), plus off-term Y2 = C * prev^T
    if (wid == 0 && elect_one()) {
        uint64_t dCh = mk_desc(sbase + FO_CHI), dCl = mk_desc(sbase + FO_CLO);
        uint64_t dBh = mk_desc(sbase + FO_BHI), dBl = mk_desc(sbase + FO_BLO);
        uint32_t id1 = (SL == 128) ? IDESC_N(128) : IDESC_N(256);
#pragma unroll
        for (int ks = 0; ks < 4; ks++) {
            mma_f16_ss(tmem, dCh + ks*2, dBh + ks*2, id1, ks > 0);
            mma_f16_ss(tmem, dCh + ks*2, dBl + ks*2, id1, 1);
            mma_f16_ss(tmem, dCl + ks*2, dBh + ks*2, id1, 1);
        }
        TC_COMMIT(sbase + 8);
        uint64_t dPh = mk_desc(sbase + FO_PHI), dPl = mk_desc(sbase + FO_PLO);
        uint32_t id64 = IDESC_N(64);
#pragma unroll
        for (int ks = 0; ks < 4; ks++) {
            mma_f16_ss(tmem + 320, dCh + ks*2, dPh + ks*2, id64, ks > 0);
            mma_f16_ss(tmem + 320, dCh + ks*2, dPl + ks*2, id64, 1);
            mma_f16_ss(tmem + 320, dCl + ks*2, dPh + ks*2, id64, 1);
        }
        TC_COMMIT(sbase + 16);
    }
    MBAR_WAIT(sbase + 8, 0);
    TC_FENCE_AFTER();

    int lrow = wid * 32 + lid;                  // valid for wid<4
    float acl = acs[l0g + (lrow & 127)];

    for (int sl = 0; sl < nsl; sl++) {
        if (sl == 1) MBAR_WAIT(sbase + 24, 0);  // slice-0 MMAs done with smem
        if (wid < 4) {
#pragma unroll
            for (int rd = 0; rd < 4; rd++) {
                uint32_t r[32];
                ldtm32(r, tmem + sl*128 + rd*32);
                TC_WAIT_LD();
                int colbase = sl*128 + rd*32;
#pragma unroll
                for (int j = 0; j < 32; j += 2) {
                    int cg0 = colbase + j, cg1 = cg0 + 1;
                    float v0 = __uint_as_float(r[j]);
                    float v1 = __uint_as_float(r[j+1]);
                    v0 = (cg0 <= l0g + lrow) ? v0 * expf(acl - acs[cg0]) : 0.f;
                    v1 = (cg1 <= l0g + lrow) ? v1 * expf(acl - acs[cg1]) : 0.f;
                    float h0, lo0, h1, lo1;
                    split2(v0, h0, lo0); split2(v1, h1, lo1);
                    int sIn = rd*32 + j;
                    uint32_t off = swz((uint32_t)(((lrow>>3) + (sIn>>6)*16)*1024
                                                  + (lrow&7)*128 + (sIn&63)*2));
                    *(uint32_t*)(sm + FO_BHI + off) = pack_bf2(h0, h1);
                    *(uint32_t*)(sm + FO_BLO + off) = pack_bf2(lo0, lo1);
                }
            }
            FENCE_ASYNC();
        }
        __syncthreads();
        if (wid == 0 && elect_one()) {
            uint64_t dSh = mk_desc(sbase + FO_BHI), dSl = mk_desc(sbase + FO_BLO);
            uint64_t dXh = mk_desc(sbase + FO_XHI), dXl = mk_desc(sbase + FO_XLO);
            uint32_t id64 = IDESC_N(64);
#pragma unroll
            for (int ks2 = 0; ks2 < 8; ks2++) {
                int ksg = sl*8 + ks2;
                uint64_t ao = (uint64_t)((ks2 >> 2)*1024 + (ks2 & 3)*2);
                uint64_t bo = (uint64_t)((ksg >> 2)*512 + (ksg & 3)*2);
                mma_f16_ss(tmem + 256, dSh + ao, dXh + bo, id64,
                           !(sl == 0 && ks2 == 0));
                mma_f16_ss(tmem + 256, dSh + ao, dXl + bo, id64, 1);
                mma_f16_ss(tmem + 256, dSl + ao, dXh + bo, id64, 1);
            }
            TC_COMMIT(sbase + 24 + (uint32_t)sl * 8);
        }
    }
    MBAR_WAIT(sbase + 24 + (uint32_t)(nsl - 1) * 8, 0);
    MBAR_WAIT(sbase + 16, 0);
    TC_FENCE_AFTER();

    if (wid < 4) {
        int row = chunk_row + l0g + lrow;
        float e = expf(acl);
        uint32_t* dsthi = (uint32_t*)(yhi + (size_t)row * DD + h * 64);
        uint32_t* dstlo = (uint32_t*)(ylo + (size_t)row * DD + h * 64);
#pragma unroll
        for (int hb = 0; hb < 2; hb++) {
            uint32_t y1[32], y2[32];
            ldtm32(y1, tmem + 256 + hb*32); TC_WAIT_LD();
            ldtm32(y2, tmem + 320 + hb*32); TC_WAIT_LD();
#pragma unroll
            for (int j = 0; j < 32; j += 2) {
                float v0 = __uint_as_float(y1[j])   + e * __uint_as_float(y2[j]);
                float v1 = __uint_as_float(y1[j+1]) + e * __uint_as_float(y2[j+1]);
                float h0, lo0, h1, lo1;
                split2(v0, h0, lo0); split2(v1, h1, lo1);
                dsthi[hb*16 + j/2] = pack_bf2(h0, h1);
                dstlo[hb*16 + j/2] = pack_bf2(lo0, lo1);
            }
        }
        TC_FENCE_BEFORE();
    }
    __syncthreads();
    if (wid == 0) TC_DEALLOC(tmem, 512);
#else
    // CUDA-core fallback (non-'a' pass only)
    float* sC = (float*)(sm + 2048);      // [128][64]
    float* sS = (float*)(sm + 34816);     // [128][64]
    float* sB = (float*)(sm + 67584);     // [64][64]
    float* sX = (float*)(sm + 83968);     // [64][64]
    float* sP = (float*)(sm + 100352);    // [64][64]
    int tx = tid & 15, ty = tid >> 4;

    acs[tid] = g_ac[(chunk_row + tid) * HH + h];
    for (int t = 0; t < 16; t++) {
        int pr = tid + t * 256;
        int rr = pr >> 5, pp = pr & 31;
        int row = chunk_row + l0g + rr;
        const float* cb = g_c + (size_t)row * DD + h * 64;
        float a = cb[pp], q = cb[pp + 32];
        float c1 = cosp[row*64 + pp],      s1 = sinp[row*64 + pp];
        float c2 = cosp[row*64 + pp + 32], s2 = sinp[row*64 + pp + 32];
        sC[rr*64 + pp]      = a * c1 - q * s1;
        sC[rr*64 + pp + 32] = q * c2 + a * s2;
    }
    {
        int pbase = ((b * NCC + c) * HH + h) * 4096;
        for (int t = 0; t < 16; t++) {
            int idx = tid + t * 256;
            sP[idx] = g_prev[pbase + idx];
        }
    }
    __syncthreads();

    float accD[8][4], accO[8][4];
#pragma unroll
    for (int i = 0; i < 8; i++)
#pragma unroll
        for (int j = 0; j < 4; j++) { accD[i][j] = 0.f; accO[i][j] = 0.f; }
    for (int n = 0; n < 64; n++)
#pragma unroll
        for (int i = 0; i < 8; i++)
#pragma unroll
            for (int j = 0; j < 4; j++)
                accO[i][j] += sC[(ty*8+i)*64 + n] * sP[(tx*4+j)*64 + n];

    for (int stile = 0; stile < SL/64; stile++) {
        for (int t = 0; t < 8; t++) {
            int pr = tid + t * 256;
            int rr = pr >> 5, pp = pr & 31;
            int row = chunk_row + stile*64 + rr;
            const float* bb = g_b + (size_t)row * DD + h * 64;
            const float* xx = g_x + (size_t)row * DD + h * 64;
            float a = bb[pp], q = bb[pp + 32];
            float c1 = cosp[row*64 + pp],      s1 = sinp[row*64 + pp];
            float c2 = cosp[row*64 + pp + 32], s2 = sinp[row*64 + pp + 32];
            float dtv = g_dt[row * HH + h];
            sB[rr*64 + pp]      = a * c1 - q * s1;
            sB[rr*64 + pp + 32] = q * c2 + a * s2;
            sX[rr*64 + pp]      = xx[pp] * dtv;
            sX[rr*64 + pp + 32] = xx[pp + 32] * dtv;
        }
        __syncthreads();
        for (int t = 0; t < 32; t++) {
            int idx = tid + t * 256;
            int l = idx >> 6, sIn = idx & 63;
            int sg = stile*64 + sIn;
            float v = 0.f;
            if (sg <= l0g + l) {
                for (int n = 0; n < 64; n++)
                    v += sC[l*64 + n] * sB[sIn*64 + n];
                v *= expf(acs[l0g + l] - acs[sg]);
            }
            sS[idx] = v;
        }
        __syncthreads();
        for (int s = 0; s < 64; s++)
#pragma unroll
            for (int i = 0; i < 8; i++)
#pragma unroll
                for (int j = 0; j < 4; j++)
                    accD[i][j] += sS[(ty*8+i)*64 + s] * sX[s*64 + tx*4 + j];
        __syncthreads();
    }
#pragma unroll
    for (int i = 0; i < 8; i++) {
        int lr = ty*8 + i;
        int row = chunk_row + l0g + lr;
        float e = expf(acs[l0g + lr]);
#pragma unroll
        for (int j = 0; j < 4; j++) {
            float v = accD[i][j] + e * accO[i][j];
            __nv_bfloat16 hb = __float2bfloat16(v);
            __nv_bfloat16 lb = __float2bfloat16(v - __bfloat162float(hb));
            yhi[(size_t)row * DD + h*64 + tx*4 + j] = hb;
            ylo[(size_t)row * DD + h*64 + tx*4 + j] = lb;
        }
    }
#endif
}

// ---------------------------------------------------------------------------
// kernel_launch
// ---------------------------------------------------------------------------
extern "C" void kernel_launch(void* const* d_in, const int* in_sizes, int n_in,
                              void* d_out, int out_size) {
    (void)in_sizes; (void)n_in; (void)out_size;
    const float* hs   = (const float*)d_in[0];
    const float* cosp = (const float*)d_in[1];
    const float* sinp = (const float*)d_in[2];
    const float* Wc   = (const float*)d_in[3];
    const float* Wb   = (const float*)d_in[4];
    const float* Wdt  = (const float*)d_in[5];
    const float* Wx   = (const float*)d_in[6];
    const float* Wout = (const float*)d_in[7];
    const float* A    = (const float*)d_in[8];
    float* out = (float*)d_out;
    float* fs  = out + (size_t)MM * DD;

    float *pc, *pb, *px;
    __nv_bfloat16 *ahi, *alo, *whi, *wlo;
    cudaGetSymbolAddress((void**)&pc, g_c);
    cudaGetSymbolAddress((void**)&pb, g_b);
    cudaGetSymbolAddress((void**)&px, g_x);
    cudaGetSymbolAddress((void**)&ahi, g_ahi);
    cudaGetSymbolAddress((void**)&alo, g_alo);
    cudaGetSymbolAddress((void**)&whi, g_wt_hi);
    cudaGetSymbolAddress((void**)&wlo, g_wt_lo);

    int gemm_smem = 1024 + 2 * BUF_STRIDE;           // 197632 B
    int dt_smem = 16 * 1028 * 4;                     // 65792 B
    cudaFuncSetAttribute(gemm_t, cudaFuncAttributeMaxDynamicSharedMemorySize, gemm_smem);
    cudaFuncSetAttribute(dt2, cudaFuncAttributeMaxDynamicSharedMemorySize, dt_smem);
    cudaFuncSetAttribute(flash_k, cudaFuncAttributeMaxDynamicSharedMemorySize, FL_SMEM);

    fsplit<<<(MM * DD / 4) / 256, 256>>>(hs, ahi, alo);
    dim3 wg(32, 32);
    wsplit<<<wg, 256>>>(Wc,   whi + 0 * (size_t)DD * DD, wlo + 0 * (size_t)DD * DD);
    wsplit<<<wg, 256>>>(Wb,   whi + 1 * (size_t)DD * DD, wlo + 1 * (size_t)DD * DD);
    wsplit<<<wg, 256>>>(Wx,   whi + 2 * (size_t)DD * DD, wlo + 2 * (size_t)DD * DD);
    wsplit<<<wg, 256>>>(Wout, whi + 3 * (size_t)DD * DD, wlo + 3 * (size_t)DD * DD);

    dim3 gg(GN / 256, MM / 128);
    gemm_t<<<gg, 256, gemm_smem>>>(ahi, alo, whi + 0 * (size_t)DD * DD, wlo + 0 * (size_t)DD * DD, pc);
    gemm_t<<<gg, 256, gemm_smem>>>(ahi, alo, whi + 1 * (size_t)DD * DD, wlo + 1 * (size_t)DD * DD, pb);
    gemm_t<<<gg, 256, gemm_smem>>>(ahi, alo, whi + 2 * (size_t)DD * DD, wlo + 2 * (size_t)DD * DD, px);

    dt2<<<MM / 32, 256, dt_smem>>>(hs, Wdt);
    acum_kernel<<<BB * NCC * HH, 256>>>(A);
    kb_kernel<<<BB * NCC * HH, 256>>>(cosp, sinp);
    kc_kernel<<<BB * HH, 256>>>(fs);

    flash_k<<<BB * NCC * HH * 2, 256, FL_SMEM>>>(cosp, sinp, ahi, alo);

    gemm_t<<<gg, 256, gemm_smem>>>(ahi, alo, whi + 3 * (size_t)DD * DD, wlo + 3 * (size_t)DD * DD, out);
}

// round 5
// speedup vs baseline: 3.3546x; 1.0747x over previous
#include <cuda_runtime.h>
#include <cuda_bf16.h>
#include <math.h>
#include <stdint.h>

// Problem constants (fixed by the dataset)
#define BB  2
#define LL  8192
#define DD  1024
#define HH  16
#define PP  64
#define CLc 256
#define NCC 32
#define MM  (BB*LL)   // 16384 rows

#if defined(__CUDA_ARCH_FEAT_SM103_ALL) || defined(__CUDA_ARCH_FEAT_SM100_ALL) || \
    defined(__CUDA_ARCH_FEAT_SM101_ALL) || defined(__CUDA_ARCH_SPECIFIC__)
#define HAS_TCGEN05 1
#else
#define HAS_TCGEN05 0
#endif

// ---------------------------------------------------------------------------
// Scratch
// ---------------------------------------------------------------------------
__device__ float g_c[BB*LL*DD];
__device__ float g_b[BB*LL*DD];
__device__ float g_x[BB*LL*DD];
__device__ float g_dt[BB*LL*HH];
__device__ float g_ac[BB*LL*HH];
__device__ float g_cdec[BB*NCC*HH];
__device__ float g_states[BB*NCC*HH*PP*PP];
__device__ float g_prev[BB*NCC*HH*PP*PP];

__device__ __nv_bfloat16 g_ahi[MM*DD];
__device__ __nv_bfloat16 g_alo[MM*DD];
__device__ __nv_bfloat16 g_wt_hi[4][DD*DD];
__device__ __nv_bfloat16 g_wt_lo[4][DD*DD];

// ---------------------------------------------------------------------------
// Helpers
// ---------------------------------------------------------------------------
__device__ __forceinline__ uint32_t smem_u32(const void* p) {
    uint32_t a;
    asm("{ .reg .u64 t; cvta.to.shared.u64 t, %1; cvt.u32.u64 %0, t; }"
        : "=r"(a) : "l"(p));
    return a;
}
__device__ __forceinline__ uint32_t swz(uint32_t off) { return off ^ ((off >> 3) & 0x70); }

__device__ __forceinline__ void split2(float v, float& hi, float& lo) {
    __nv_bfloat16 h = __float2bfloat16(v);
    hi = __bfloat162float(h);
    lo = v - hi;
}
__device__ __forceinline__ uint32_t pack_bf2(float a, float b) {
    __nv_bfloat162 t = __halves2bfloat162(__float2bfloat16(a), __float2bfloat16(b));
    return *(uint32_t*)&t;
}
__device__ __forceinline__ void st_split_bf16(char* hi, char* lo, uint32_t off, float v) {
    __nv_bfloat16 h = __float2bfloat16(v);
    __nv_bfloat16 l = __float2bfloat16(v - __bfloat162float(h));
    *(__nv_bfloat16*)(hi + off) = h;
    *(__nv_bfloat16*)(lo + off) = l;
}

#if HAS_TCGEN05
__device__ __forceinline__ uint32_t elect_one() {
    uint32_t pred;
    asm volatile("{\n\t.reg .pred p;\n\telect.sync _|p, 0xFFFFFFFF;\n\t"
                 "selp.b32 %0, 1, 0, p;\n\t}" : "=r"(pred));
    return pred;
}
#define MBAR_INIT(a, c) \
    asm volatile("mbarrier.init.shared.b64 [%0], %1;" :: "r"(a), "r"(c) : "memory")
#define MBAR_WAIT(a, ph) do { \
    asm volatile("{\n\t.reg .pred P1;\n\t" \
        "WL_%=:\n\t" \
        "mbarrier.try_wait.parity.acquire.cta.shared::cta.b64 P1, [%0], %1, 0x989680;\n\t" \
        "@P1 bra.uni WD_%=;\n\tbra.uni WL_%=;\n\tWD_%=:\n\t}" \
        :: "r"(a), "r"(ph) : "memory"); \
} while (0)
#define TC_ALLOC(sa, n) \
    asm volatile("tcgen05.alloc.cta_group::1.sync.aligned.shared::cta.b32 [%0], %1;" \
                 :: "r"(sa), "r"(n) : "memory")
#define TC_DEALLOC(t, n) \
    asm volatile("tcgen05.dealloc.cta_group::1.sync.aligned.b32 %0, %1;" :: "r"(t), "r"(n))
#define TC_COMMIT(a) \
    asm volatile("tcgen05.commit.cta_group::1.mbarrier::arrive::one.shared::cluster.b64 [%0];" \
                 :: "r"(a) : "memory")
#define TC_FENCE_AFTER() asm volatile("tcgen05.fence::after_thread_sync;" ::: "memory")
#define TC_FENCE_BEFORE() asm volatile("tcgen05.fence::before_thread_sync;" ::: "memory")
#define TC_WAIT_LD() asm volatile("tcgen05.wait::ld.sync.aligned;" ::: "memory")
#define FENCE_ASYNC() asm volatile("fence.proxy.async.shared::cta;" ::: "memory")

__device__ __forceinline__ void mma_f16_ss(uint32_t d, uint64_t ad, uint64_t bd,
                                           uint32_t idesc, uint32_t en) {
    asm volatile("{\n\t.reg .pred p;\n\tsetp.ne.u32 p, %4, 0;\n\t"
                 "tcgen05.mma.cta_group::1.kind::f16 [%0], %1, %2, %3, {%5,%5,%5,%5}, p;\n\t}"
                 :: "r"(d), "l"(ad), "l"(bd), "r"(idesc), "r"(en), "r"(0u) : "memory");
}
__device__ __forceinline__ void ldtm32(uint32_t* r, uint32_t ta) {
    asm volatile("tcgen05.ld.sync.aligned.32x32b.x32.b32 "
        "{%0,%1,%2,%3,%4,%5,%6,%7,%8,%9,%10,%11,%12,%13,%14,%15,"
        "%16,%17,%18,%19,%20,%21,%22,%23,%24,%25,%26,%27,%28,%29,%30,%31}, [%32];"
        : "=r"(r[0]),"=r"(r[1]),"=r"(r[2]),"=r"(r[3]),"=r"(r[4]),"=r"(r[5]),"=r"(r[6]),"=r"(r[7]),
          "=r"(r[8]),"=r"(r[9]),"=r"(r[10]),"=r"(r[11]),"=r"(r[12]),"=r"(r[13]),"=r"(r[14]),"=r"(r[15]),
          "=r"(r[16]),"=r"(r[17]),"=r"(r[18]),"=r"(r[19]),"=r"(r[20]),"=r"(r[21]),"=r"(r[22]),"=r"(r[23]),
          "=r"(r[24]),"=r"(r[25]),"=r"(r[26]),"=r"(r[27]),"=r"(r[28]),"=r"(r[29]),"=r"(r[30]),"=r"(r[31])
        : "r"(ta));
}
static constexpr uint64_t DESC_BASE =
    (uint64_t(2) << 61) | (uint64_t(1) << 46) | (uint64_t(64) << 32) | (uint64_t(1) << 16);
__device__ __forceinline__ uint64_t mk_desc(uint32_t addr) {
    return DESC_BASE | ((uint64_t)(addr >> 4) & 0x3FFF);
}
#define IDESC_N(N) ((1u<<4)|(1u<<7)|(1u<<10)|(((N)/8u)<<17)|(8u<<24))
#endif  // HAS_TCGEN05

// ---------------------------------------------------------------------------
// fsplit / wsplit
// ---------------------------------------------------------------------------
__global__ __launch_bounds__(256) void fsplit(const float* __restrict__ in,
                                              __nv_bfloat16* __restrict__ hi,
                                              __nv_bfloat16* __restrict__ lo) {
    int idx = blockIdx.x * 256 + threadIdx.x;
    float4 v = ((const float4*)in)[idx];
    __nv_bfloat16 h0 = __float2bfloat16(v.x), h1 = __float2bfloat16(v.y);
    __nv_bfloat16 h2 = __float2bfloat16(v.z), h3 = __float2bfloat16(v.w);
    __nv_bfloat16 l0 = __float2bfloat16(v.x - __bfloat162float(h0));
    __nv_bfloat16 l1 = __float2bfloat16(v.y - __bfloat162float(h1));
    __nv_bfloat16 l2 = __float2bfloat16(v.z - __bfloat162float(h2));
    __nv_bfloat16 l3 = __float2bfloat16(v.w - __bfloat162float(h3));
    ((__nv_bfloat162*)hi)[idx*2]     = __halves2bfloat162(h0, h1);
    ((__nv_bfloat162*)hi)[idx*2 + 1] = __halves2bfloat162(h2, h3);
    ((__nv_bfloat162*)lo)[idx*2]     = __halves2bfloat162(l0, l1);
    ((__nv_bfloat162*)lo)[idx*2 + 1] = __halves2bfloat162(l2, l3);
}

__global__ __launch_bounds__(256) void wsplit(const float* __restrict__ W,
                                              __nv_bfloat16* __restrict__ Thi,
                                              __nv_bfloat16* __restrict__ Tlo) {
    __shared__ float t[32][33];
    int bx = blockIdx.x * 32, by = blockIdx.y * 32;
    int x = threadIdx.x & 31, y = threadIdx.x >> 5;
#pragma unroll
    for (int j = 0; j < 4; j++)
        t[y + j*8][x] = W[(size_t)(by + y + j*8) * DD + bx + x];
    __syncthreads();
#pragma unroll
    for (int j = 0; j < 4; j++) {
        float v = t[x][y + j*8];
        __nv_bfloat16 h = __float2bfloat16(v);
        __nv_bfloat16 l = __float2bfloat16(v - __bfloat162float(h));
        size_t o = (size_t)(bx + y + j*8) * DD + by + x;
        Thi[o] = h; Tlo[o] = l;
    }
}

// ---------------------------------------------------------------------------
// tcgen05 GEMM (with CUDA-core fallback)
// ---------------------------------------------------------------------------
#define GK 1024
#define GN 1024
#define NCHUNK 16
#define BUF_STRIDE 98304
#define GIDESC ((1u<<4)|(1u<<7)|(1u<<10)|((256u/8)<<17)|((128u/16)<<24))

__global__ __launch_bounds__(256, 1) void gemm_t(
        const __nv_bfloat16* __restrict__ Ahi, const __nv_bfloat16* __restrict__ Alo,
        const __nv_bfloat16* __restrict__ Bhi, const __nv_bfloat16* __restrict__ Blo,
        float* __restrict__ C) {
    extern __shared__ char sm[];
#if HAS_TCGEN05
    uint32_t sbase = smem_u32(sm);
    int tid = threadIdx.x;
    int wid = tid >> 5, lid = tid & 31;
    int bn = blockIdx.x * 256, bm = blockIdx.y * 128;

    if (tid == 0) { MBAR_INIT(sbase + 8, 1); MBAR_INIT(sbase + 16, 1); }
    if (wid == 0) TC_ALLOC(sbase, 256);
    __syncthreads();
    uint32_t tmem;
    asm volatile("ld.shared.b32 %0, [%1];" : "=r"(tmem) : "r"(sbase));

    auto load_chunk = [&](int chunk, int buf) {
        uint32_t boff = 1024u + (uint32_t)buf * BUF_STRIDE;
        int k0 = chunk * 64;
#pragma unroll
        for (int t = 0; t < 4; t++) {
            int i = tid + t * 256;
            int r = i >> 3, c8 = i & 7;
            uint32_t so = swz((uint32_t)(r * 128 + c8 * 16));
            *(uint4*)(sm + boff + so) =
                *(const uint4*)(Ahi + (size_t)(bm + r) * GK + k0 + c8 * 8);
            *(uint4*)(sm + boff + 16384 + so) =
                *(const uint4*)(Alo + (size_t)(bm + r) * GK + k0 + c8 * 8);
        }
#pragma unroll
        for (int t = 0; t < 8; t++) {
            int i = tid + t * 256;
            int r = i >> 3, c8 = i & 7;
            uint32_t so = swz((uint32_t)(r * 128 + c8 * 16));
            *(uint4*)(sm + boff + 32768 + so) =
                *(const uint4*)(Bhi + (size_t)(bn + r) * GK + k0 + c8 * 8);
            *(uint4*)(sm + boff + 65536 + so) =
                *(const uint4*)(Blo + (size_t)(bn + r) * GK + k0 + c8 * 8);
        }
    };

    load_chunk(0, 0);
    FENCE_ASYNC();
    __syncthreads();

    int ph0 = 0, ph1 = 0;
    for (int k = 0; k < NCHUNK; k++) {
        int b = k & 1;
        if (wid == 0) {
            if (elect_one()) {
                uint32_t boff = sbase + 1024u + (uint32_t)b * BUF_STRIDE;
                uint64_t dah = mk_desc(boff);
                uint64_t dal = mk_desc(boff + 16384);
                uint64_t dbh = mk_desc(boff + 32768);
                uint64_t dbl = mk_desc(boff + 65536);
#pragma unroll
                for (int ks = 0; ks < 4; ks++) {
                    mma_f16_ss(tmem, dah + ks*2, dbh + ks*2, GIDESC,
                               (k == 0 && ks == 0) ? 0u : 1u);
                    mma_f16_ss(tmem, dah + ks*2, dbl + ks*2, GIDESC, 1u);
                    mma_f16_ss(tmem, dal + ks*2, dbh + ks*2, GIDESC, 1u);
                }
                TC_COMMIT(sbase + 8 + (uint32_t)b * 8);
            }
        }
        if (k + 1 < NCHUNK) {
            int nb = (k + 1) & 1;
            if (k >= 1) {
                uint32_t mb = sbase + 8 + (uint32_t)nb * 8;
                if (nb == 0) { MBAR_WAIT(mb, ph0); ph0 ^= 1; }
                else         { MBAR_WAIT(mb, ph1); ph1 ^= 1; }
            }
            load_chunk(k + 1, nb);
            FENCE_ASYNC();
            __syncthreads();
        }
    }
    MBAR_WAIT(sbase + 16, ph1);
    TC_FENCE_AFTER();

    if (wid < 4) {
        int row = bm + wid * 32 + lid;
        float* crow = C + (size_t)row * GN + bn;
#pragma unroll
        for (int cb = 0; cb < 8; cb++) {
            uint32_t r[32];
            ldtm32(r, tmem + cb * 32);
            TC_WAIT_LD();
#pragma unroll
            for (int j = 0; j < 8; j++) {
                float4 v = make_float4(__uint_as_float(r[j*4]), __uint_as_float(r[j*4+1]),
                                       __uint_as_float(r[j*4+2]), __uint_as_float(r[j*4+3]));
                *(float4*)(crow + cb * 32 + j * 4) = v;
            }
        }
        TC_FENCE_BEFORE();
    }
    __syncthreads();
    if (wid == 0) TC_DEALLOC(tmem, 256);
#else
    int tid = threadIdx.x;
    int tx = tid & 15, ty = tid >> 4;
    int bn = blockIdx.x * 256, bm = blockIdx.y * 128;
    float* sA = (float*)sm;
    float* sB = (float*)(sm + 8192);
    for (int half = 0; half < 2; half++) {
        int bn2 = bn + half * 128;
        float acc[8][8];
#pragma unroll
        for (int i = 0; i < 8; i++)
#pragma unroll
            for (int j = 0; j < 8; j++) acc[i][j] = 0.f;
        for (int k0 = 0; k0 < GK; k0 += 16) {
            for (int i = tid; i < 2048; i += 256) {
                int r = i >> 4, kk = i & 15;
                sA[kk*128 + r] = __bfloat162float(Ahi[(size_t)(bm + r)*GK + k0 + kk]) +
                                 __bfloat162float(Alo[(size_t)(bm + r)*GK + k0 + kk]);
                sB[kk*128 + r] = __bfloat162float(Bhi[(size_t)(bn2 + r)*GK + k0 + kk]) +
                                 __bfloat162float(Blo[(size_t)(bn2 + r)*GK + k0 + kk]);
            }
            __syncthreads();
#pragma unroll
            for (int kk = 0; kk < 16; kk++) {
                float a[8], b[8];
#pragma unroll
                for (int i = 0; i < 4; i++) {
                    a[i] = sA[kk*128 + ty*4 + i];
                    a[i+4] = sA[kk*128 + 64 + ty*4 + i];
                    b[i] = sB[kk*128 + tx*4 + i];
                    b[i+4] = sB[kk*128 + 64 + tx*4 + i];
                }
#pragma unroll
                for (int i = 0; i < 8; i++)
#pragma unroll
                    for (int j = 0; j < 8; j++) acc[i][j] += a[i] * b[j];
            }
            __syncthreads();
        }
#pragma unroll
        for (int i = 0; i < 8; i++) {
            int row = bm + ((i < 4) ? (ty*4 + i) : (64 + ty*4 + i - 4));
#pragma unroll
            for (int j = 0; j < 8; j++) {
                int col = bn2 + ((j < 4) ? (tx*4 + j) : (64 + tx*4 + j - 4));
                C[(size_t)row * GN + col] = acc[i][j];
            }
        }
        __syncthreads();
    }
#endif
}

// ---------------------------------------------------------------------------
// dt = softplus(hs @ Wdt)
// ---------------------------------------------------------------------------
__global__ __launch_bounds__(256) void dt2(const float* __restrict__ hs,
                                           const float* __restrict__ Wdt) {
    extern __shared__ float sw[];
    int tid = threadIdx.x;
    for (int i = tid; i < 16384; i += 256)
        sw[(i & 15) * 1028 + (i >> 4)] = Wdt[i];
    __syncthreads();
    int w = tid >> 5, l = tid & 31;
    int row0 = blockIdx.x * 32 + w * 4;
    float acc[4][16];
#pragma unroll
    for (int r = 0; r < 4; r++)
#pragma unroll
        for (int n = 0; n < 16; n++) acc[r][n] = 0.f;
#pragma unroll
    for (int it = 0; it < 8; it++) {
        int k0 = it * 128 + l * 4;
        float4 h[4];
#pragma unroll
        for (int r = 0; r < 4; r++)
            h[r] = *(const float4*)&hs[(size_t)(row0 + r) * DD + k0];
#pragma unroll
        for (int n = 0; n < 16; n++) {
            float4 wv = *(const float4*)&sw[n * 1028 + k0];
#pragma unroll
            for (int r = 0; r < 4; r++)
                acc[r][n] += h[r].x*wv.x + h[r].y*wv.y + h[r].z*wv.z + h[r].w*wv.w;
        }
    }
#pragma unroll
    for (int off = 16; off; off >>= 1)
#pragma unroll
        for (int r = 0; r < 4; r++)
#pragma unroll
            for (int n = 0; n < 16; n++)
                acc[r][n] += __shfl_xor_sync(0xFFFFFFFFu, acc[r][n], off);
    if (l == 0) {
#pragma unroll
        for (int r = 0; r < 4; r++)
#pragma unroll
            for (int n = 0; n < 16; n++) {
                float s = acc[r][n];
                g_dt[(row0 + r) * HH + n] = fmaxf(s, 0.f) + log1pf(expf(-fabsf(s)));
            }
    }
}

// ---------------------------------------------------------------------------
// Per-chunk inclusive cumsum of dA
// ---------------------------------------------------------------------------
__global__ __launch_bounds__(256) void acum_kernel(const float* __restrict__ A) {
    __shared__ float s[256];
    int bid = blockIdx.x;
    int h = bid & 15, c = (bid >> 4) & 31, b = bid >> 9;
    int l = threadIdx.x;
    int row = b * LL + c * CLc + l;
    s[l] = g_dt[row * HH + h] * A[h];
    __syncthreads();
    for (int off = 1; off < 256; off <<= 1) {
        float u = (l >= off) ? s[l - off] : 0.f;
        __syncthreads();
        s[l] += u;
        __syncthreads();
    }
    g_ac[row * HH + h] = s[l];
    if (l == 255) g_cdec[bid] = expf(s[255]);
}

// ---------------------------------------------------------------------------
// Chunk states (rope + x*dt fused into the fill)
// ---------------------------------------------------------------------------
__global__ __launch_bounds__(256) void kb_kernel(const float* __restrict__ cosp,
                                                 const float* __restrict__ sinp) {
    __shared__ float sX[4096];
    __shared__ float sB[4096];
    int bid = blockIdx.x;
    int h = bid & 15, c = (bid >> 4) & 31, b = bid >> 9;
    int tid = threadIdx.x, tx = tid & 15, ty = tid >> 4;
    int chunk_row = b * LL + c * CLc;
    float aclast = g_ac[(chunk_row + 255) * HH + h];

    float acc[4][4];
#pragma unroll
    for (int i = 0; i < 4; i++)
#pragma unroll
        for (int j = 0; j < 4; j++) acc[i][j] = 0.f;

    for (int ltile = 0; ltile < 4; ltile++) {
        int r0 = chunk_row + ltile * 64;
#pragma unroll
        for (int t = 0; t < 8; t++) {
            int pr = tid + t * 256;
            int rr = pr >> 5, pp = pr & 31;
            int row = r0 + rr;
            const float* bb = g_b + (size_t)row * DD + h * 64;
            const float* xx = g_x + (size_t)row * DD + h * 64;
            float a = bb[pp], q = bb[pp + 32];
            float c1 = cosp[row*64 + pp],      s1 = sinp[row*64 + pp];
            float c2 = cosp[row*64 + pp + 32], s2 = sinp[row*64 + pp + 32];
            float w = __expf(aclast - g_ac[row * HH + h]);
            float dtv = g_dt[row * HH + h];
            sB[rr*64 + pp]      = (a * c1 - q * s1) * w;
            sB[rr*64 + pp + 32] = (q * c2 + a * s2) * w;
            sX[rr*64 + pp]      = xx[pp] * dtv;
            sX[rr*64 + pp + 32] = xx[pp + 32] * dtv;
        }
        __syncthreads();
#pragma unroll 4
        for (int l = 0; l < 64; l++) {
            float xv[4], bv[4];
#pragma unroll
            for (int i = 0; i < 4; i++) xv[i] = sX[l * 64 + ty * 4 + i];
#pragma unroll
            for (int j = 0; j < 4; j++) bv[j] = sB[l * 64 + tx * 4 + j];
#pragma unroll
            for (int i = 0; i < 4; i++)
#pragma unroll
                for (int j = 0; j < 4; j++) acc[i][j] += xv[i] * bv[j];
        }
        __syncthreads();
    }
    int sb = ((b * NCC + c) * HH + h) * 4096;
#pragma unroll
    for (int i = 0; i < 4; i++) {
        float4 v = make_float4(acc[i][0], acc[i][1], acc[i][2], acc[i][3]);
        *(float4*)&g_states[sb + (ty * 4 + i) * 64 + tx * 4] = v;
    }
}

// ---------------------------------------------------------------------------
// Sequential chunk scan
// ---------------------------------------------------------------------------
__global__ __launch_bounds__(256) void kc_kernel(float* __restrict__ fs) {
    int bid = blockIdx.x;
    int h = bid & 15, b = bid >> 4;
    int tid = threadIdx.x;
    float st[16];
#pragma unroll
    for (int k = 0; k < 16; k++) st[k] = 0.f;
    for (int c = 0; c < NCC; c++) {
        float dec = g_cdec[(b * NCC + c) * HH + h];
        int base = ((b * NCC + c) * HH + h) * 4096;
#pragma unroll
        for (int k = 0; k < 16; k++) {
            int e = k * 256 + tid;
            g_prev[base + e] = st[k];
            st[k] = st[k] * dec + g_states[base + e];
        }
    }
    int fb = (b * HH + h) * 4096;
#pragma unroll
    for (int k = 0; k < 16; k++) fs[fb + k * 256 + tid] = st[k];
}

// ---------------------------------------------------------------------------
// Flash kernel: Y_diag + Y_off on tensor cores; 8-warp epilogues, __expf.
// ---------------------------------------------------------------------------
#define FL_SMEM 182272
#define FO_AC   64
#define FO_CHI  2048
#define FO_CLO  18432
#define FO_BHI  34816
#define FO_BLO  67584
#define FO_XHI  100352
#define FO_XLO  133120
#define FO_PHI  165888
#define FO_PLO  174080

__global__ __launch_bounds__(256, 1) void flash_k(const float* __restrict__ cosp,
                                                  const float* __restrict__ sinp,
                                                  __nv_bfloat16* __restrict__ yhi,
                                                  __nv_bfloat16* __restrict__ ylo) {
    extern __shared__ char sm[];
    int tid = threadIdx.x, wid = tid >> 5, lid = tid & 31;
    int bid = blockIdx.x;
    int half = bid & 1, h = (bid >> 1) & 15, c = (bid >> 5) & 31, b = bid >> 10;
    int chunk_row = b * LL + c * CLc;
    int l0g = half * 128;
    int SL = half ? 256 : 128;
    float* acs = (float*)(sm + FO_AC);

#if HAS_TCGEN05
    uint32_t sbase = smem_u32(sm);
    int nsl = SL / 128;
    if (tid == 0) {
        MBAR_INIT(sbase + 8, 1);  MBAR_INIT(sbase + 16, 1);
        MBAR_INIT(sbase + 24, 1); MBAR_INIT(sbase + 32, 1);
    }
    if (wid == 0) TC_ALLOC(sbase, 512);
    __syncthreads();
    uint32_t tmem;
    asm volatile("ld.shared.b32 %0, [%1];" : "=r"(tmem) : "r"(sbase));

    acs[tid] = g_ac[(chunk_row + tid) * HH + h];

    // C tile (rope) 128x64 hi/lo
    for (int t = 0; t < 16; t++) {
        int pr = tid + t * 256;
        int rr = pr >> 5, pp = pr & 31;
        int row = chunk_row + l0g + rr;
        const float* cb = g_c + (size_t)row * DD + h * 64;
        float a = cb[pp], q = cb[pp + 32];
        float c1 = cosp[row*64 + pp],      s1 = sinp[row*64 + pp];
        float c2 = cosp[row*64 + pp + 32], s2 = sinp[row*64 + pp + 32];
        float v1 = a * c1 - q * s1;
        float v2 = q * c2 + a * s2;
        st_split_bf16(sm + FO_CHI, sm + FO_CLO, swz(rr*128 + pp*2), v1);
        st_split_bf16(sm + FO_CHI, sm + FO_CLO, swz(rr*128 + (pp+32)*2), v2);
    }
    // B tile (rope) SLx64 hi/lo
    for (int t = 0; t < SL/8; t++) {
        int pr = tid + t * 256;
        int rr = pr >> 5, pp = pr & 31;
        int row = chunk_row + rr;
        const float* bb = g_b + (size_t)row * DD + h * 64;
        float a = bb[pp], q = bb[pp + 32];
        float c1 = cosp[row*64 + pp],      s1 = sinp[row*64 + pp];
        float c2 = cosp[row*64 + pp + 32], s2 = sinp[row*64 + pp + 32];
        float v1 = a * c1 - q * s1;
        float v2 = q * c2 + a * s2;
        st_split_bf16(sm + FO_BHI, sm + FO_BLO, swz(rr*128 + pp*2), v1);
        st_split_bf16(sm + FO_BHI, sm + FO_BLO, swz(rr*128 + (pp+32)*2), v2);
    }
    // X^T tile: [64 p][SL s] blocked atoms, x*dt fused
    for (int t = 0; t < SL/8; t++) {
        int idx = tid + t * 256;
        int p = idx & 63, sp = idx >> 6;
        int s = sp * 2;
        int row1 = chunk_row + s, row2 = row1 + 1;
        float x1 = g_x[(size_t)row1 * DD + h*64 + p] * g_dt[row1*HH + h];
        float x2 = g_x[(size_t)row2 * DD + h*64 + p] * g_dt[row2*HH + h];
        float h1, lo1, h2, lo2;
        split2(x1, h1, lo1); split2(x2, h2, lo2);
        uint32_t off = swz((uint32_t)(((p>>3) + (s>>6)*8)*1024 + (p&7)*128 + (s&63)*2));
        *(uint32_t*)(sm + FO_XHI + off) = pack_bf2(h1, h2);
        *(uint32_t*)(sm + FO_XLO + off) = pack_bf2(lo1, lo2);
    }
    // prev tile [64 p][64 n]
    {
        int pbase = ((b * NCC + c) * HH + h) * 4096;
        for (int t = 0; t < 16; t++) {
            int idx = tid + t * 256;
            int p = idx >> 6, n = idx & 63;
            float v = g_prev[pbase + idx];
            st_split_bf16(sm + FO_PHI, sm + FO_PLO, swz(p*128 + n*2), v);
        }
    }
    FENCE_ASYNC();
    __syncthreads();

    // MMA1: S = C * B^T, plus off-term Y2 = C * prev^T
    if (wid == 0 && elect_one()) {
        uint64_t dCh = mk_desc(sbase + FO_CHI), dCl = mk_desc(sbase + FO_CLO);
        uint64_t dBh = mk_desc(sbase + FO_BHI), dBl = mk_desc(sbase + FO_BLO);
        uint32_t id1 = (SL == 128) ? IDESC_N(128) : IDESC_N(256);
#pragma unroll
        for (int ks = 0; ks < 4; ks++) {
            mma_f16_ss(tmem, dCh + ks*2, dBh + ks*2, id1, ks > 0);
            mma_f16_ss(tmem, dCh + ks*2, dBl + ks*2, id1, 1);
            mma_f16_ss(tmem, dCl + ks*2, dBh + ks*2, id1, 1);
        }
        TC_COMMIT(sbase + 8);
        uint64_t dPh = mk_desc(sbase + FO_PHI), dPl = mk_desc(sbase + FO_PLO);
        uint32_t id64 = IDESC_N(64);
#pragma unroll
        for (int ks = 0; ks < 4; ks++) {
            mma_f16_ss(tmem + 320, dCh + ks*2, dPh + ks*2, id64, ks > 0);
            mma_f16_ss(tmem + 320, dCh + ks*2, dPl + ks*2, id64, 1);
            mma_f16_ss(tmem + 320, dCl + ks*2, dPh + ks*2, id64, 1);
        }
        TC_COMMIT(sbase + 16);
    }
    MBAR_WAIT(sbase + 8, 0);
    TC_FENCE_AFTER();

    int sub = wid & 3, grp = wid >> 2;
    int lrow = sub * 32 + lid;
    float acl = acs[l0g + lrow];

    for (int sl = 0; sl < nsl; sl++) {
        if (sl == 1) MBAR_WAIT(sbase + 24, 0);
        // S epilogue: 8 warps — grp g handles column blocks rd = g, g+2
#pragma unroll
        for (int rd = grp; rd < 4; rd += 2) {
            uint32_t r[32];
            ldtm32(r, tmem + sl*128 + rd*32);
            TC_WAIT_LD();
            int colbase = sl*128 + rd*32;
#pragma unroll
            for (int j = 0; j < 32; j += 2) {
                int cg0 = colbase + j, cg1 = cg0 + 1;
                float v0 = __uint_as_float(r[j]);
                float v1 = __uint_as_float(r[j+1]);
                v0 = (cg0 <= l0g + lrow) ? v0 * __expf(acl - acs[cg0]) : 0.f;
                v1 = (cg1 <= l0g + lrow) ? v1 * __expf(acl - acs[cg1]) : 0.f;
                float h0, lo0, h1, lo1;
                split2(v0, h0, lo0); split2(v1, h1, lo1);
                int sIn = rd*32 + j;
                uint32_t off = swz((uint32_t)(((lrow>>3) + (sIn>>6)*16)*1024
                                              + (lrow&7)*128 + (sIn&63)*2));
                *(uint32_t*)(sm + FO_BHI + off) = pack_bf2(h0, h1);
                *(uint32_t*)(sm + FO_BLO + off) = pack_bf2(lo0, lo1);
            }
        }
        FENCE_ASYNC();
        __syncthreads();
        if (wid == 0 && elect_one()) {
            uint64_t dSh = mk_desc(sbase + FO_BHI), dSl = mk_desc(sbase + FO_BLO);
            uint64_t dXh = mk_desc(sbase + FO_XHI), dXl = mk_desc(sbase + FO_XLO);
            uint32_t id64 = IDESC_N(64);
#pragma unroll
            for (int ks2 = 0; ks2 < 8; ks2++) {
                int ksg = sl*8 + ks2;
                uint64_t ao = (uint64_t)((ks2 >> 2)*1024 + (ks2 & 3)*2);
                uint64_t bo = (uint64_t)((ksg >> 2)*512 + (ksg & 3)*2);
                mma_f16_ss(tmem + 256, dSh + ao, dXh + bo, id64,
                           !(sl == 0 && ks2 == 0));
                mma_f16_ss(tmem + 256, dSh + ao, dXl + bo, id64, 1);
                mma_f16_ss(tmem + 256, dSl + ao, dXh + bo, id64, 1);
            }
            TC_COMMIT(sbase + 24 + (uint32_t)sl * 8);
        }
    }
    MBAR_WAIT(sbase + 24 + (uint32_t)(nsl - 1) * 8, 0);
    MBAR_WAIT(sbase + 16, 0);
    TC_FENCE_AFTER();

    // Final epilogue: 8 warps — grp handles 32-column half hb = grp
    {
        int row = chunk_row + l0g + lrow;
        float e = __expf(acl);
        uint32_t* dsthi = (uint32_t*)(yhi + (size_t)row * DD + h * 64);
        uint32_t* dstlo = (uint32_t*)(ylo + (size_t)row * DD + h * 64);
        uint32_t y1[32], y2[32];
        ldtm32(y1, tmem + 256 + grp*32); TC_WAIT_LD();
        ldtm32(y2, tmem + 320 + grp*32); TC_WAIT_LD();
#pragma unroll
        for (int j = 0; j < 32; j += 2) {
            float v0 = __uint_as_float(y1[j])   + e * __uint_as_float(y2[j]);
            float v1 = __uint_as_float(y1[j+1]) + e * __uint_as_float(y2[j+1]);
            float h0, lo0, h1, lo1;
            split2(v0, h0, lo0); split2(v1, h1, lo1);
            dsthi[grp*16 + j/2] = pack_bf2(h0, h1);
            dstlo[grp*16 + j/2] = pack_bf2(lo0, lo1);
        }
        TC_FENCE_BEFORE();
    }
    __syncthreads();
    if (wid == 0) TC_DEALLOC(tmem, 512);
#else
    // CUDA-core fallback (non-'a' pass only)
    float* sC = (float*)(sm + 2048);
    float* sS = (float*)(sm + 34816);
    float* sB = (float*)(sm + 67584);
    float* sX = (float*)(sm + 83968);
    float* sP = (float*)(sm + 100352);
    int tx = tid & 15, ty = tid >> 4;

    acs[tid] = g_ac[(chunk_row + tid) * HH + h];
    for (int t = 0; t < 16; t++) {
        int pr = tid + t * 256;
        int rr = pr >> 5, pp = pr & 31;
        int row = chunk_row + l0g + rr;
        const float* cb = g_c + (size_t)row * DD + h * 64;
        float a = cb[pp], q = cb[pp + 32];
        float c1 = cosp[row*64 + pp],      s1 = sinp[row*64 + pp];
        float c2 = cosp[row*64 + pp + 32], s2 = sinp[row*64 + pp + 32];
        sC[rr*64 + pp]      = a * c1 - q * s1;
        sC[rr*64 + pp + 32] = q * c2 + a * s2;
    }
    {
        int pbase = ((b * NCC + c) * HH + h) * 4096;
        for (int t = 0; t < 16; t++) {
            int idx = tid + t * 256;
            sP[idx] = g_prev[pbase + idx];
        }
    }
    __syncthreads();

    float accD[8][4], accO[8][4];
#pragma unroll
    for (int i = 0; i < 8; i++)
#pragma unroll
        for (int j = 0; j < 4; j++) { accD[i][j] = 0.f; accO[i][j] = 0.f; }
    for (int n = 0; n < 64; n++)
#pragma unroll
        for (int i = 0; i < 8; i++)
#pragma unroll
            for (int j = 0; j < 4; j++)
                accO[i][j] += sC[(ty*8+i)*64 + n] * sP[(tx*4+j)*64 + n];

    for (int stile = 0; stile < SL/64; stile++) {
        for (int t = 0; t < 8; t++) {
            int pr = tid + t * 256;
            int rr = pr >> 5, pp = pr & 31;
            int row = chunk_row + stile*64 + rr;
            const float* bb = g_b + (size_t)row * DD + h * 64;
            const float* xx = g_x + (size_t)row * DD + h * 64;
            float a = bb[pp], q = bb[pp + 32];
            float c1 = cosp[row*64 + pp],      s1 = sinp[row*64 + pp];
            float c2 = cosp[row*64 + pp + 32], s2 = sinp[row*64 + pp + 32];
            float dtv = g_dt[row * HH + h];
            sB[rr*64 + pp]      = a * c1 - q * s1;
            sB[rr*64 + pp + 32] = q * c2 + a * s2;
            sX[rr*64 + pp]      = xx[pp] * dtv;
            sX[rr*64 + pp + 32] = xx[pp + 32] * dtv;
        }
        __syncthreads();
        for (int t = 0; t < 32; t++) {
            int idx = tid + t * 256;
            int l = idx >> 6, sIn = idx & 63;
            int sg = stile*64 + sIn;
            float v = 0.f;
            if (sg <= l0g + l) {
                for (int n = 0; n < 64; n++)
                    v += sC[l*64 + n] * sB[sIn*64 + n];
                v *= expf(acs[l0g + l] - acs[sg]);
            }
            sS[idx] = v;
        }
        __syncthreads();
        for (int s = 0; s < 64; s++)
#pragma unroll
            for (int i = 0; i < 8; i++)
#pragma unroll
                for (int j = 0; j < 4; j++)
                    accD[i][j] += sS[(ty*8+i)*64 + s] * sX[s*64 + tx*4 + j];
        __syncthreads();
    }
#pragma unroll
    for (int i = 0; i < 8; i++) {
        int lr = ty*8 + i;
        int row = chunk_row + l0g + lr;
        float e = expf(acs[l0g + lr]);
#pragma unroll
        for (int j = 0; j < 4; j++) {
            float v = accD[i][j] + e * accO[i][j];
            __nv_bfloat16 hb = __float2bfloat16(v);
            __nv_bfloat16 lb = __float2bfloat16(v - __bfloat162float(hb));
            yhi[(size_t)row * DD + h*64 + tx*4 + j] = hb;
            ylo[(size_t)row * DD + h*64 + tx*4 + j] = lb;
        }
    }
#endif
}

// ---------------------------------------------------------------------------
// kernel_launch
// ---------------------------------------------------------------------------
extern "C" void kernel_launch(void* const* d_in, const int* in_sizes, int n_in,
                              void* d_out, int out_size) {
    (void)in_sizes; (void)n_in; (void)out_size;
    const float* hs   = (const float*)d_in[0];
    const float* cosp = (const float*)d_in[1];
    const float* sinp = (const float*)d_in[2];
    const float* Wc   = (const float*)d_in[3];
    const float* Wb   = (const float*)d_in[4];
    const float* Wdt  = (const float*)d_in[5];
    const float* Wx   = (const float*)d_in[6];
    const float* Wout = (const float*)d_in[7];
    const float* A    = (const float*)d_in[8];
    float* out = (float*)d_out;
    float* fs  = out + (size_t)MM * DD;

    float *pc, *pb, *px;
    __nv_bfloat16 *ahi, *alo, *whi, *wlo;
    cudaGetSymbolAddress((void**)&pc, g_c);
    cudaGetSymbolAddress((void**)&pb, g_b);
    cudaGetSymbolAddress((void**)&px, g_x);
    cudaGetSymbolAddress((void**)&ahi, g_ahi);
    cudaGetSymbolAddress((void**)&alo, g_alo);
    cudaGetSymbolAddress((void**)&whi, g_wt_hi);
    cudaGetSymbolAddress((void**)&wlo, g_wt_lo);

    int gemm_smem = 1024 + 2 * BUF_STRIDE;
    int dt_smem = 16 * 1028 * 4;
    cudaFuncSetAttribute(gemm_t, cudaFuncAttributeMaxDynamicSharedMemorySize, gemm_smem);
    cudaFuncSetAttribute(dt2, cudaFuncAttributeMaxDynamicSharedMemorySize, dt_smem);
    cudaFuncSetAttribute(flash_k, cudaFuncAttributeMaxDynamicSharedMemorySize, FL_SMEM);

    fsplit<<<(MM * DD / 4) / 256, 256>>>(hs, ahi, alo);
    dim3 wg(32, 32);
    wsplit<<<wg, 256>>>(Wc,   whi + 0 * (size_t)DD * DD, wlo + 0 * (size_t)DD * DD);
    wsplit<<<wg, 256>>>(Wb,   whi + 1 * (size_t)DD * DD, wlo + 1 * (size_t)DD * DD);
    wsplit<<<wg, 256>>>(Wx,   whi + 2 * (size_t)DD * DD, wlo + 2 * (size_t)DD * DD);
    wsplit<<<wg, 256>>>(Wout, whi + 3 * (size_t)DD * DD, wlo + 3 * (size_t)DD * DD);

    dim3 gg(GN / 256, MM / 128);
    gemm_t<<<gg, 256, gemm_smem>>>(ahi, alo, whi + 0 * (size_t)DD * DD, wlo + 0 * (size_t)DD * DD, pc);
    gemm_t<<<gg, 256, gemm_smem>>>(ahi, alo, whi + 1 * (size_t)DD * DD, wlo + 1 * (size_t)DD * DD, pb);
    gemm_t<<<gg, 256, gemm_smem>>>(ahi, alo, whi + 2 * (size_t)DD * DD, wlo + 2 * (size_t)DD * DD, px);

    dt2<<<MM / 32, 256, dt_smem>>>(hs, Wdt);
    acum_kernel<<<BB * NCC * HH, 256>>>(A);
    kb_kernel<<<BB * NCC * HH, 256>>>(cosp, sinp);
    kc_kernel<<<BB * HH, 256>>>(fs);

    flash_k<<<BB * NCC * HH * 2, 256, FL_SMEM>>>(cosp, sinp, ahi, alo);

    gemm_t<<<gg, 256, gemm_smem>>>(ahi, alo, whi + 3 * (size_t)DD * DD, wlo + 3 * (size_t)DD * DD, out);
}

// round 7
// speedup vs baseline: 4.4089x; 1.3143x over previous
#include <cuda_runtime.h>
#include <cuda_bf16.h>
#include <math.h>
#include <stdint.h>

// Problem constants (fixed by the dataset)
#define BB  2
#define LL  8192
#define DD  1024
#define HH  16
#define PP  64
#define CLc 256
#define NCC 32
#define MM  (BB*LL)   // 16384 rows

#if defined(__CUDA_ARCH_FEAT_SM103_ALL) || defined(__CUDA_ARCH_FEAT_SM100_ALL) || \
    defined(__CUDA_ARCH_FEAT_SM101_ALL) || defined(__CUDA_ARCH_SPECIFIC__)
#define HAS_TCGEN05 1
#else
#define HAS_TCGEN05 0
#endif

// ---------------------------------------------------------------------------
// Scratch
// ---------------------------------------------------------------------------
__device__ float g_c[BB*LL*DD];
__device__ float g_b[BB*LL*DD];
__device__ float g_x[BB*LL*DD];
__device__ float g_dt[BB*LL*HH];
__device__ float g_ac[BB*LL*HH];
__device__ float g_cdec[BB*NCC*HH];
__device__ float g_states[BB*NCC*HH*PP*PP];
__device__ float g_prev[BB*NCC*HH*PP*PP];

// TILED bf16 operands: A-side tiles 128x64 (16KB, swizzled), index (mb*16+chunk).
// B-side (weights) tiles 256x64 (32KB, swizzled), index (nb*16+chunk).
__device__ __nv_bfloat16 g_ahi[MM*DD];
__device__ __nv_bfloat16 g_alo[MM*DD];
__device__ __nv_bfloat16 g_wt_hi[4][DD*DD];
__device__ __nv_bfloat16 g_wt_lo[4][DD*DD];

// ---------------------------------------------------------------------------
// Helpers
// ---------------------------------------------------------------------------
__device__ __forceinline__ uint32_t smem_u32(const void* p) {
    uint32_t a;
    asm("{ .reg .u64 t; cvta.to.shared.u64 t, %1; cvt.u32.u64 %0, t; }"
        : "=r"(a) : "l"(p));
    return a;
}
__device__ __forceinline__ uint32_t swz(uint32_t off) { return off ^ ((off >> 3) & 0x70); }

__device__ __forceinline__ void split2(float v, float& hi, float& lo) {
    __nv_bfloat16 h = __float2bfloat16(v);
    hi = __bfloat162float(h);
    lo = v - hi;
}
__device__ __forceinline__ uint32_t pack_bf2(float a, float b) {
    __nv_bfloat162 t = __halves2bfloat162(__float2bfloat16(a), __float2bfloat16(b));
    return *(uint32_t*)&t;
}

// tiled-layout addressing
__device__ __forceinline__ uint32_t a_tile_off(int row, int k) {   // 128-row tiles
    uint32_t tile = (uint32_t)(row >> 7) * 16u + (uint32_t)(k >> 6);
    return (tile << 14) + swz(((uint32_t)(row & 127) << 7) + ((uint32_t)(k & 63) << 1));
}
__device__ __forceinline__ uint32_t b_tile_off(int n, int k) {     // 256-row tiles
    uint32_t tile = (uint32_t)(n >> 8) * 16u + (uint32_t)(k >> 6);
    return (tile << 15) + swz(((uint32_t)(n & 255) << 7) + ((uint32_t)(k & 63) << 1));
}

#if HAS_TCGEN05
__device__ __forceinline__ uint32_t elect_one() {
    uint32_t pred;
    asm volatile("{\n\t.reg .pred p;\n\telect.sync _|p, 0xFFFFFFFF;\n\t"
                 "selp.b32 %0, 1, 0, p;\n\t}" : "=r"(pred));
    return pred;
}
#define MBAR_INIT(a, c) \
    asm volatile("mbarrier.init.shared.b64 [%0], %1;" :: "r"(a), "r"(c) : "memory")
#define MBAR_EXPECT_TX(a, n) \
    asm volatile("mbarrier.arrive.expect_tx.shared.b64 _, [%0], %1;" :: "r"(a), "r"(n) : "memory")
#define MBAR_WAIT(a, ph) do { \
    asm volatile("{\n\t.reg .pred P1;\n\t" \
        "WL_%=:\n\t" \
        "mbarrier.try_wait.parity.acquire.cta.shared::cta.b64 P1, [%0], %1, 0x989680;\n\t" \
        "@P1 bra.uni WD_%=;\n\tbra.uni WL_%=;\n\tWD_%=:\n\t}" \
        :: "r"(a), "r"(ph) : "memory"); \
} while (0)
#define BULK_G2S(dst, src, n, mbar) \
    asm volatile("cp.async.bulk.shared::cta.global.mbarrier::complete_tx::bytes " \
                 "[%0], [%1], %2, [%3];" \
                 :: "r"(dst), "l"(src), "r"(n), "r"(mbar) : "memory")
#define TC_ALLOC(sa, n) \
    asm volatile("tcgen05.alloc.cta_group::1.sync.aligned.shared::cta.b32 [%0], %1;" \
                 :: "r"(sa), "r"(n) : "memory")
#define TC_DEALLOC(t, n) \
    asm volatile("tcgen05.dealloc.cta_group::1.sync.aligned.b32 %0, %1;" :: "r"(t), "r"(n))
#define TC_COMMIT(a) \
    asm volatile("tcgen05.commit.cta_group::1.mbarrier::arrive::one.shared::cluster.b64 [%0];" \
                 :: "r"(a) : "memory")
#define TC_FENCE_AFTER() asm volatile("tcgen05.fence::after_thread_sync;" ::: "memory")
#define TC_FENCE_BEFORE() asm volatile("tcgen05.fence::before_thread_sync;" ::: "memory")
#define TC_WAIT_LD() asm volatile("tcgen05.wait::ld.sync.aligned;" ::: "memory")
#define FENCE_ASYNC() asm volatile("fence.proxy.async.shared::cta;" ::: "memory")

__device__ __forceinline__ void mma_f16_ss(uint32_t d, uint64_t ad, uint64_t bd,
                                           uint32_t idesc, uint32_t en) {
    asm volatile("{\n\t.reg .pred p;\n\tsetp.ne.u32 p, %4, 0;\n\t"
                 "tcgen05.mma.cta_group::1.kind::f16 [%0], %1, %2, %3, {%5,%5,%5,%5}, p;\n\t}"
                 :: "r"(d), "l"(ad), "l"(bd), "r"(idesc), "r"(en), "r"(0u) : "memory");
}
__device__ __forceinline__ void ldtm32(uint32_t* r, uint32_t ta) {
    asm volatile("tcgen05.ld.sync.aligned.32x32b.x32.b32 "
        "{%0,%1,%2,%3,%4,%5,%6,%7,%8,%9,%10,%11,%12,%13,%14,%15,"
        "%16,%17,%18,%19,%20,%21,%22,%23,%24,%25,%26,%27,%28,%29,%30,%31}, [%32];"
        : "=r"(r[0]),"=r"(r[1]),"=r"(r[2]),"=r"(r[3]),"=r"(r[4]),"=r"(r[5]),"=r"(r[6]),"=r"(r[7]),
          "=r"(r[8]),"=r"(r[9]),"=r"(r[10]),"=r"(r[11]),"=r"(r[12]),"=r"(r[13]),"=r"(r[14]),"=r"(r[15]),
          "=r"(r[16]),"=r"(r[17]),"=r"(r[18]),"=r"(r[19]),"=r"(r[20]),"=r"(r[21]),"=r"(r[22]),"=r"(r[23]),
          "=r"(r[24]),"=r"(r[25]),"=r"(r[26]),"=r"(r[27]),"=r"(r[28]),"=r"(r[29]),"=r"(r[30]),"=r"(r[31])
        : "r"(ta));
}
static constexpr uint64_t DESC_BASE =
    (uint64_t(2) << 61) | (uint64_t(1) << 46) | (uint64_t(64) << 32) | (uint64_t(1) << 16);
__device__ __forceinline__ uint64_t mk_desc(uint32_t addr) {
    return DESC_BASE | ((uint64_t)(addr >> 4) & 0x3FFF);
}
#define IDESC_N(N) ((1u<<4)|(1u<<7)|(1u<<10)|(((N)/8u)<<17)|(8u<<24))
#endif  // HAS_TCGEN05

// ---------------------------------------------------------------------------
// fsplit: hs fp32 row-major -> TILED bf16 hi/lo. 8 elements/thread.
// ---------------------------------------------------------------------------
__global__ __launch_bounds__(256) void fsplit(const float* __restrict__ in,
                                              char* __restrict__ hi,
                                              char* __restrict__ lo) {
    int t = blockIdx.x * 256 + threadIdx.x;
    int row = t >> 7;
    int k8 = t & 127;                      // k/8
    const float4* p = (const float4*)(in + ((size_t)row << 10) + (k8 << 3));
    float4 v0 = p[0], v1 = p[1];
    float h[8], l[8];
    split2(v0.x, h[0], l[0]); split2(v0.y, h[1], l[1]);
    split2(v0.z, h[2], l[2]); split2(v0.w, h[3], l[3]);
    split2(v1.x, h[4], l[4]); split2(v1.y, h[5], l[5]);
    split2(v1.z, h[6], l[6]); split2(v1.w, h[7], l[7]);
    uint32_t tile = (uint32_t)(row >> 7) * 16u + (uint32_t)(k8 >> 3);
    uint32_t off = (tile << 14) + swz(((uint32_t)(row & 127) << 7) + ((uint32_t)(k8 & 7) << 4));
    *(uint4*)(hi + off) = make_uint4(pack_bf2(h[0],h[1]), pack_bf2(h[2],h[3]),
                                     pack_bf2(h[4],h[5]), pack_bf2(h[6],h[7]));
    *(uint4*)(lo + off) = make_uint4(pack_bf2(l[0],l[1]), pack_bf2(l[2],l[3]),
                                     pack_bf2(l[4],l[5]), pack_bf2(l[6],l[7]));
}

// ---------------------------------------------------------------------------
// wsplit: W[K][N] fp32 -> transposed TILED bf16 hi/lo (256-row tiles)
// ---------------------------------------------------------------------------
__global__ __launch_bounds__(256) void wsplit(const float* __restrict__ W,
                                              char* __restrict__ Thi,
                                              char* __restrict__ Tlo) {
    __shared__ float t[32][33];
    int bx = blockIdx.x * 32, by = blockIdx.y * 32;
    int x = threadIdx.x & 31, y = threadIdx.x >> 5;
#pragma unroll
    for (int j = 0; j < 4; j++)
        t[y + j*8][x] = W[(size_t)(by + y + j*8) * DD + bx + x];
    __syncthreads();
#pragma unroll
    for (int j = 0; j < 4; j++) {
        float v = t[x][y + j*8];
        float h, l;
        split2(v, h, l);
        int n = bx + y + j*8, k = by + x;
        uint32_t off = b_tile_off(n, k);
        *(__nv_bfloat16*)(Thi + off) = __float2bfloat16(h);
        *(__nv_bfloat16*)(Tlo + off) = __float2bfloat16(l);
    }
}

// ---------------------------------------------------------------------------
// tcgen05 GEMM with bulk-copy loads. grid=(4, 128), 256 threads.
// ---------------------------------------------------------------------------
#define GK 1024
#define GN 1024
#define NCHUNK 16
#define BUF_STRIDE 98304
#define GIDESC ((1u<<4)|(1u<<7)|(1u<<10)|((256u/8)<<17)|((128u/16)<<24))

__global__ __launch_bounds__(256, 1) void gemm_t(
        const char* __restrict__ Ahi, const char* __restrict__ Alo,
        const char* __restrict__ Bhi, const char* __restrict__ Blo,
        float* __restrict__ C) {
    extern __shared__ char sm[];
#if HAS_TCGEN05
    uint32_t sbase = smem_u32(sm);
    int tid = threadIdx.x;
    int wid = tid >> 5, lid = tid & 31;
    int bn = blockIdx.x, bm = blockIdx.y;

    // layout: [0] tmem ptr, [8] full0, [16] full1, [24] empty0, [32] empty1
    if (tid == 0) {
        MBAR_INIT(sbase + 8, 1);  MBAR_INIT(sbase + 16, 1);
        MBAR_INIT(sbase + 24, 1); MBAR_INIT(sbase + 32, 1);
    }
    if (wid == 0) TC_ALLOC(sbase, 256);
    __syncthreads();
    uint32_t tmem;
    asm volatile("ld.shared.b32 %0, [%1];" : "=r"(tmem) : "r"(sbase));

    if (wid == 0 && elect_one()) {
        auto load = [&](int chunk, int b) {
            uint32_t mb = sbase + 8 + (uint32_t)b * 8;
            MBAR_EXPECT_TX(mb, 98304u);
            uint32_t d = sbase + 1024u + (uint32_t)b * BUF_STRIDE;
            size_t ao = ((size_t)bm * 16 + chunk) << 14;
            size_t bo = ((size_t)bn * 16 + chunk) << 15;
            BULK_G2S(d,          Ahi + ao, 16384u, mb);
            BULK_G2S(d + 16384,  Alo + ao, 16384u, mb);
            BULK_G2S(d + 32768,  Bhi + bo, 32768u, mb);
            BULK_G2S(d + 65536,  Blo + bo, 32768u, mb);
        };
        load(0, 0);
        load(1, 1);
        int f0 = 0, f1 = 0, e0 = 0, e1 = 0;
        for (int k = 0; k < NCHUNK; k++) {
            int b = k & 1;
            if (b == 0) { MBAR_WAIT(sbase + 8, f0);  f0 ^= 1; }
            else        { MBAR_WAIT(sbase + 16, f1); f1 ^= 1; }
            uint32_t boff = sbase + 1024u + (uint32_t)b * BUF_STRIDE;
            uint64_t dah = mk_desc(boff);
            uint64_t dal = mk_desc(boff + 16384);
            uint64_t dbh = mk_desc(boff + 32768);
            uint64_t dbl = mk_desc(boff + 65536);
#pragma unroll
            for (int ks = 0; ks < 4; ks++) {
                mma_f16_ss(tmem, dah + ks*2, dbh + ks*2, GIDESC,
                           (k == 0 && ks == 0) ? 0u : 1u);
                mma_f16_ss(tmem, dah + ks*2, dbl + ks*2, GIDESC, 1u);
                mma_f16_ss(tmem, dal + ks*2, dbh + ks*2, GIDESC, 1u);
            }
            TC_COMMIT(sbase + 24 + (uint32_t)b * 8);
            if (k + 2 < NCHUNK) {
                if (b == 0) { MBAR_WAIT(sbase + 24, e0); e0 ^= 1; }
                else        { MBAR_WAIT(sbase + 32, e1); e1 ^= 1; }
                load(k + 2, b);
            }
        }
        MBAR_WAIT(sbase + 24, e0);
        MBAR_WAIT(sbase + 32, e1);
    }
    __syncthreads();
    TC_FENCE_AFTER();

    if (wid < 4) {
        int row = bm * 128 + wid * 32 + lid;
        float* crow = C + (size_t)row * GN + bn * 256;
#pragma unroll
        for (int cb = 0; cb < 8; cb++) {
            uint32_t r[32];
            ldtm32(r, tmem + cb * 32);
            TC_WAIT_LD();
#pragma unroll
            for (int j = 0; j < 8; j++) {
                float4 v = make_float4(__uint_as_float(r[j*4]), __uint_as_float(r[j*4+1]),
                                       __uint_as_float(r[j*4+2]), __uint_as_float(r[j*4+3]));
                *(float4*)(crow + cb * 32 + j * 4) = v;
            }
        }
        TC_FENCE_BEFORE();
    }
    __syncthreads();
    if (wid == 0) TC_DEALLOC(tmem, 256);
#else
    // CUDA-core fallback (non-'a' pass only) — reads TILED bf16 operands.
    int tid = threadIdx.x;
    int tx = tid & 15, ty = tid >> 4;
    int bn = blockIdx.x * 256, bm = blockIdx.y * 128;
    float* sA = (float*)sm;
    float* sB = (float*)(sm + 8192);
    auto rdA = [&](const char* p, int row, int k) {
        uint32_t off = a_tile_off(row, k);
        return __bfloat162float(*(const __nv_bfloat16*)(p + off));
    };
    auto rdB = [&](const char* p, int n, int k) {
        uint32_t off = b_tile_off(n, k);
        return __bfloat162float(*(const __nv_bfloat16*)(p + off));
    };
    for (int half = 0; half < 2; half++) {
        int bn2 = bn + half * 128;
        float acc[8][8];
#pragma unroll
        for (int i = 0; i < 8; i++)
#pragma unroll
            for (int j = 0; j < 8; j++) acc[i][j] = 0.f;
        for (int k0 = 0; k0 < GK; k0 += 16) {
            for (int i = tid; i < 2048; i += 256) {
                int r = i >> 4, kk = i & 15;
                sA[kk*128 + r] = rdA(Ahi, bm + r, k0 + kk) + rdA(Alo, bm + r, k0 + kk);
                sB[kk*128 + r] = rdB(Bhi, bn2 + r, k0 + kk) + rdB(Blo, bn2 + r, k0 + kk);
            }
            __syncthreads();
#pragma unroll
            for (int kk = 0; kk < 16; kk++) {
                float a[8], b[8];
#pragma unroll
                for (int i = 0; i < 4; i++) {
                    a[i] = sA[kk*128 + ty*4 + i];
                    a[i+4] = sA[kk*128 + 64 + ty*4 + i];
                    b[i] = sB[kk*128 + tx*4 + i];
                    b[i+4] = sB[kk*128 + 64 + tx*4 + i];
                }
#pragma unroll
                for (int i = 0; i < 8; i++)
#pragma unroll
                    for (int j = 0; j < 8; j++) acc[i][j] += a[i] * b[j];
            }
            __syncthreads();
        }
#pragma unroll
        for (int i = 0; i < 8; i++) {
            int row = bm + ((i < 4) ? (ty*4 + i) : (64 + ty*4 + i - 4));
#pragma unroll
            for (int j = 0; j < 8; j++) {
                int col = bn2 + ((j < 4) ? (tx*4 + j) : (64 + tx*4 + j - 4));
                C[(size_t)row * GN + col] = acc[i][j];
            }
        }
        __syncthreads();
    }
#endif
}

// ---------------------------------------------------------------------------
// dt = softplus(hs @ Wdt)
// ---------------------------------------------------------------------------
__global__ __launch_bounds__(256) void dt2(const float* __restrict__ hs,
                                           const float* __restrict__ Wdt) {
    extern __shared__ float sw[];
    int tid = threadIdx.x;
    for (int i = tid; i < 16384; i += 256)
        sw[(i & 15) * 1028 + (i >> 4)] = Wdt[i];
    __syncthreads();
    int w = tid >> 5, l = tid & 31;
    int row0 = blockIdx.x * 32 + w * 4;
    float acc[4][16];
#pragma unroll
    for (int r = 0; r < 4; r++)
#pragma unroll
        for (int n = 0; n < 16; n++) acc[r][n] = 0.f;
#pragma unroll
    for (int it = 0; it < 8; it++) {
        int k0 = it * 128 + l * 4;
        float4 h[4];
#pragma unroll
        for (int r = 0; r < 4; r++)
            h[r] = *(const float4*)&hs[(size_t)(row0 + r) * DD + k0];
#pragma unroll
        for (int n = 0; n < 16; n++) {
            float4 wv = *(const float4*)&sw[n * 1028 + k0];
#pragma unroll
            for (int r = 0; r < 4; r++)
                acc[r][n] += h[r].x*wv.x + h[r].y*wv.y + h[r].z*wv.z + h[r].w*wv.w;
        }
    }
#pragma unroll
    for (int off = 16; off; off >>= 1)
#pragma unroll
        for (int r = 0; r < 4; r++)
#pragma unroll
            for (int n = 0; n < 16; n++)
                acc[r][n] += __shfl_xor_sync(0xFFFFFFFFu, acc[r][n], off);
    if (l == 0) {
#pragma unroll
        for (int r = 0; r < 4; r++)
#pragma unroll
            for (int n = 0; n < 16; n++) {
                float s = acc[r][n];
                g_dt[(row0 + r) * HH + n] = fmaxf(s, 0.f) + log1pf(expf(-fabsf(s)));
            }
    }
}

// ---------------------------------------------------------------------------
// Per-chunk inclusive cumsum of dA
// ---------------------------------------------------------------------------
__global__ __launch_bounds__(256) void acum_kernel(const float* __restrict__ A) {
    __shared__ float s[256];
    int bid = blockIdx.x;
    int h = bid & 15, c = (bid >> 4) & 31, b = bid >> 9;
    int l = threadIdx.x;
    int row = b * LL + c * CLc + l;
    s[l] = g_dt[row * HH + h] * A[h];
    __syncthreads();
    for (int off = 1; off < 256; off <<= 1) {
        float u = (l >= off) ? s[l - off] : 0.f;
        __syncthreads();
        s[l] += u;
        __syncthreads();
    }
    g_ac[row * HH + h] = s[l];
    if (l == 255) g_cdec[bid] = expf(s[255]);
}

// ---------------------------------------------------------------------------
// Chunk states (rope + x*dt fused into the fill, vectorized)
// ---------------------------------------------------------------------------
__global__ __launch_bounds__(256) void kb_kernel(const float* __restrict__ cosp,
                                                 const float* __restrict__ sinp) {
    __shared__ float sX[4096];
    __shared__ float sB[4096];
    int bid = blockIdx.x;
    int h = bid & 15, c = (bid >> 4) & 31, b = bid >> 9;
    int tid = threadIdx.x, tx = tid & 15, ty = tid >> 4;
    int chunk_row = b * LL + c * CLc;
    float aclast = g_ac[(chunk_row + 255) * HH + h];

    float acc[4][4];
#pragma unroll
    for (int i = 0; i < 4; i++)
#pragma unroll
        for (int j = 0; j < 4; j++) acc[i][j] = 0.f;

    for (int ltile = 0; ltile < 4; ltile++) {
        int r0 = chunk_row + ltile * 64;
#pragma unroll
        for (int t = 0; t < 2; t++) {
            int u = tid + t * 256;
            int rr = u >> 3, p4 = (u & 7) * 4;
            int row = r0 + rr;
            const float* bb = g_b + (size_t)row * DD + h * 64;
            const float* xx = g_x + (size_t)row * DD + h * 64;
            float4 a  = *(const float4*)(bb + p4);
            float4 q  = *(const float4*)(bb + p4 + 32);
            float4 c1 = *(const float4*)(cosp + row*64 + p4);
            float4 c2 = *(const float4*)(cosp + row*64 + p4 + 32);
            float4 s1 = *(const float4*)(sinp + row*64 + p4);
            float4 s2 = *(const float4*)(sinp + row*64 + p4 + 32);
            float w = __expf(aclast - g_ac[row * HH + h]);
            float dtv = g_dt[row * HH + h];
            float4 v1 = make_float4((a.x*c1.x - q.x*s1.x)*w, (a.y*c1.y - q.y*s1.y)*w,
                                    (a.z*c1.z - q.z*s1.z)*w, (a.w*c1.w - q.w*s1.w)*w);
            float4 v2 = make_float4((q.x*c2.x + a.x*s2.x)*w, (q.y*c2.y + a.y*s2.y)*w,
                                    (q.z*c2.z + a.z*s2.z)*w, (q.w*c2.w + a.w*s2.w)*w);
            *(float4*)&sB[rr*64 + p4]      = v1;
            *(float4*)&sB[rr*64 + p4 + 32] = v2;
            float4 xv1 = *(const float4*)(xx + p4);
            float4 xv2 = *(const float4*)(xx + p4 + 32);
            *(float4*)&sX[rr*64 + p4] =
                make_float4(xv1.x*dtv, xv1.y*dtv, xv1.z*dtv, xv1.w*dtv);
            *(float4*)&sX[rr*64 + p4 + 32] =
                make_float4(xv2.x*dtv, xv2.y*dtv, xv2.z*dtv, xv2.w*dtv);
        }
        __syncthreads();
#pragma unroll 4
        for (int l = 0; l < 64; l++) {
            float xv[4], bv[4];
#pragma unroll
            for (int i = 0; i < 4; i++) xv[i] = sX[l * 64 + ty * 4 + i];
#pragma unroll
            for (int j = 0; j < 4; j++) bv[j] = sB[l * 64 + tx * 4 + j];
#pragma unroll
            for (int i = 0; i < 4; i++)
#pragma unroll
                for (int j = 0; j < 4; j++) acc[i][j] += xv[i] * bv[j];
        }
        __syncthreads();
    }
    int sb = ((b * NCC + c) * HH + h) * 4096;
#pragma unroll
    for (int i = 0; i < 4; i++) {
        float4 v = make_float4(acc[i][0], acc[i][1], acc[i][2], acc[i][3]);
        *(float4*)&g_states[sb + (ty * 4 + i) * 64 + tx * 4] = v;
    }
}

// ---------------------------------------------------------------------------
// Sequential chunk scan
// ---------------------------------------------------------------------------
__global__ __launch_bounds__(256) void kc_kernel(float* __restrict__ fs) {
    int bid = blockIdx.x;
    int h = bid & 15, b = bid >> 4;
    int tid = threadIdx.x;
    float st[16];
#pragma unroll
    for (int k = 0; k < 16; k++) st[k] = 0.f;
    for (int c = 0; c < NCC; c++) {
        float dec = g_cdec[(b * NCC + c) * HH + h];
        int base = ((b * NCC + c) * HH + h) * 4096;
#pragma unroll
        for (int k = 0; k < 16; k++) {
            int e = k * 256 + tid;
            g_prev[base + e] = st[k];
            st[k] = st[k] * dec + g_states[base + e];
        }
    }
    int fb = (b * HH + h) * 4096;
#pragma unroll
    for (int k = 0; k < 16; k++) fs[fb + k * 256 + tid] = st[k];
}

// ---------------------------------------------------------------------------
// Flash kernel: Y_diag + Y_off on tensor cores; vectorized fills, tiled y out.
// ALL MMA tile bases are 1024-byte aligned (SW128 requirement).
// ---------------------------------------------------------------------------
#define FL_SMEM 183296
#define FO_AC   64
#define FO_DT   1088
#define FO_CHI  3072
#define FO_CLO  19456
#define FO_BHI  35840
#define FO_BLO  68608
#define FO_XHI  101376
#define FO_XLO  134144
#define FO_PHI  166912
#define FO_PLO  175104

__global__ __launch_bounds__(256, 1) void flash_k(const float* __restrict__ cosp,
                                                  const float* __restrict__ sinp,
                                                  char* __restrict__ yhi,
                                                  char* __restrict__ ylo) {
    extern __shared__ char sm[];
    int tid = threadIdx.x, wid = tid >> 5, lid = tid & 31;
    int bid = blockIdx.x;
    int half = bid & 1, h = (bid >> 1) & 15, c = (bid >> 5) & 31, b = bid >> 10;
    int chunk_row = b * LL + c * CLc;
    int l0g = half * 128;
    int SL = half ? 256 : 128;
    float* acs = (float*)(sm + FO_AC);
    float* sdt = (float*)(sm + FO_DT);

#if HAS_TCGEN05
    uint32_t sbase = smem_u32(sm);
    int nsl = SL / 128;
    if (tid == 0) {
        MBAR_INIT(sbase + 8, 1);  MBAR_INIT(sbase + 16, 1);
        MBAR_INIT(sbase + 24, 1); MBAR_INIT(sbase + 32, 1);
    }
    if (wid == 0) TC_ALLOC(sbase, 512);
    __syncthreads();
    uint32_t tmem;
    asm volatile("ld.shared.b32 %0, [%1];" : "=r"(tmem) : "r"(sbase));

    acs[tid] = g_ac[(chunk_row + tid) * HH + h];
    sdt[tid] = g_dt[(chunk_row + tid) * HH + h];
    __syncthreads();

    // C tile (rope) 128x64 hi/lo
#pragma unroll
    for (int t = 0; t < 4; t++) {
        int u = tid + t * 256;
        int rr = u >> 3, p4 = (u & 7) * 4;
        int row = chunk_row + l0g + rr;
        const float* cb = g_c + (size_t)row * DD + h * 64;
        float4 a  = *(const float4*)(cb + p4);
        float4 q  = *(const float4*)(cb + p4 + 32);
        float4 c1 = *(const float4*)(cosp + row*64 + p4);
        float4 c2 = *(const float4*)(cosp + row*64 + p4 + 32);
        float4 s1 = *(const float4*)(sinp + row*64 + p4);
        float4 s2 = *(const float4*)(sinp + row*64 + p4 + 32);
        float v1[4] = {a.x*c1.x - q.x*s1.x, a.y*c1.y - q.y*s1.y,
                       a.z*c1.z - q.z*s1.z, a.w*c1.w - q.w*s1.w};
        float v2[4] = {q.x*c2.x + a.x*s2.x, q.y*c2.y + a.y*s2.y,
                       q.z*c2.z + a.z*s2.z, q.w*c2.w + a.w*s2.w};
        float hh[4], llv[4];
        uint32_t o1 = swz((uint32_t)(rr*128 + p4*2));
        uint32_t o2 = swz((uint32_t)(rr*128 + (p4+32)*2));
#pragma unroll
        for (int i = 0; i < 4; i++) split2(v1[i], hh[i], llv[i]);
        *(uint2*)(sm + FO_CHI + o1) = make_uint2(pack_bf2(hh[0],hh[1]), pack_bf2(hh[2],hh[3]));
        *(uint2*)(sm + FO_CLO + o1) = make_uint2(pack_bf2(llv[0],llv[1]), pack_bf2(llv[2],llv[3]));
#pragma unroll
        for (int i = 0; i < 4; i++) split2(v2[i], hh[i], llv[i]);
        *(uint2*)(sm + FO_CHI + o2) = make_uint2(pack_bf2(hh[0],hh[1]), pack_bf2(hh[2],hh[3]));
        *(uint2*)(sm + FO_CLO + o2) = make_uint2(pack_bf2(llv[0],llv[1]), pack_bf2(llv[2],llv[3]));
    }
    // B tile (rope) SLx64 hi/lo
    for (int t = 0; t < SL/32; t++) {
        int u = tid + t * 256;
        int rr = u >> 3, p4 = (u & 7) * 4;
        int row = chunk_row + rr;
        const float* bb = g_b + (size_t)row * DD + h * 64;
        float4 a  = *(const float4*)(bb + p4);
        float4 q  = *(const float4*)(bb + p4 + 32);
        float4 c1 = *(const float4*)(cosp + row*64 + p4);
        float4 c2 = *(const float4*)(cosp + row*64 + p4 + 32);
        float4 s1 = *(const float4*)(sinp + row*64 + p4);
        float4 s2 = *(const float4*)(sinp + row*64 + p4 + 32);
        float v1[4] = {a.x*c1.x - q.x*s1.x, a.y*c1.y - q.y*s1.y,
                       a.z*c1.z - q.z*s1.z, a.w*c1.w - q.w*s1.w};
        float v2[4] = {q.x*c2.x + a.x*s2.x, q.y*c2.y + a.y*s2.y,
                       q.z*c2.z + a.z*s2.z, q.w*c2.w + a.w*s2.w};
        float hh[4], llv[4];
        uint32_t o1 = swz((uint32_t)(rr*128 + p4*2));
        uint32_t o2 = swz((uint32_t)(rr*128 + (p4+32)*2));
#pragma unroll
        for (int i = 0; i < 4; i++) split2(v1[i], hh[i], llv[i]);
        *(uint2*)(sm + FO_BHI + o1) = make_uint2(pack_bf2(hh[0],hh[1]), pack_bf2(hh[2],hh[3]));
        *(uint2*)(sm + FO_BLO + o1) = make_uint2(pack_bf2(llv[0],llv[1]), pack_bf2(llv[2],llv[3]));
#pragma unroll
        for (int i = 0; i < 4; i++) split2(v2[i], hh[i], llv[i]);
        *(uint2*)(sm + FO_BHI + o2) = make_uint2(pack_bf2(hh[0],hh[1]), pack_bf2(hh[2],hh[3]));
        *(uint2*)(sm + FO_BLO + o2) = make_uint2(pack_bf2(llv[0],llv[1]), pack_bf2(llv[2],llv[3]));
    }
    // X^T tile: [64 p][SL s] blocked atoms; units (p, s-group of 4)
    for (int t = 0; t < SL/16; t++) {
        int u = tid + t * 256;
        int p = u & 63, sg = u >> 6;
        int s0 = sg * 4;
        float hh[4], llv[4];
#pragma unroll
        for (int i = 0; i < 4; i++) {
            int s = s0 + i;
            float xv = g_x[(size_t)(chunk_row + s) * DD + h*64 + p] * sdt[s];
            split2(xv, hh[i], llv[i]);
        }
        uint32_t off = swz((uint32_t)(((p>>3) + (s0>>6)*8)*1024 + (p&7)*128 + (s0&63)*2));
        *(uint2*)(sm + FO_XHI + off) = make_uint2(pack_bf2(hh[0],hh[1]), pack_bf2(hh[2],hh[3]));
        *(uint2*)(sm + FO_XLO + off) = make_uint2(pack_bf2(llv[0],llv[1]), pack_bf2(llv[2],llv[3]));
    }
    // prev tile [64 p][64 n]
    {
        int pbase = ((b * NCC + c) * HH + h) * 4096;
#pragma unroll
        for (int t = 0; t < 4; t++) {
            int u = tid + t * 256;
            int p = u >> 4, n4 = (u & 15) * 4;
            float4 v = *(const float4*)(g_prev + pbase + p*64 + n4);
            float hh[4], llv[4];
            split2(v.x, hh[0], llv[0]); split2(v.y, hh[1], llv[1]);
            split2(v.z, hh[2], llv[2]); split2(v.w, hh[3], llv[3]);
            uint32_t off = swz((uint32_t)(p*128 + n4*2));
            *(uint2*)(sm + FO_PHI + off) = make_uint2(pack_bf2(hh[0],hh[1]), pack_bf2(hh[2],hh[3]));
            *(uint2*)(sm + FO_PLO + off) = make_uint2(pack_bf2(llv[0],llv[1]), pack_bf2(llv[2],llv[3]));
        }
    }
    FENCE_ASYNC();
    __syncthreads();

    // MMA1: S = C * B^T, plus off-term Y2 = C * prev^T
    if (wid == 0 && elect_one()) {
        uint64_t dCh = mk_desc(sbase + FO_CHI), dCl = mk_desc(sbase + FO_CLO);
        uint64_t dBh = mk_desc(sbase + FO_BHI), dBl = mk_desc(sbase + FO_BLO);
        uint32_t id1 = (SL == 128) ? IDESC_N(128) : IDESC_N(256);
#pragma unroll
        for (int ks = 0; ks < 4; ks++) {
            mma_f16_ss(tmem, dCh + ks*2, dBh + ks*2, id1, ks > 0);
            mma_f16_ss(tmem, dCh + ks*2, dBl + ks*2, id1, 1);
            mma_f16_ss(tmem, dCl + ks*2, dBh + ks*2, id1, 1);
        }
        TC_COMMIT(sbase + 8);
        uint64_t dPh = mk_desc(sbase + FO_PHI), dPl = mk_desc(sbase + FO_PLO);
        uint32_t id64 = IDESC_N(64);
#pragma unroll
        for (int ks = 0; ks < 4; ks++) {
            mma_f16_ss(tmem + 320, dCh + ks*2, dPh + ks*2, id64, ks > 0);
            mma_f16_ss(tmem + 320, dCh + ks*2, dPl + ks*2, id64, 1);
            mma_f16_ss(tmem + 320, dCl + ks*2, dPh + ks*2, id64, 1);
        }
        TC_COMMIT(sbase + 16);
    }
    MBAR_WAIT(sbase + 8, 0);
    TC_FENCE_AFTER();

    int sub = wid & 3, grp = wid >> 2;
    int lrow = sub * 32 + lid;
    float acl = acs[l0g + lrow];

    for (int sl = 0; sl < nsl; sl++) {
        if (sl == 1) MBAR_WAIT(sbase + 24, 0);
#pragma unroll
        for (int rd = grp; rd < 4; rd += 2) {
            uint32_t r[32];
            ldtm32(r, tmem + sl*128 + rd*32);
            TC_WAIT_LD();
            int colbase = sl*128 + rd*32;
#pragma unroll
            for (int j = 0; j < 32; j += 4) {
                float vv[4], hh[4], llv[4];
#pragma unroll
                for (int i = 0; i < 4; i++) {
                    int cg = colbase + j + i;
                    float v = __uint_as_float(r[j+i]);
                    vv[i] = (cg <= l0g + lrow) ? v * __expf(acl - acs[cg]) : 0.f;
                    split2(vv[i], hh[i], llv[i]);
                }
                int sIn = rd*32 + j;
                uint32_t off = swz((uint32_t)(((lrow>>3) + (sIn>>6)*16)*1024
                                              + (lrow&7)*128 + (sIn&63)*2));
                *(uint2*)(sm + FO_BHI + off) = make_uint2(pack_bf2(hh[0],hh[1]), pack_bf2(hh[2],hh[3]));
                *(uint2*)(sm + FO_BLO + off) = make_uint2(pack_bf2(llv[0],llv[1]), pack_bf2(llv[2],llv[3]));
            }
        }
        FENCE_ASYNC();
        __syncthreads();
        if (wid == 0 && elect_one()) {
            uint64_t dSh = mk_desc(sbase + FO_BHI), dSl = mk_desc(sbase + FO_BLO);
            uint64_t dXh = mk_desc(sbase + FO_XHI), dXl = mk_desc(sbase + FO_XLO);
            uint32_t id64 = IDESC_N(64);
#pragma unroll
            for (int ks2 = 0; ks2 < 8; ks2++) {
                int ksg = sl*8 + ks2;
                uint64_t ao = (uint64_t)((ks2 >> 2)*1024 + (ks2 & 3)*2);
                uint64_t bo = (uint64_t)((ksg >> 2)*512 + (ksg & 3)*2);
                mma_f16_ss(tmem + 256, dSh + ao, dXh + bo, id64,
                           !(sl == 0 && ks2 == 0));
                mma_f16_ss(tmem + 256, dSh + ao, dXl + bo, id64, 1);
                mma_f16_ss(tmem + 256, dSl + ao, dXh + bo, id64, 1);
            }
            TC_COMMIT(sbase + 24 + (uint32_t)sl * 8);
        }
    }
    MBAR_WAIT(sbase + 24 + (uint32_t)(nsl - 1) * 8, 0);
    MBAR_WAIT(sbase + 16, 0);
    TC_FENCE_AFTER();

    // Final epilogue: write y as TILED bf16 hi/lo (tile = (row>>7)*16 + h)
    {
        int row = chunk_row + l0g + lrow;
        uint32_t tile = (uint32_t)(row >> 7) * 16u + (uint32_t)h;
        char* dhi = yhi + ((size_t)tile << 14);
        char* dlo = ylo + ((size_t)tile << 14);
        float e = __expf(acl);
        uint32_t y1[32], y2[32];
        ldtm32(y1, tmem + 256 + grp*32); TC_WAIT_LD();
        ldtm32(y2, tmem + 320 + grp*32); TC_WAIT_LD();
#pragma unroll
        for (int j = 0; j < 32; j += 4) {
            float hh[4], llv[4];
#pragma unroll
            for (int i = 0; i < 4; i++) {
                float v = __uint_as_float(y1[j+i]) + e * __uint_as_float(y2[j+i]);
                split2(v, hh[i], llv[i]);
            }
            uint32_t off = swz((uint32_t)((row & 127)*128 + (grp*32 + j)*2));
            *(uint2*)(dhi + off) = make_uint2(pack_bf2(hh[0],hh[1]), pack_bf2(hh[2],hh[3]));
            *(uint2*)(dlo + off) = make_uint2(pack_bf2(llv[0],llv[1]), pack_bf2(llv[2],llv[3]));
        }
        TC_FENCE_BEFORE();
    }
    __syncthreads();
    if (wid == 0) TC_DEALLOC(tmem, 512);
#else
    // CUDA-core fallback (non-'a' pass only)
    float* sC = (float*)(sm + FO_CHI);     // 32KB
    float* sS = (float*)(sm + FO_BHI);     // 32KB
    float* sB = (float*)(sm + FO_BLO);     // 16KB used
    float* sX = (float*)(sm + FO_XHI);     // 16KB used
    float* sP = (float*)(sm + FO_XLO);     // 16KB used
    int tx = tid & 15, ty = tid >> 4;

    acs[tid] = g_ac[(chunk_row + tid) * HH + h];
    for (int t = 0; t < 16; t++) {
        int pr = tid + t * 256;
        int rr = pr >> 5, pp = pr & 31;
        int row = chunk_row + l0g + rr;
        const float* cb = g_c + (size_t)row * DD + h * 64;
        float a = cb[pp], q = cb[pp + 32];
        float c1 = cosp[row*64 + pp],      s1 = sinp[row*64 + pp];
        float c2 = cosp[row*64 + pp + 32], s2 = sinp[row*64 + pp + 32];
        sC[rr*64 + pp]      = a * c1 - q * s1;
        sC[rr*64 + pp + 32] = q * c2 + a * s2;
    }
    {
        int pbase = ((b * NCC + c) * HH + h) * 4096;
        for (int t = 0; t < 16; t++) {
            int idx = tid + t * 256;
            sP[idx] = g_prev[pbase + idx];
        }
    }
    __syncthreads();

    float accD[8][4], accO[8][4];
#pragma unroll
    for (int i = 0; i < 8; i++)
#pragma unroll
        for (int j = 0; j < 4; j++) { accD[i][j] = 0.f; accO[i][j] = 0.f; }
    for (int n = 0; n < 64; n++)
#pragma unroll
        for (int i = 0; i < 8; i++)
#pragma unroll
            for (int j = 0; j < 4; j++)
                accO[i][j] += sC[(ty*8+i)*64 + n] * sP[(tx*4+j)*64 + n];

    for (int stile = 0; stile < SL/64; stile++) {
        for (int t = 0; t < 8; t++) {
            int pr = tid + t * 256;
            int rr = pr >> 5, pp = pr & 31;
            int row = chunk_row + stile*64 + rr;
            const float* bb = g_b + (size_t)row * DD + h * 64;
            const float* xx = g_x + (size_t)row * DD + h * 64;
            float a = bb[pp], q = bb[pp + 32];
            float c1 = cosp[row*64 + pp],      s1 = sinp[row*64 + pp];
            float c2 = cosp[row*64 + pp + 32], s2 = sinp[row*64 + pp + 32];
            float dtv = g_dt[row * HH + h];
            sB[rr*64 + pp]      = a * c1 - q * s1;
            sB[rr*64 + pp + 32] = q * c2 + a * s2;
            sX[rr*64 + pp]      = xx[pp] * dtv;
            sX[rr*64 + pp + 32] = xx[pp + 32] * dtv;
        }
        __syncthreads();
        for (int t = 0; t < 32; t++) {
            int idx = tid + t * 256;
            int l = idx >> 6, sIn = idx & 63;
            int sg = stile*64 + sIn;
            float v = 0.f;
            if (sg <= l0g + l) {
                for (int n = 0; n < 64; n++)
                    v += sC[l*64 + n] * sB[sIn*64 + n];
                v *= expf(acs[l0g + l] - acs[sg]);
            }
            sS[idx] = v;
        }
        __syncthreads();
        for (int s = 0; s < 64; s++)
#pragma unroll
            for (int i = 0; i < 8; i++)
#pragma unroll
                for (int j = 0; j < 4; j++)
                    accD[i][j] += sS[(ty*8+i)*64 + s] * sX[s*64 + tx*4 + j];
        __syncthreads();
    }
#pragma unroll
    for (int i = 0; i < 8; i++) {
        int lr = ty*8 + i;
        int row = chunk_row + l0g + lr;
        float e = expf(acs[l0g + lr]);
        uint32_t tile = (uint32_t)(row >> 7) * 16u + (uint32_t)h;
#pragma unroll
        for (int j = 0; j < 4; j++) {
            float v = accD[i][j] + e * accO[i][j];
            float hh, llv;
            split2(v, hh, llv);
            int col = tx*4 + j;
            uint32_t off = ((uint32_t)tile << 14) +
                           swz((uint32_t)((row & 127)*128 + col*2));
            *(__nv_bfloat16*)(yhi + off) = __float2bfloat16(hh);
            *(__nv_bfloat16*)(ylo + off) = __float2bfloat16(llv);
        }
    }
#endif
}

// ---------------------------------------------------------------------------
// kernel_launch
// ---------------------------------------------------------------------------
extern "C" void kernel_launch(void* const* d_in, const int* in_sizes, int n_in,
                              void* d_out, int out_size) {
    (void)in_sizes; (void)n_in; (void)out_size;
    const float* hs   = (const float*)d_in[0];
    const float* cosp = (const float*)d_in[1];
    const float* sinp = (const float*)d_in[2];
    const float* Wc   = (const float*)d_in[3];
    const float* Wb   = (const float*)d_in[4];
    const float* Wdt  = (const float*)d_in[5];
    const float* Wx   = (const float*)d_in[6];
    const float* Wout = (const float*)d_in[7];
    const float* A    = (const float*)d_in[8];
    float* out = (float*)d_out;
    float* fs  = out + (size_t)MM * DD;

    float *pc, *pb, *px;
    char *ahi, *alo, *whi, *wlo;
    cudaGetSymbolAddress((void**)&pc, g_c);
    cudaGetSymbolAddress((void**)&pb, g_b);
    cudaGetSymbolAddress((void**)&px, g_x);
    cudaGetSymbolAddress((void**)&ahi, g_ahi);
    cudaGetSymbolAddress((void**)&alo, g_alo);
    cudaGetSymbolAddress((void**)&whi, g_wt_hi);
    cudaGetSymbolAddress((void**)&wlo, g_wt_lo);

    const size_t WSZ = (size_t)2 * DD * DD;   // bytes per weight matrix (bf16)

    int gemm_smem = 1024 + 2 * BUF_STRIDE;
    int dt_smem = 16 * 1028 * 4;
    cudaFuncSetAttribute(gemm_t, cudaFuncAttributeMaxDynamicSharedMemorySize, gemm_smem);
    cudaFuncSetAttribute(dt2, cudaFuncAttributeMaxDynamicSharedMemorySize, dt_smem);
    cudaFuncSetAttribute(flash_k, cudaFuncAttributeMaxDynamicSharedMemorySize, FL_SMEM);

    fsplit<<<MM * DD / 8 / 256, 256>>>(hs, ahi, alo);
    dim3 wg(32, 32);
    wsplit<<<wg, 256>>>(Wc,   whi + 0*WSZ, wlo + 0*WSZ);
    wsplit<<<wg, 256>>>(Wb,   whi + 1*WSZ, wlo + 1*WSZ);
    wsplit<<<wg, 256>>>(Wx,   whi + 2*WSZ, wlo + 2*WSZ);
    wsplit<<<wg, 256>>>(Wout, whi + 3*WSZ, wlo + 3*WSZ);

    dim3 gg(GN / 256, MM / 128);
    gemm_t<<<gg, 256, gemm_smem>>>(ahi, alo, whi + 0*WSZ, wlo + 0*WSZ, pc);
    gemm_t<<<gg, 256, gemm_smem>>>(ahi, alo, whi + 1*WSZ, wlo + 1*WSZ, pb);
    gemm_t<<<gg, 256, gemm_smem>>>(ahi, alo, whi + 2*WSZ, wlo + 2*WSZ, px);

    dt2<<<MM / 32, 256, dt_smem>>>(hs, Wdt);
    acum_kernel<<<BB * NCC * HH, 256>>>(A);
    kb_kernel<<<BB * NCC * HH, 256>>>(cosp, sinp);
    kc_kernel<<<BB * HH, 256>>>(fs);

    flash_k<<<BB * NCC * HH * 2, 256, FL_SMEM>>>(cosp, sinp, ahi, alo);

    gemm_t<<<gg, 256, gemm_smem>>>(ahi, alo, whi + 3*WSZ, wlo + 3*WSZ, out);
}

// round 8
// speedup vs baseline: 4.7938x; 1.0873x over previous
#include <cuda_runtime.h>
#include <cuda_bf16.h>
#include <math.h>
#include <stdint.h>

// Problem constants (fixed by the dataset)
#define BB  2
#define LL  8192
#define DD  1024
#define HH  16
#define PP  64
#define CLc 256
#define NCC 32
#define MM  (BB*LL)   // 16384 rows

#if defined(__CUDA_ARCH_FEAT_SM103_ALL) || defined(__CUDA_ARCH_FEAT_SM100_ALL) || \
    defined(__CUDA_ARCH_FEAT_SM101_ALL) || defined(__CUDA_ARCH_SPECIFIC__)
#define HAS_TCGEN05 1
#else
#define HAS_TCGEN05 0
#endif

// ---------------------------------------------------------------------------
// Scratch
// ---------------------------------------------------------------------------
__device__ float g_c[BB*LL*DD];
__device__ float g_b[BB*LL*DD];
__device__ float g_x[BB*LL*DD];
__device__ float g_dt[BB*LL*HH];
__device__ float g_ac[BB*LL*HH];
__device__ float g_cdec[BB*NCC*HH];
__device__ float g_states[BB*NCC*HH*PP*PP];
__device__ float g_prev[BB*NCC*HH*PP*PP];

// TILED bf16 operands: A-side tiles 128x64 (16KB, swizzled), index (mb*16+chunk).
// B-side (weights) tiles 256x64 (32KB, swizzled), index (nb*16+chunk).
__device__ __nv_bfloat16 g_ahi[MM*DD];
__device__ __nv_bfloat16 g_alo[MM*DD];
__device__ __nv_bfloat16 g_wt_hi[4][DD*DD];
__device__ __nv_bfloat16 g_wt_lo[4][DD*DD];

// ---------------------------------------------------------------------------
// Helpers
// ---------------------------------------------------------------------------
__device__ __forceinline__ uint32_t smem_u32(const void* p) {
    uint32_t a;
    asm("{ .reg .u64 t; cvta.to.shared.u64 t, %1; cvt.u32.u64 %0, t; }"
        : "=r"(a) : "l"(p));
    return a;
}
__device__ __forceinline__ uint32_t swz(uint32_t off) { return off ^ ((off >> 3) & 0x70); }

__device__ __forceinline__ void split2(float v, float& hi, float& lo) {
    __nv_bfloat16 h = __float2bfloat16(v);
    hi = __bfloat162float(h);
    lo = v - hi;
}
__device__ __forceinline__ uint32_t pack_bf2(float a, float b) {
    __nv_bfloat162 t = __halves2bfloat162(__float2bfloat16(a), __float2bfloat16(b));
    return *(uint32_t*)&t;
}
// Packed split: (v0, v1) -> hi2 (bf16x2: lower=v0, upper=v1), lo2 likewise.
__device__ __forceinline__ void split_pack2(float v0, float v1,
                                            uint32_t& hi2, uint32_t& lo2) {
    asm("cvt.rn.bf16x2.f32 %0, %1, %2;" : "=r"(hi2) : "f"(v1), "f"(v0));
    float h0 = __uint_as_float(hi2 << 16);
    float h1 = __uint_as_float(hi2 & 0xFFFF0000u);
    asm("cvt.rn.bf16x2.f32 %0, %1, %2;" : "=r"(lo2) : "f"(v1 - h1), "f"(v0 - h0));
}

// tiled-layout addressing
__device__ __forceinline__ uint32_t a_tile_off(int row, int k) {   // 128-row tiles
    uint32_t tile = (uint32_t)(row >> 7) * 16u + (uint32_t)(k >> 6);
    return (tile << 14) + swz(((uint32_t)(row & 127) << 7) + ((uint32_t)(k & 63) << 1));
}
__device__ __forceinline__ uint32_t b_tile_off(int n, int k) {     // 256-row tiles
    uint32_t tile = (uint32_t)(n >> 8) * 16u + (uint32_t)(k >> 6);
    return (tile << 15) + swz(((uint32_t)(n & 255) << 7) + ((uint32_t)(k & 63) << 1));
}

#if HAS_TCGEN05
__device__ __forceinline__ uint32_t elect_one() {
    uint32_t pred;
    asm volatile("{\n\t.reg .pred p;\n\telect.sync _|p, 0xFFFFFFFF;\n\t"
                 "selp.b32 %0, 1, 0, p;\n\t}" : "=r"(pred));
    return pred;
}
#define MBAR_INIT(a, c) \
    asm volatile("mbarrier.init.shared.b64 [%0], %1;" :: "r"(a), "r"(c) : "memory")
#define MBAR_EXPECT_TX(a, n) \
    asm volatile("mbarrier.arrive.expect_tx.shared.b64 _, [%0], %1;" :: "r"(a), "r"(n) : "memory")
#define MBAR_WAIT(a, ph) do { \
    asm volatile("{\n\t.reg .pred P1;\n\t" \
        "WL_%=:\n\t" \
        "mbarrier.try_wait.parity.acquire.cta.shared::cta.b64 P1, [%0], %1, 0x989680;\n\t" \
        "@P1 bra.uni WD_%=;\n\tbra.uni WL_%=;\n\tWD_%=:\n\t}" \
        :: "r"(a), "r"(ph) : "memory"); \
} while (0)
#define BULK_G2S(dst, src, n, mbar) \
    asm volatile("cp.async.bulk.shared::cta.global.mbarrier::complete_tx::bytes " \
                 "[%0], [%1], %2, [%3];" \
                 :: "r"(dst), "l"(src), "r"(n), "r"(mbar) : "memory")
#define TC_ALLOC(sa, n) \
    asm volatile("tcgen05.alloc.cta_group::1.sync.aligned.shared::cta.b32 [%0], %1;" \
                 :: "r"(sa), "r"(n) : "memory")
#define TC_DEALLOC(t, n) \
    asm volatile("tcgen05.dealloc.cta_group::1.sync.aligned.b32 %0, %1;" :: "r"(t), "r"(n))
#define TC_COMMIT(a) \
    asm volatile("tcgen05.commit.cta_group::1.mbarrier::arrive::one.shared::cluster.b64 [%0];" \
                 :: "r"(a) : "memory")
#define TC_FENCE_AFTER() asm volatile("tcgen05.fence::after_thread_sync;" ::: "memory")
#define TC_FENCE_BEFORE() asm volatile("tcgen05.fence::before_thread_sync;" ::: "memory")
#define TC_WAIT_LD() asm volatile("tcgen05.wait::ld.sync.aligned;" ::: "memory")
#define FENCE_ASYNC() asm volatile("fence.proxy.async.shared::cta;" ::: "memory")

__device__ __forceinline__ void mma_f16_ss(uint32_t d, uint64_t ad, uint64_t bd,
                                           uint32_t idesc, uint32_t en) {
    asm volatile("{\n\t.reg .pred p;\n\tsetp.ne.u32 p, %4, 0;\n\t"
                 "tcgen05.mma.cta_group::1.kind::f16 [%0], %1, %2, %3, {%5,%5,%5,%5}, p;\n\t}"
                 :: "r"(d), "l"(ad), "l"(bd), "r"(idesc), "r"(en), "r"(0u) : "memory");
}
__device__ __forceinline__ void ldtm32(uint32_t* r, uint32_t ta) {
    asm volatile("tcgen05.ld.sync.aligned.32x32b.x32.b32 "
        "{%0,%1,%2,%3,%4,%5,%6,%7,%8,%9,%10,%11,%12,%13,%14,%15,"
        "%16,%17,%18,%19,%20,%21,%22,%23,%24,%25,%26,%27,%28,%29,%30,%31}, [%32];"
        : "=r"(r[0]),"=r"(r[1]),"=r"(r[2]),"=r"(r[3]),"=r"(r[4]),"=r"(r[5]),"=r"(r[6]),"=r"(r[7]),
          "=r"(r[8]),"=r"(r[9]),"=r"(r[10]),"=r"(r[11]),"=r"(r[12]),"=r"(r[13]),"=r"(r[14]),"=r"(r[15]),
          "=r"(r[16]),"=r"(r[17]),"=r"(r[18]),"=r"(r[19]),"=r"(r[20]),"=r"(r[21]),"=r"(r[22]),"=r"(r[23]),
          "=r"(r[24]),"=r"(r[25]),"=r"(r[26]),"=r"(r[27]),"=r"(r[28]),"=r"(r[29]),"=r"(r[30]),"=r"(r[31])
        : "r"(ta));
}
static constexpr uint64_t DESC_BASE =
    (uint64_t(2) << 61) | (uint64_t(1) << 46) | (uint64_t(64) << 32) | (uint64_t(1) << 16);
__device__ __forceinline__ uint64_t mk_desc(uint32_t addr) {
    return DESC_BASE | ((uint64_t)(addr >> 4) & 0x3FFF);
}
#define IDESC_N(N) ((1u<<4)|(1u<<7)|(1u<<10)|(((N)/8u)<<17)|(8u<<24))
#endif  // HAS_TCGEN05

// ---------------------------------------------------------------------------
// fsplit: hs fp32 row-major -> TILED bf16 hi/lo. 8 elements/thread.
// ---------------------------------------------------------------------------
__global__ __launch_bounds__(256) void fsplit(const float* __restrict__ in,
                                              char* __restrict__ hi,
                                              char* __restrict__ lo) {
    int t = blockIdx.x * 256 + threadIdx.x;
    int row = t >> 7;
    int k8 = t & 127;                      // k/8
    const float4* p = (const float4*)(in + ((size_t)row << 10) + (k8 << 3));
    float4 v0 = p[0], v1 = p[1];
    uint4 hv, lv;
    split_pack2(v0.x, v0.y, hv.x, lv.x);
    split_pack2(v0.z, v0.w, hv.y, lv.y);
    split_pack2(v1.x, v1.y, hv.z, lv.z);
    split_pack2(v1.z, v1.w, hv.w, lv.w);
    uint32_t tile = (uint32_t)(row >> 7) * 16u + (uint32_t)(k8 >> 3);
    uint32_t off = (tile << 14) + swz(((uint32_t)(row & 127) << 7) + ((uint32_t)(k8 & 7) << 4));
    *(uint4*)(hi + off) = hv;
    *(uint4*)(lo + off) = lv;
}

// ---------------------------------------------------------------------------
// wsplit: W[K][N] fp32 -> transposed TILED bf16 hi/lo (256-row tiles)
// ---------------------------------------------------------------------------
__global__ __launch_bounds__(256) void wsplit(const float* __restrict__ W,
                                              char* __restrict__ Thi,
                                              char* __restrict__ Tlo) {
    __shared__ float t[32][33];
    int bx = blockIdx.x * 32, by = blockIdx.y * 32;
    int x = threadIdx.x & 31, y = threadIdx.x >> 5;
#pragma unroll
    for (int j = 0; j < 4; j++)
        t[y + j*8][x] = W[(size_t)(by + y + j*8) * DD + bx + x];
    __syncthreads();
#pragma unroll
    for (int j = 0; j < 4; j++) {
        float v = t[x][y + j*8];
        float h, l;
        split2(v, h, l);
        int n = bx + y + j*8, k = by + x;
        uint32_t off = b_tile_off(n, k);
        *(__nv_bfloat16*)(Thi + off) = __float2bfloat16(h);
        *(__nv_bfloat16*)(Tlo + off) = __float2bfloat16(l);
    }
}

// ---------------------------------------------------------------------------
// tcgen05 GEMM with bulk-copy loads. grid=(4, 128), 256 threads.
// ---------------------------------------------------------------------------
#define GK 1024
#define GN 1024
#define NCHUNK 16
#define BUF_STRIDE 98304
#define GIDESC ((1u<<4)|(1u<<7)|(1u<<10)|((256u/8)<<17)|((128u/16)<<24))

__global__ __launch_bounds__(256, 1) void gemm_t(
        const char* __restrict__ Ahi, const char* __restrict__ Alo,
        const char* __restrict__ Bhi, const char* __restrict__ Blo,
        float* __restrict__ C) {
    extern __shared__ char sm[];
#if HAS_TCGEN05
    uint32_t sbase = smem_u32(sm);
    int tid = threadIdx.x;
    int wid = tid >> 5, lid = tid & 31;
    int bn = blockIdx.x, bm = blockIdx.y;

    if (tid == 0) {
        MBAR_INIT(sbase + 8, 1);  MBAR_INIT(sbase + 16, 1);
        MBAR_INIT(sbase + 24, 1); MBAR_INIT(sbase + 32, 1);
    }
    if (wid == 0) TC_ALLOC(sbase, 256);
    __syncthreads();
    uint32_t tmem;
    asm volatile("ld.shared.b32 %0, [%1];" : "=r"(tmem) : "r"(sbase));

    if (wid == 0 && elect_one()) {
        auto load = [&](int chunk, int b) {
            uint32_t mb = sbase + 8 + (uint32_t)b * 8;
            MBAR_EXPECT_TX(mb, 98304u);
            uint32_t d = sbase + 1024u + (uint32_t)b * BUF_STRIDE;
            size_t ao = ((size_t)bm * 16 + chunk) << 14;
            size_t bo = ((size_t)bn * 16 + chunk) << 15;
            BULK_G2S(d,          Ahi + ao, 16384u, mb);
            BULK_G2S(d + 16384,  Alo + ao, 16384u, mb);
            BULK_G2S(d + 32768,  Bhi + bo, 32768u, mb);
            BULK_G2S(d + 65536,  Blo + bo, 32768u, mb);
        };
        load(0, 0);
        load(1, 1);
        int f0 = 0, f1 = 0, e0 = 0, e1 = 0;
        for (int k = 0; k < NCHUNK; k++) {
            int b = k & 1;
            if (b == 0) { MBAR_WAIT(sbase + 8, f0);  f0 ^= 1; }
            else        { MBAR_WAIT(sbase + 16, f1); f1 ^= 1; }
            uint32_t boff = sbase + 1024u + (uint32_t)b * BUF_STRIDE;
            uint64_t dah = mk_desc(boff);
            uint64_t dal = mk_desc(boff + 16384);
            uint64_t dbh = mk_desc(boff + 32768);
            uint64_t dbl = mk_desc(boff + 65536);
#pragma unroll
            for (int ks = 0; ks < 4; ks++) {
                mma_f16_ss(tmem, dah + ks*2, dbh + ks*2, GIDESC,
                           (k == 0 && ks == 0) ? 0u : 1u);
                mma_f16_ss(tmem, dah + ks*2, dbl + ks*2, GIDESC, 1u);
                mma_f16_ss(tmem, dal + ks*2, dbh + ks*2, GIDESC, 1u);
            }
            TC_COMMIT(sbase + 24 + (uint32_t)b * 8);
            if (k + 2 < NCHUNK) {
                if (b == 0) { MBAR_WAIT(sbase + 24, e0); e0 ^= 1; }
                else        { MBAR_WAIT(sbase + 32, e1); e1 ^= 1; }
                load(k + 2, b);
            }
        }
        MBAR_WAIT(sbase + 24, e0);
        MBAR_WAIT(sbase + 32, e1);
    }
    __syncthreads();
    TC_FENCE_AFTER();

    if (wid < 4) {
        int row = bm * 128 + wid * 32 + lid;
        float* crow = C + (size_t)row * GN + bn * 256;
#pragma unroll
        for (int cb = 0; cb < 8; cb++) {
            uint32_t r[32];
            ldtm32(r, tmem + cb * 32);
            TC_WAIT_LD();
#pragma unroll
            for (int j = 0; j < 8; j++) {
                float4 v = make_float4(__uint_as_float(r[j*4]), __uint_as_float(r[j*4+1]),
                                       __uint_as_float(r[j*4+2]), __uint_as_float(r[j*4+3]));
                *(float4*)(crow + cb * 32 + j * 4) = v;
            }
        }
        TC_FENCE_BEFORE();
    }
    __syncthreads();
    if (wid == 0) TC_DEALLOC(tmem, 256);
#else
    // CUDA-core fallback (non-'a' pass only) — reads TILED bf16 operands.
    int tid = threadIdx.x;
    int tx = tid & 15, ty = tid >> 4;
    int bn = blockIdx.x * 256, bm = blockIdx.y * 128;
    float* sA = (float*)sm;
    float* sB = (float*)(sm + 8192);
    auto rdA = [&](const char* p, int row, int k) {
        uint32_t off = a_tile_off(row, k);
        return __bfloat162float(*(const __nv_bfloat16*)(p + off));
    };
    auto rdB = [&](const char* p, int n, int k) {
        uint32_t off = b_tile_off(n, k);
        return __bfloat162float(*(const __nv_bfloat16*)(p + off));
    };
    for (int half = 0; half < 2; half++) {
        int bn2 = bn + half * 128;
        float acc[8][8];
#pragma unroll
        for (int i = 0; i < 8; i++)
#pragma unroll
            for (int j = 0; j < 8; j++) acc[i][j] = 0.f;
        for (int k0 = 0; k0 < GK; k0 += 16) {
            for (int i = tid; i < 2048; i += 256) {
                int r = i >> 4, kk = i & 15;
                sA[kk*128 + r] = rdA(Ahi, bm + r, k0 + kk) + rdA(Alo, bm + r, k0 + kk);
                sB[kk*128 + r] = rdB(Bhi, bn2 + r, k0 + kk) + rdB(Blo, bn2 + r, k0 + kk);
            }
            __syncthreads();
#pragma unroll
            for (int kk = 0; kk < 16; kk++) {
                float a[8], b[8];
#pragma unroll
                for (int i = 0; i < 4; i++) {
                    a[i] = sA[kk*128 + ty*4 + i];
                    a[i+4] = sA[kk*128 + 64 + ty*4 + i];
                    b[i] = sB[kk*128 + tx*4 + i];
                    b[i+4] = sB[kk*128 + 64 + tx*4 + i];
                }
#pragma unroll
                for (int i = 0; i < 8; i++)
#pragma unroll
                    for (int j = 0; j < 8; j++) acc[i][j] += a[i] * b[j];
            }
            __syncthreads();
        }
#pragma unroll
        for (int i = 0; i < 8; i++) {
            int row = bm + ((i < 4) ? (ty*4 + i) : (64 + ty*4 + i - 4));
#pragma unroll
            for (int j = 0; j < 8; j++) {
                int col = bn2 + ((j < 4) ? (tx*4 + j) : (64 + tx*4 + j - 4));
                C[(size_t)row * GN + col] = acc[i][j];
            }
        }
        __syncthreads();
    }
#endif
}

// ---------------------------------------------------------------------------
// dt = softplus(hs @ Wdt)
// ---------------------------------------------------------------------------
__global__ __launch_bounds__(256) void dt2(const float* __restrict__ hs,
                                           const float* __restrict__ Wdt) {
    extern __shared__ float sw[];
    int tid = threadIdx.x;
    for (int i = tid; i < 16384; i += 256)
        sw[(i & 15) * 1028 + (i >> 4)] = Wdt[i];
    __syncthreads();
    int w = tid >> 5, l = tid & 31;
    int row0 = blockIdx.x * 32 + w * 4;
    float acc[4][16];
#pragma unroll
    for (int r = 0; r < 4; r++)
#pragma unroll
        for (int n = 0; n < 16; n++) acc[r][n] = 0.f;
#pragma unroll
    for (int it = 0; it < 8; it++) {
        int k0 = it * 128 + l * 4;
        float4 h[4];
#pragma unroll
        for (int r = 0; r < 4; r++)
            h[r] = *(const float4*)&hs[(size_t)(row0 + r) * DD + k0];
#pragma unroll
        for (int n = 0; n < 16; n++) {
            float4 wv = *(const float4*)&sw[n * 1028 + k0];
#pragma unroll
            for (int r = 0; r < 4; r++)
                acc[r][n] += h[r].x*wv.x + h[r].y*wv.y + h[r].z*wv.z + h[r].w*wv.w;
        }
    }
#pragma unroll
    for (int off = 16; off; off >>= 1)
#pragma unroll
        for (int r = 0; r < 4; r++)
#pragma unroll
            for (int n = 0; n < 16; n++)
                acc[r][n] += __shfl_xor_sync(0xFFFFFFFFu, acc[r][n], off);
    if (l == 0) {
#pragma unroll
        for (int r = 0; r < 4; r++)
#pragma unroll
            for (int n = 0; n < 16; n++) {
                float s = acc[r][n];
                g_dt[(row0 + r) * HH + n] = fmaxf(s, 0.f) + log1pf(expf(-fabsf(s)));
            }
    }
}

// ---------------------------------------------------------------------------
// Per-chunk inclusive cumsum of dA
// ---------------------------------------------------------------------------
__global__ __launch_bounds__(256) void acum_kernel(const float* __restrict__ A) {
    __shared__ float s[256];
    int bid = blockIdx.x;
    int h = bid & 15, c = (bid >> 4) & 31, b = bid >> 9;
    int l = threadIdx.x;
    int row = b * LL + c * CLc + l;
    s[l] = g_dt[row * HH + h] * A[h];
    __syncthreads();
    for (int off = 1; off < 256; off <<= 1) {
        float u = (l >= off) ? s[l - off] : 0.f;
        __syncthreads();
        s[l] += u;
        __syncthreads();
    }
    g_ac[row * HH + h] = s[l];
    if (l == 255) g_cdec[bid] = expf(s[255]);
}

// ---------------------------------------------------------------------------
// Chunk states (rope + x*dt fused into the fill, vectorized)
// ---------------------------------------------------------------------------
__global__ __launch_bounds__(256) void kb_kernel(const float* __restrict__ cosp,
                                                 const float* __restrict__ sinp) {
    __shared__ float sX[4096];
    __shared__ float sB[4096];
    int bid = blockIdx.x;
    int h = bid & 15, c = (bid >> 4) & 31, b = bid >> 9;
    int tid = threadIdx.x, tx = tid & 15, ty = tid >> 4;
    int chunk_row = b * LL + c * CLc;
    float aclast = g_ac[(chunk_row + 255) * HH + h];

    float acc[4][4];
#pragma unroll
    for (int i = 0; i < 4; i++)
#pragma unroll
        for (int j = 0; j < 4; j++) acc[i][j] = 0.f;

    for (int ltile = 0; ltile < 4; ltile++) {
        int r0 = chunk_row + ltile * 64;
#pragma unroll
        for (int t = 0; t < 2; t++) {
            int u = tid + t * 256;
            int rr = u >> 3, p4 = (u & 7) * 4;
            int row = r0 + rr;
            const float* bb = g_b + (size_t)row * DD + h * 64;
            const float* xx = g_x + (size_t)row * DD + h * 64;
            float4 a  = *(const float4*)(bb + p4);
            float4 q  = *(const float4*)(bb + p4 + 32);
            float4 c1 = *(const float4*)(cosp + row*64 + p4);
            float4 c2 = *(const float4*)(cosp + row*64 + p4 + 32);
            float4 s1 = *(const float4*)(sinp + row*64 + p4);
            float4 s2 = *(const float4*)(sinp + row*64 + p4 + 32);
            float w = __expf(aclast - g_ac[row * HH + h]);
            float dtv = g_dt[row * HH + h];
            float4 v1 = make_float4((a.x*c1.x - q.x*s1.x)*w, (a.y*c1.y - q.y*s1.y)*w,
                                    (a.z*c1.z - q.z*s1.z)*w, (a.w*c1.w - q.w*s1.w)*w);
            float4 v2 = make_float4((q.x*c2.x + a.x*s2.x)*w, (q.y*c2.y + a.y*s2.y)*w,
                                    (q.z*c2.z + a.z*s2.z)*w, (q.w*c2.w + a.w*s2.w)*w);
            *(float4*)&sB[rr*64 + p4]      = v1;
            *(float4*)&sB[rr*64 + p4 + 32] = v2;
            float4 xv1 = *(const float4*)(xx + p4);
            float4 xv2 = *(const float4*)(xx + p4 + 32);
            *(float4*)&sX[rr*64 + p4] =
                make_float4(xv1.x*dtv, xv1.y*dtv, xv1.z*dtv, xv1.w*dtv);
            *(float4*)&sX[rr*64 + p4 + 32] =
                make_float4(xv2.x*dtv, xv2.y*dtv, xv2.z*dtv, xv2.w*dtv);
        }
        __syncthreads();
#pragma unroll 4
        for (int l = 0; l < 64; l++) {
            float xv[4], bv[4];
#pragma unroll
            for (int i = 0; i < 4; i++) xv[i] = sX[l * 64 + ty * 4 + i];
#pragma unroll
            for (int j = 0; j < 4; j++) bv[j] = sB[l * 64 + tx * 4 + j];
#pragma unroll
            for (int i = 0; i < 4; i++)
#pragma unroll
                for (int j = 0; j < 4; j++) acc[i][j] += xv[i] * bv[j];
        }
        __syncthreads();
    }
    int sb = ((b * NCC + c) * HH + h) * 4096;
#pragma unroll
    for (int i = 0; i < 4; i++) {
        float4 v = make_float4(acc[i][0], acc[i][1], acc[i][2], acc[i][3]);
        *(float4*)&g_states[sb + (ty * 4 + i) * 64 + tx * 4] = v;
    }
}

// ---------------------------------------------------------------------------
// Sequential chunk scan
// ---------------------------------------------------------------------------
__global__ __launch_bounds__(256) void kc_kernel(float* __restrict__ fs) {
    int bid = blockIdx.x;
    int h = bid & 15, b = bid >> 4;
    int tid = threadIdx.x;
    float st[16];
#pragma unroll
    for (int k = 0; k < 16; k++) st[k] = 0.f;
    for (int c = 0; c < NCC; c++) {
        float dec = g_cdec[(b * NCC + c) * HH + h];
        int base = ((b * NCC + c) * HH + h) * 4096;
#pragma unroll
        for (int k = 0; k < 16; k++) {
            int e = k * 256 + tid;
            g_prev[base + e] = st[k];
            st[k] = st[k] * dec + g_states[base + e];
        }
    }
    int fb = (b * HH + h) * 4096;
#pragma unroll
    for (int k = 0; k < 16; k++) fs[fb + k * 256 + tid] = st[k];
}

// ---------------------------------------------------------------------------
// Flash kernel: Y_diag + Y_off on tensor cores.
// Factorized decay (ecol/erow) kills per-element MUFU; packed splits.
// ALL MMA tile bases 1024-byte aligned.
// ---------------------------------------------------------------------------
#define FL_SMEM 183296
#define FO_AC   64
#define FO_DT   1088
#define FO_CHI  3072
#define FO_CLO  19456
#define FO_BHI  35840
#define FO_BLO  68608
#define FO_XHI  101376
#define FO_XLO  134144
#define FO_PHI  166912
#define FO_PLO  175104

__global__ __launch_bounds__(256, 1) void flash_k(const float* __restrict__ cosp,
                                                  const float* __restrict__ sinp,
                                                  char* __restrict__ yhi,
                                                  char* __restrict__ ylo) {
    extern __shared__ char sm[];
    int tid = threadIdx.x, wid = tid >> 5, lid = tid & 31;
    int bid = blockIdx.x;
    int half = bid & 1, h = (bid >> 1) & 15, c = (bid >> 5) & 31, b = bid >> 10;
    int chunk_row = b * LL + c * CLc;
    int l0g = half * 128;
    int SL = half ? 256 : 128;
    float* acs = (float*)(sm + FO_AC);
    float* sdt = (float*)(sm + FO_DT);    // aliased: dt during fills, ecol after

#if HAS_TCGEN05
    uint32_t sbase = smem_u32(sm);
    int nsl = SL / 128;
    if (tid == 0) {
        MBAR_INIT(sbase + 8, 1);  MBAR_INIT(sbase + 16, 1);
        MBAR_INIT(sbase + 24, 1); MBAR_INIT(sbase + 32, 1);
    }
    if (wid == 0) TC_ALLOC(sbase, 512);
    __syncthreads();
    uint32_t tmem;
    asm volatile("ld.shared.b32 %0, [%1];" : "=r"(tmem) : "r"(sbase));

    acs[tid] = g_ac[(chunk_row + tid) * HH + h];
    sdt[tid] = g_dt[(chunk_row + tid) * HH + h];
    __syncthreads();

    // C tile (rope) 128x64 hi/lo
#pragma unroll
    for (int t = 0; t < 4; t++) {
        int u = tid + t * 256;
        int rr = u >> 3, p4 = (u & 7) * 4;
        int row = chunk_row + l0g + rr;
        const float* cb = g_c + (size_t)row * DD + h * 64;
        float4 a  = *(const float4*)(cb + p4);
        float4 q  = *(const float4*)(cb + p4 + 32);
        float4 c1 = *(const float4*)(cosp + row*64 + p4);
        float4 c2 = *(const float4*)(cosp + row*64 + p4 + 32);
        float4 s1 = *(const float4*)(sinp + row*64 + p4);
        float4 s2 = *(const float4*)(sinp + row*64 + p4 + 32);
        uint2 hv1, lv1, hv2, lv2;
        split_pack2(a.x*c1.x - q.x*s1.x, a.y*c1.y - q.y*s1.y, hv1.x, lv1.x);
        split_pack2(a.z*c1.z - q.z*s1.z, a.w*c1.w - q.w*s1.w, hv1.y, lv1.y);
        split_pack2(q.x*c2.x + a.x*s2.x, q.y*c2.y + a.y*s2.y, hv2.x, lv2.x);
        split_pack2(q.z*c2.z + a.z*s2.z, q.w*c2.w + a.w*s2.w, hv2.y, lv2.y);
        uint32_t o1 = swz((uint32_t)(rr*128 + p4*2));
        uint32_t o2 = swz((uint32_t)(rr*128 + (p4+32)*2));
        *(uint2*)(sm + FO_CHI + o1) = hv1;
        *(uint2*)(sm + FO_CLO + o1) = lv1;
        *(uint2*)(sm + FO_CHI + o2) = hv2;
        *(uint2*)(sm + FO_CLO + o2) = lv2;
    }
    // B tile (rope) SLx64 hi/lo
    for (int t = 0; t < SL/32; t++) {
        int u = tid + t * 256;
        int rr = u >> 3, p4 = (u & 7) * 4;
        int row = chunk_row + rr;
        const float* bb = g_b + (size_t)row * DD + h * 64;
        float4 a  = *(const float4*)(bb + p4);
        float4 q  = *(const float4*)(bb + p4 + 32);
        float4 c1 = *(const float4*)(cosp + row*64 + p4);
        float4 c2 = *(const float4*)(cosp + row*64 + p4 + 32);
        float4 s1 = *(const float4*)(sinp + row*64 + p4);
        float4 s2 = *(const float4*)(sinp + row*64 + p4 + 32);
        uint2 hv1, lv1, hv2, lv2;
        split_pack2(a.x*c1.x - q.x*s1.x, a.y*c1.y - q.y*s1.y, hv1.x, lv1.x);
        split_pack2(a.z*c1.z - q.z*s1.z, a.w*c1.w - q.w*s1.w, hv1.y, lv1.y);
        split_pack2(q.x*c2.x + a.x*s2.x, q.y*c2.y + a.y*s2.y, hv2.x, lv2.x);
        split_pack2(q.z*c2.z + a.z*s2.z, q.w*c2.w + a.w*s2.w, hv2.y, lv2.y);
        uint32_t o1 = swz((uint32_t)(rr*128 + p4*2));
        uint32_t o2 = swz((uint32_t)(rr*128 + (p4+32)*2));
        *(uint2*)(sm + FO_BHI + o1) = hv1;
        *(uint2*)(sm + FO_BLO + o1) = lv1;
        *(uint2*)(sm + FO_BHI + o2) = hv2;
        *(uint2*)(sm + FO_BLO + o2) = lv2;
    }
    // X^T tile: [64 p][SL s] blocked atoms; units (p, s-group of 4)
    for (int t = 0; t < SL/16; t++) {
        int u = tid + t * 256;
        int p = u & 63, sg = u >> 6;
        int s0 = sg * 4;
        float xv[4];
#pragma unroll
        for (int i = 0; i < 4; i++)
            xv[i] = g_x[(size_t)(chunk_row + s0 + i) * DD + h*64 + p] * sdt[s0 + i];
        uint2 hv, lv;
        split_pack2(xv[0], xv[1], hv.x, lv.x);
        split_pack2(xv[2], xv[3], hv.y, lv.y);
        uint32_t off = swz((uint32_t)(((p>>3) + (s0>>6)*8)*1024 + (p&7)*128 + (s0&63)*2));
        *(uint2*)(sm + FO_XHI + off) = hv;
        *(uint2*)(sm + FO_XLO + off) = lv;
    }
    // prev tile [64 p][64 n]
    {
        int pbase = ((b * NCC + c) * HH + h) * 4096;
#pragma unroll
        for (int t = 0; t < 4; t++) {
            int u = tid + t * 256;
            int p = u >> 4, n4 = (u & 15) * 4;
            float4 v = *(const float4*)(g_prev + pbase + p*64 + n4);
            uint2 hv, lv;
            split_pack2(v.x, v.y, hv.x, lv.x);
            split_pack2(v.z, v.w, hv.y, lv.y);
            uint32_t off = swz((uint32_t)(p*128 + n4*2));
            *(uint2*)(sm + FO_PHI + off) = hv;
            *(uint2*)(sm + FO_PLO + off) = lv;
        }
    }
    FENCE_ASYNC();
    __syncthreads();

    // ecol (reuses sdt space — dt no longer needed): exp(ref_j - acs[cg]),
    // ref_j = acs[32*(cg/32)]. Bounded since acs is decreasing.
    sdt[tid] = __expf(acs[tid & ~31] - acs[tid]);
    __syncthreads();
    float* ecol = sdt;

    // MMA1: S = C * B^T, plus off-term Y2 = C * prev^T
    if (wid == 0 && elect_one()) {
        uint64_t dCh = mk_desc(sbase + FO_CHI), dCl = mk_desc(sbase + FO_CLO);
        uint64_t dBh = mk_desc(sbase + FO_BHI), dBl = mk_desc(sbase + FO_BLO);
        uint32_t id1 = (SL == 128) ? IDESC_N(128) : IDESC_N(256);
#pragma unroll
        for (int ks = 0; ks < 4; ks++) {
            mma_f16_ss(tmem, dCh + ks*2, dBh + ks*2, id1, ks > 0);
            mma_f16_ss(tmem, dCh + ks*2, dBl + ks*2, id1, 1);
            mma_f16_ss(tmem, dCl + ks*2, dBh + ks*2, id1, 1);
        }
        TC_COMMIT(sbase + 8);
        uint64_t dPh = mk_desc(sbase + FO_PHI), dPl = mk_desc(sbase + FO_PLO);
        uint32_t id64 = IDESC_N(64);
#pragma unroll
        for (int ks = 0; ks < 4; ks++) {
            mma_f16_ss(tmem + 320, dCh + ks*2, dPh + ks*2, id64, ks > 0);
            mma_f16_ss(tmem + 320, dCh + ks*2, dPl + ks*2, id64, 1);
            mma_f16_ss(tmem + 320, dCl + ks*2, dPh + ks*2, id64, 1);
        }
        TC_COMMIT(sbase + 16);
    }
    MBAR_WAIT(sbase + 8, 0);
    TC_FENCE_AFTER();

    int sub = wid & 3, grp = wid >> 2;
    int lrow = sub * 32 + lid;
    float acl = acs[l0g + lrow];

    // per-thread row factors vs each 32-column reference
    float erow[8];
#pragma unroll
    for (int j = 0; j < 8; j++) erow[j] = __expf(acl - acs[j * 32]);

    for (int sl = 0; sl < nsl; sl++) {
        if (sl == 1) MBAR_WAIT(sbase + 24, 0);
#pragma unroll
        for (int rd = grp; rd < 4; rd += 2) {
            uint32_t r[32];
            ldtm32(r, tmem + sl*128 + rd*32);
            TC_WAIT_LD();
            int colbase = sl*128 + rd*32;
            float er = erow[colbase >> 5];   // 32-col block constant
#pragma unroll
            for (int j = 0; j < 32; j += 4) {
                float vv[4];
#pragma unroll
                for (int i = 0; i < 4; i++) {
                    int cg = colbase + j + i;
                    float v = __uint_as_float(r[j+i]) * er * ecol[cg];
                    vv[i] = (cg <= l0g + lrow) ? v : 0.f;
                }
                uint2 hv, lv;
                split_pack2(vv[0], vv[1], hv.x, lv.x);
                split_pack2(vv[2], vv[3], hv.y, lv.y);
                int sIn = rd*32 + j;
                uint32_t off = swz((uint32_t)(((lrow>>3) + (sIn>>6)*16)*1024
                                              + (lrow&7)*128 + (sIn&63)*2));
                *(uint2*)(sm + FO_BHI + off) = hv;
                *(uint2*)(sm + FO_BLO + off) = lv;
            }
        }
        FENCE_ASYNC();
        __syncthreads();
        if (wid == 0 && elect_one()) {
            uint64_t dSh = mk_desc(sbase + FO_BHI), dSl = mk_desc(sbase + FO_BLO);
            uint64_t dXh = mk_desc(sbase + FO_XHI), dXl = mk_desc(sbase + FO_XLO);
            uint32_t id64 = IDESC_N(64);
#pragma unroll
            for (int ks2 = 0; ks2 < 8; ks2++) {
                int ksg = sl*8 + ks2;
                uint64_t ao = (uint64_t)((ks2 >> 2)*1024 + (ks2 & 3)*2);
                uint64_t bo = (uint64_t)((ksg >> 2)*512 + (ksg & 3)*2);
                mma_f16_ss(tmem + 256, dSh + ao, dXh + bo, id64,
                           !(sl == 0 && ks2 == 0));
                mma_f16_ss(tmem + 256, dSh + ao, dXl + bo, id64, 1);
                mma_f16_ss(tmem + 256, dSl + ao, dXh + bo, id64, 1);
            }
            TC_COMMIT(sbase + 24 + (uint32_t)sl * 8);
        }
    }
    MBAR_WAIT(sbase + 24 + (uint32_t)(nsl - 1) * 8, 0);
    MBAR_WAIT(sbase + 16, 0);
    TC_FENCE_AFTER();

    // Final epilogue: write y as TILED bf16 hi/lo (tile = (row>>7)*16 + h)
    {
        int row = chunk_row + l0g + lrow;
        uint32_t tile = (uint32_t)(row >> 7) * 16u + (uint32_t)h;
        char* dhi = yhi + ((size_t)tile << 14);
        char* dlo = ylo + ((size_t)tile << 14);
        float e = __expf(acl);
        uint32_t y1[32], y2[32];
        ldtm32(y1, tmem + 256 + grp*32); TC_WAIT_LD();
        ldtm32(y2, tmem + 320 + grp*32); TC_WAIT_LD();
#pragma unroll
        for (int j = 0; j < 32; j += 4) {
            float vv[4];
#pragma unroll
            for (int i = 0; i < 4; i++)
                vv[i] = __uint_as_float(y1[j+i]) + e * __uint_as_float(y2[j+i]);
            uint2 hv, lv;
            split_pack2(vv[0], vv[1], hv.x, lv.x);
            split_pack2(vv[2], vv[3], hv.y, lv.y);
            uint32_t off = swz((uint32_t)((row & 127)*128 + (grp*32 + j)*2));
            *(uint2*)(dhi + off) = hv;
            *(uint2*)(dlo + off) = lv;
        }
        TC_FENCE_BEFORE();
    }
    __syncthreads();
    if (wid == 0) TC_DEALLOC(tmem, 512);
#else
    // CUDA-core fallback (non-'a' pass only)
    float* sC = (float*)(sm + FO_CHI);
    float* sS = (float*)(sm + FO_BHI);
    float* sB = (float*)(sm + FO_BLO);
    float* sX = (float*)(sm + FO_XHI);
    float* sP = (float*)(sm + FO_XLO);
    int tx = tid & 15, ty = tid >> 4;

    acs[tid] = g_ac[(chunk_row + tid) * HH + h];
    for (int t = 0; t < 16; t++) {
        int pr = tid + t * 256;
        int rr = pr >> 5, pp = pr & 31;
        int row = chunk_row + l0g + rr;
        const float* cb = g_c + (size_t)row * DD + h * 64;
        float a = cb[pp], q = cb[pp + 32];
        float c1 = cosp[row*64 + pp],      s1 = sinp[row*64 + pp];
        float c2 = cosp[row*64 + pp + 32], s2 = sinp[row*64 + pp + 32];
        sC[rr*64 + pp]      = a * c1 - q * s1;
        sC[rr*64 + pp + 32] = q * c2 + a * s2;
    }
    {
        int pbase = ((b * NCC + c) * HH + h) * 4096;
        for (int t = 0; t < 16; t++) {
            int idx = tid + t * 256;
            sP[idx] = g_prev[pbase + idx];
        }
    }
    __syncthreads();

    float accD[8][4], accO[8][4];
#pragma unroll
    for (int i = 0; i < 8; i++)
#pragma unroll
        for (int j = 0; j < 4; j++) { accD[i][j] = 0.f; accO[i][j] = 0.f; }
    for (int n = 0; n < 64; n++)
#pragma unroll
        for (int i = 0; i < 8; i++)
#pragma unroll
            for (int j = 0; j < 4; j++)
                accO[i][j] += sC[(ty*8+i)*64 + n] * sP[(tx*4+j)*64 + n];

    for (int stile = 0; stile < SL/64; stile++) {
        for (int t = 0; t < 8; t++) {
            int pr = tid + t * 256;
            int rr = pr >> 5, pp = pr & 31;
            int row = chunk_row + stile*64 + rr;
            const float* bb = g_b + (size_t)row * DD + h * 64;
            const float* xx = g_x + (size_t)row * DD + h * 64;
            float a = bb[pp], q = bb[pp + 32];
            float c1 = cosp[row*64 + pp],      s1 = sinp[row*64 + pp];
            float c2 = cosp[row*64 + pp + 32], s2 = sinp[row*64 + pp + 32];
            float dtv = g_dt[row * HH + h];
            sB[rr*64 + pp]      = a * c1 - q * s1;
            sB[rr*64 + pp + 32] = q * c2 + a * s2;
            sX[rr*64 + pp]      = xx[pp] * dtv;
            sX[rr*64 + pp + 32] = xx[pp + 32] * dtv;
        }
        __syncthreads();
        for (int t = 0; t < 32; t++) {
            int idx = tid + t * 256;
            int l = idx >> 6, sIn = idx & 63;
            int sg = stile*64 + sIn;
            float v = 0.f;
            if (sg <= l0g + l) {
                for (int n = 0; n < 64; n++)
                    v += sC[l*64 + n] * sB[sIn*64 + n];
                v *= expf(acs[l0g + l] - acs[sg]);
            }
            sS[idx] = v;
        }
        __syncthreads();
        for (int s = 0; s < 64; s++)
#pragma unroll
            for (int i = 0; i < 8; i++)
#pragma unroll
                for (int j = 0; j < 4; j++)
                    accD[i][j] += sS[(ty*8+i)*64 + s] * sX[s*64 + tx*4 + j];
        __syncthreads();
    }
#pragma unroll
    for (int i = 0; i < 8; i++) {
        int lr = ty*8 + i;
        int row = chunk_row + l0g + lr;
        float e = expf(acs[l0g + lr]);
        uint32_t tile = (uint32_t)(row >> 7) * 16u + (uint32_t)h;
#pragma unroll
        for (int j = 0; j < 4; j++) {
            float v = accD[i][j] + e * accO[i][j];
            float hh, llv;
            split2(v, hh, llv);
            int col = tx*4 + j;
            uint32_t off = ((uint32_t)tile << 14) +
                           swz((uint32_t)((row & 127)*128 + col*2));
            *(__nv_bfloat16*)(yhi + off) = __float2bfloat16(hh);
            *(__nv_bfloat16*)(ylo + off) = __float2bfloat16(llv);
        }
    }
#endif
}

// ---------------------------------------------------------------------------
// kernel_launch
// ---------------------------------------------------------------------------
extern "C" void kernel_launch(void* const* d_in, const int* in_sizes, int n_in,
                              void* d_out, int out_size) {
    (void)in_sizes; (void)n_in; (void)out_size;
    const float* hs   = (const float*)d_in[0];
    const float* cosp = (const float*)d_in[1];
    const float* sinp = (const float*)d_in[2];
    const float* Wc   = (const float*)d_in[3];
    const float* Wb   = (const float*)d_in[4];
    const float* Wdt  = (const float*)d_in[5];
    const float* Wx   = (const float*)d_in[6];
    const float* Wout = (const float*)d_in[7];
    const float* A    = (const float*)d_in[8];
    float* out = (float*)d_out;
    float* fs  = out + (size_t)MM * DD;

    float *pc, *pb, *px;
    char *ahi, *alo, *whi, *wlo;
    cudaGetSymbolAddress((void**)&pc, g_c);
    cudaGetSymbolAddress((void**)&pb, g_b);
    cudaGetSymbolAddress((void**)&px, g_x);
    cudaGetSymbolAddress((void**)&ahi, g_ahi);
    cudaGetSymbolAddress((void**)&alo, g_alo);
    cudaGetSymbolAddress((void**)&whi, g_wt_hi);
    cudaGetSymbolAddress((void**)&wlo, g_wt_lo);

    const size_t WSZ = (size_t)2 * DD * DD;   // bytes per weight matrix (bf16)

    int gemm_smem = 1024 + 2 * BUF_STRIDE;
    int dt_smem = 16 * 1028 * 4;
    cudaFuncSetAttribute(gemm_t, cudaFuncAttributeMaxDynamicSharedMemorySize, gemm_smem);
    cudaFuncSetAttribute(dt2, cudaFuncAttributeMaxDynamicSharedMemorySize, dt_smem);
    cudaFuncSetAttribute(flash_k, cudaFuncAttributeMaxDynamicSharedMemorySize, FL_SMEM);

    fsplit<<<MM * DD / 8 / 256, 256>>>(hs, ahi, alo);
    dim3 wg(32, 32);
    wsplit<<<wg, 256>>>(Wc,   whi + 0*WSZ, wlo + 0*WSZ);
    wsplit<<<wg, 256>>>(Wb,   whi + 1*WSZ, wlo + 1*WSZ);
    wsplit<<<wg, 256>>>(Wx,   whi + 2*WSZ, wlo + 2*WSZ);
    wsplit<<<wg, 256>>>(Wout, whi + 3*WSZ, wlo + 3*WSZ);

    dim3 gg(GN / 256, MM / 128);
    gemm_t<<<gg, 256, gemm_smem>>>(ahi, alo, whi + 0*WSZ, wlo + 0*WSZ, pc);
    gemm_t<<<gg, 256, gemm_smem>>>(ahi, alo, whi + 1*WSZ, wlo + 1*WSZ, pb);
    gemm_t<<<gg, 256, gemm_smem>>>(ahi, alo, whi + 2*WSZ, wlo + 2*WSZ, px);

    dt2<<<MM / 32, 256, dt_smem>>>(hs, Wdt);
    acum_kernel<<<BB * NCC * HH, 256>>>(A);
    kb_kernel<<<BB * NCC * HH, 256>>>(cosp, sinp);
    kc_kernel<<<BB * HH, 256>>>(fs);

    flash_k<<<BB * NCC * HH * 2, 256, FL_SMEM>>>(cosp, sinp, ahi, alo);

    gemm_t<<<gg, 256, gemm_smem>>>(ahi, alo, whi + 3*WSZ, wlo + 3*WSZ, out);
}